// round 8
// baseline (speedup 1.0000x reference)
#include <cuda_runtime.h>
#include <cuda_bf16.h>
#include <math.h>
#include <stdint.h>

#define N_NODES 100000
#define N_EDGES 800000

typedef __nv_bfloat16  bf16;
typedef __nv_bfloat162 bf162;

// ---------------- scratch (device globals; no allocs allowed) ----------------
__device__ bf16 g_xsh[(size_t)N_NODES * 128], g_xsl[(size_t)N_NODES * 128];
__device__ bf16 g_xmh[(size_t)N_NODES * 384], g_xml[(size_t)N_NODES * 384];
__device__ bf16 g_h0h[(size_t)N_NODES * 128], g_h0l[(size_t)N_NODES * 128];
__device__ bf16 g_a0h[(size_t)N_NODES * 128], g_a0l[(size_t)N_NODES * 128];
__device__ bf16 g_h1h[(size_t)N_NODES * 256], g_h1l[(size_t)N_NODES * 256];
__device__ bf16 g_a1h[(size_t)N_NODES * 256], g_a1l[(size_t)N_NODES * 256];
__device__ bf16 g_h2h[(size_t)N_NODES * 128], g_h2l[(size_t)N_NODES * 128];
__device__ bf16 g_hfh[(size_t)N_NODES * 128], g_hfl[(size_t)N_NODES * 128];
__device__ bf16 g_c1h[(size_t)N_NODES * 64],  g_c1l[(size_t)N_NODES * 64];
__device__ bf16 g_wh[262144], g_wl[262144];
__device__ int g_counts[N_NODES];
__device__ int g_rowptr[N_NODES + 1];
__device__ int g_fill  [N_NODES];
__device__ int g_csr   [N_EDGES];

// weight plane offsets (elements)
#define WOFF_ENC 0        // 512*128 = 65536
#define WOFF_S0S 65536    // 128*256 = 32768
#define WOFF_S0N 98304
#define WOFF_S1S 131072   // 256*128
#define WOFF_S1N 163840
#define WOFF_REL 196608   // 256*128
#define WOFF_C1  229376   // 128*64 = 8192
#define WOFF_C2  237568   // 64*32  = 2048
#define WOFF_END 239616

// ---------------- bf16x3 tensor-core GEMM, 512 threads, 3-stage ----------------
#define BM 128
#define BK 32
#define A_STRIDE 40
#define A_PLANE (BM * A_STRIDE)
#define NSTAGE 3

__device__ __forceinline__ void cp16(uint32_t dst, const void* src, bool pred) {
    asm volatile("cp.async.cg.shared.global [%0], [%1], 16, %2;"
                 :: "r"(dst), "l"(src), "r"(pred ? 16 : 0));
}

#define LDMX4(r, addr)                                                          \
    asm volatile("ldmatrix.sync.aligned.m8n8.x4.shared.b16 {%0,%1,%2,%3},[%4];" \
                 : "=r"((r)[0]), "=r"((r)[1]), "=r"((r)[2]), "=r"((r)[3])       \
                 : "r"(addr))

#define LDMX4T(r, addr)                                                         \
    asm volatile("ldmatrix.sync.aligned.m8n8.x4.trans.shared.b16 "              \
                 "{%0,%1,%2,%3},[%4];"                                          \
                 : "=r"((r)[0]), "=r"((r)[1]), "=r"((r)[2]), "=r"((r)[3])       \
                 : "r"(addr))

#define MMA_BF16(acc, a, b0, b1)                                                \
    asm volatile(                                                               \
        "mma.sync.aligned.m16n8k16.row.col.f32.bf16.bf16.f32 "                  \
        "{%0,%1,%2,%3},{%4,%5,%6,%7},{%8,%9},{%0,%1,%2,%3};"                    \
        : "+f"((acc)[0]), "+f"((acc)[1]), "+f"((acc)[2]), "+f"((acc)[3])        \
        : "r"((a)[0]), "r"((a)[1]), "r"((a)[2]), "r"((a)[3]),                   \
          "r"(b0), "r"(b1))

template<int BN_>
__global__ __launch_bounds__(512) void gemm_bf16x3(
    const bf16* __restrict__ A0h, const bf16* __restrict__ A0l, int K0,
    const bf16* __restrict__ A1h, const bf16* __restrict__ A1l, int K1,
    const bf16* __restrict__ W0h, const bf16* __restrict__ W0l,
    const bf16* __restrict__ W1h, const bf16* __restrict__ W1l,
    int M, int N,
    const float* __restrict__ bias,
    const float* __restrict__ bng, const float* __restrict__ bnb,
    const float* __restrict__ bnm, const float* __restrict__ bnv,
    int do_relu,
    float* __restrict__ Cf, bf16* __restrict__ Ch, bf16* __restrict__ Cl)
{
    constexpr int B_STRIDE = BN_ + 8;
    constexpr int B_PLANE  = BK * B_STRIDE;
    constexpr int STAGE_ELEMS = 2 * A_PLANE + 2 * B_PLANE;
    constexpr int WARP_N = BN_ / 4;           // 32 (BN=128) / 16 (BN=64)
    constexpr int NT = WARP_N / 8;            // n8 tiles per warp
    constexpr int P  = WARP_N / 16;           // LDMX4T groups per plane
    constexpr int BCHUNK = BN_ / 8;           // 16B chunks per B k-row
    constexpr int BTOT = 32 * BCHUNK;         // total B chunks per plane

    extern __shared__ bf16 smem[];
    const uint32_t smem_u32 = (uint32_t)__cvta_generic_to_shared(smem);

    const int tid  = threadIdx.x;
    const int lane = tid & 31;
    const int wid  = tid >> 5;                // 0..15
    const int wm   = (wid & 3) * 32;
    const int wn   = (wid >> 2) * WARP_N;
    const int brow = blockIdx.y * BM;
    const int bcol = blockIdx.x * BN_;
    const int K = K0 + K1;
    const int T = K / BK;

    // A loader: row = tid>>2 (0..127), k = (tid&3)*8; one cp16 per plane
    const int a_row = tid >> 2;
    const int a_k   = (tid & 3) * 8;
    const int a_gr  = brow + a_row;
    const bool a_ok = (a_gr < M);
    // B loader: chunk id = tid; k = tid / BCHUNK, n = (tid % BCHUNK)*8
    const int b_k  = tid / BCHUNK;
    const int b_n  = (tid % BCHUNK) * 8;
    const bool b_act = (tid < BTOT);

    const int a_lm = (wm + (lane & 15)) * A_STRIDE + (lane >> 4) * 8;
    const int b_lm = ((lane & 7) + ((lane >> 3) & 1) * 8) * B_STRIDE
                     + wn + (lane >> 4) * 8;

    float acc[2][NT][4];
#pragma unroll
    for (int mt = 0; mt < 2; mt++)
#pragma unroll
        for (int nt = 0; nt < NT; nt++)
#pragma unroll
            for (int i = 0; i < 4; i++) acc[mt][nt][i] = 0.f;

#define LOAD_TILE(t, st) do {                                                     \
        const int kt_ = (t) * BK;                                                 \
        { int gk0 = kt_ + a_k;                                                    \
          const bf16 *sph, *spl;                                                  \
          if (gk0 < K0) { sph = A0h + (size_t)a_gr * K0 + gk0;                    \
                          spl = A0l + (size_t)a_gr * K0 + gk0; }                  \
          else          { sph = A1h + (size_t)a_gr * K1 + (gk0 - K0);             \
                          spl = A1l + (size_t)a_gr * K1 + (gk0 - K0); }           \
          uint32_t dh = smem_u32 +                                                \
              ((st) * STAGE_ELEMS + a_row * A_STRIDE + a_k) * 2;                  \
          cp16(dh,                sph, a_ok);                                     \
          cp16(dh + A_PLANE * 2,  spl, a_ok);                                     \
        }                                                                         \
        if (b_act) {                                                              \
          int gk = kt_ + b_k;                                                     \
          const bf16 *wph, *wpl; int kk2;                                         \
          if (gk < K0) { wph = W0h; wpl = W0l; kk2 = gk; }                        \
          else         { wph = W1h; wpl = W1l; kk2 = gk - K0; }                   \
          int n0 = bcol + b_n;                                                    \
          bool ok = (n0 < N);                                                     \
          uint32_t dbh = smem_u32 +                                               \
              ((st) * STAGE_ELEMS + 2 * A_PLANE + b_k * B_STRIDE + b_n) * 2;      \
          cp16(dbh,               wph + (size_t)kk2 * N + n0, ok);                \
          cp16(dbh + B_PLANE * 2, wpl + (size_t)kk2 * N + n0, ok);                \
        }                                                                         \
        asm volatile("cp.async.commit_group;");                                   \
    } while (0)

    LOAD_TILE(0, 0);
    if (T > 1) LOAD_TILE(1, 1);

    for (int t = 0; t < T; ++t) {
        const int st = t % NSTAGE;
        if (t + 2 < T) {
            LOAD_TILE(t + 2, (t + 2) % NSTAGE);
            asm volatile("cp.async.wait_group 2;");
        } else if (t + 1 < T) {
            asm volatile("cp.async.wait_group 1;");
        } else {
            asm volatile("cp.async.wait_group 0;");
        }
        __syncthreads();

        const uint32_t base = smem_u32 + st * STAGE_ELEMS * 2;
#pragma unroll
        for (int k16 = 0; k16 < 2; k16++) {
            uint32_t ah[2][4], al[2][4], bh[P][4], bl[P][4];
#pragma unroll
            for (int mt = 0; mt < 2; mt++) {
                uint32_t ad = base + (a_lm + mt * 16 * A_STRIDE + k16 * 16) * 2;
                LDMX4(ah[mt], ad);
                LDMX4(al[mt], ad + A_PLANE * 2);
            }
#pragma unroll
            for (int p = 0; p < P; p++) {
                uint32_t bd = base + (2 * A_PLANE + b_lm + p * 16
                                      + k16 * 16 * B_STRIDE) * 2;
                LDMX4T(bh[p], bd);
                LDMX4T(bl[p], bd + B_PLANE * 2);
            }
#pragma unroll
            for (int mt = 0; mt < 2; mt++)
#pragma unroll
                for (int nt = 0; nt < NT; nt++) {
                    const int p = nt >> 1, q = (nt & 1) * 2;
                    MMA_BF16(acc[mt][nt], al[mt], bh[p][q], bh[p][q + 1]);
                    MMA_BF16(acc[mt][nt], ah[mt], bl[p][q], bl[p][q + 1]);
                    MMA_BF16(acc[mt][nt], ah[mt], bh[p][q], bh[p][q + 1]);
                }
        }
        __syncthreads();
    }

#pragma unroll
    for (int nt = 0; nt < NT; nt++) {
        const int col = bcol + wn + 8 * nt + 2 * (lane & 3);
        if (col >= N) continue;
        float sc0 = 1.f, sh0 = 0.f, sc1 = 1.f, sh1 = 0.f;
        if (bias) { sh0 = bias[col]; sh1 = bias[col + 1]; }
        if (bng) {
            float s0 = bng[col]     * rsqrtf(bnv[col]     + 1e-5f);
            float s1 = bng[col + 1] * rsqrtf(bnv[col + 1] + 1e-5f);
            sh0 = (sh0 - bnm[col])     * s0 + bnb[col];
            sh1 = (sh1 - bnm[col + 1]) * s1 + bnb[col + 1];
            sc0 = s0; sc1 = s1;
        }
#pragma unroll
        for (int mt = 0; mt < 2; mt++) {
#pragma unroll
            for (int half = 0; half < 2; half++) {
                const int row = brow + wm + 16 * mt + (lane >> 2) + 8 * half;
                if (row >= M) continue;
                const float* c = acc[mt][nt] + 2 * half;
                float v0 = c[0] * sc0 + sh0;
                float v1 = c[1] * sc1 + sh1;
                if (do_relu) { v0 = fmaxf(v0, 0.f); v1 = fmaxf(v1, 0.f); }
                if (Ch) {
                    bf162 hi = __float22bfloat162_rn(make_float2(v0, v1));
                    float2 hf2 = __bfloat1622float2(hi);
                    bf162 lo = __float22bfloat162_rn(
                        make_float2(v0 - hf2.x, v1 - hf2.y));
                    *(bf162*)(Ch + (size_t)row * N + col) = hi;
                    *(bf162*)(Cl + (size_t)row * N + col) = lo;
                } else {
                    *(float2*)(Cf + (size_t)row * N + col) = make_float2(v0, v1);
                }
            }
        }
    }
}

// ---------------- split fp32 -> bf16 hi/lo planes (inputs) ----------------
__global__ void split_planes(const float* __restrict__ x,
                             bf16* __restrict__ xh, bf16* __restrict__ xl, int n4)
{
    int i = blockIdx.x * blockDim.x + threadIdx.x;
    if (i >= n4) return;
    float4 v = ((const float4*)x)[i];
    bf162 h0 = __float22bfloat162_rn(make_float2(v.x, v.y));
    bf162 h1 = __float22bfloat162_rn(make_float2(v.z, v.w));
    float2 f0 = __bfloat1622float2(h0);
    float2 f1 = __bfloat1622float2(h1);
    bf162 l0 = __float22bfloat162_rn(make_float2(v.x - f0.x, v.y - f0.y));
    bf162 l1 = __float22bfloat162_rn(make_float2(v.z - f1.x, v.w - f1.y));
    ((bf162*)xh)[i * 2]     = h0;
    ((bf162*)xh)[i * 2 + 1] = h1;
    ((bf162*)xl)[i * 2]     = l0;
    ((bf162*)xl)[i * 2 + 1] = l1;
}

// ---------------- merged weight split: all 8 segments in one launch ----------
struct WSeg { const float* src[8]; int beg[9]; };

__global__ void split_weights(WSeg ws, bf16* __restrict__ wh, bf16* __restrict__ wl)
{
    int i4 = blockIdx.x * blockDim.x + threadIdx.x;
    int i  = i4 * 4;
    if (i >= ws.beg[8]) return;
    int s = 0;
#pragma unroll
    for (int k = 0; k < 7; k++) s += (i >= ws.beg[k + 1]) ? 1 : 0;
    float4 v = *(const float4*)(ws.src[s] + (i - ws.beg[s]));
    bf162 h0 = __float22bfloat162_rn(make_float2(v.x, v.y));
    bf162 h1 = __float22bfloat162_rn(make_float2(v.z, v.w));
    float2 f0 = __bfloat1622float2(h0);
    float2 f1 = __bfloat1622float2(h1);
    bf162 l0 = __float22bfloat162_rn(make_float2(v.x - f0.x, v.y - f0.y));
    bf162 l1 = __float22bfloat162_rn(make_float2(v.z - f1.x, v.w - f1.y));
    ((bf162*)wh)[i4 * 2]     = h0;
    ((bf162*)wh)[i4 * 2 + 1] = h1;
    ((bf162*)wl)[i4 * 2]     = l0;
    ((bf162*)wl)[i4 * 2 + 1] = l1;
}

// ---------------- CSR construction ----------------
__global__ void count_deg(const int* __restrict__ dst, int* __restrict__ counts, int E)
{
    int e = blockIdx.x * blockDim.x + threadIdx.x;
    if (e < E) atomicAdd(&counts[dst[e]], 1);
}

__global__ __launch_bounds__(1024) void scan_counts(
    const int* __restrict__ counts, int* __restrict__ rowptr,
    int* __restrict__ fill, int n)
{
    __shared__ int part[1024];
    const int tid = threadIdx.x;
    const int chunk = (n + 1023) / 1024;
    const int begin = min(tid * chunk, n);
    const int end   = min(begin + chunk, n);
    int s = 0;
    for (int i = begin; i < end; i++) s += counts[i];
    part[tid] = s;
    __syncthreads();
    for (int off = 1; off < 1024; off <<= 1) {
        int v = (tid >= off) ? part[tid - off] : 0;
        __syncthreads();
        part[tid] += v;
        __syncthreads();
    }
    int pre = (tid == 0) ? 0 : part[tid - 1];
    for (int i = begin; i < end; i++) {
        rowptr[i] = pre;
        fill[i]   = pre;
        pre += counts[i];
    }
    if (end == n && begin <= n) rowptr[n] = pre;
}

__global__ void fill_csr(const int* __restrict__ src, const int* __restrict__ dst,
                         int* __restrict__ fill, int* __restrict__ csr, int E)
{
    int e = blockIdx.x * blockDim.x + threadIdx.x;
    if (e < E) {
        int pos = atomicAdd(&fill[dst[e]], 1);
        csr[pos] = src[e];
    }
}

// ---------------- CSR gather mean: warp per dst node, writes planes ----------
__global__ void gather_mean(const bf16* __restrict__ hh, const bf16* __restrict__ hl,
                            const int* __restrict__ csr, const int* __restrict__ rowptr,
                            bf16* __restrict__ oh, bf16* __restrict__ ol,
                            int Nn, int D)
{
    const int warp = (blockIdx.x * blockDim.x + threadIdx.x) >> 5;
    const int lane = threadIdx.x & 31;
    if (warp >= Nn) return;
    const int e0 = rowptr[warp];
    const int e1 = rowptr[warp + 1];
    const float inv = 1.f / (float)max(e1 - e0, 1);
    const int nseg = D >> 7;
    float acc[8];
#pragma unroll
    for (int i = 0; i < 8; i++) acc[i] = 0.f;

    for (int e = e0; e < e1; e++) {
        const int s = csr[e];
        const bf16* rh = hh + (size_t)s * D + lane * 4;
        const bf16* rl = hl + (size_t)s * D + lane * 4;
#pragma unroll
        for (int g = 0; g < 2; g++) {
            if (g < nseg) {
                uint2 vh = *(const uint2*)(rh + g * 128);
                uint2 vl = *(const uint2*)(rl + g * 128);
                float2 a0 = __bfloat1622float2(*(const bf162*)&vh.x);
                float2 a1 = __bfloat1622float2(*(const bf162*)&vh.y);
                float2 b0 = __bfloat1622float2(*(const bf162*)&vl.x);
                float2 b1 = __bfloat1622float2(*(const bf162*)&vl.y);
                acc[g * 4 + 0] += a0.x + b0.x;
                acc[g * 4 + 1] += a0.y + b0.y;
                acc[g * 4 + 2] += a1.x + b1.x;
                acc[g * 4 + 3] += a1.y + b1.y;
            }
        }
    }

#pragma unroll
    for (int g = 0; g < 2; g++) {
        if (g < nseg) {
            float v0 = acc[g * 4 + 0] * inv;
            float v1 = acc[g * 4 + 1] * inv;
            float v2 = acc[g * 4 + 2] * inv;
            float v3 = acc[g * 4 + 3] * inv;
            bf162 h0 = __float22bfloat162_rn(make_float2(v0, v1));
            bf162 h1 = __float22bfloat162_rn(make_float2(v2, v3));
            float2 f0 = __bfloat1622float2(h0);
            float2 f1 = __bfloat1622float2(h1);
            bf162 l0 = __float22bfloat162_rn(make_float2(v0 - f0.x, v1 - f0.y));
            bf162 l1 = __float22bfloat162_rn(make_float2(v2 - f1.x, v3 - f1.y));
            uint2 wh_, wl_;
            wh_.x = *(uint32_t*)&h0; wh_.y = *(uint32_t*)&h1;
            wl_.x = *(uint32_t*)&l0; wl_.y = *(uint32_t*)&l1;
            *(uint2*)(oh + (size_t)warp * D + g * 128 + lane * 4) = wh_;
            *(uint2*)(ol + (size_t)warp * D + g * 128 + lane * 4) = wl_;
        }
    }
}

// ---------------- launch helper ----------------
static inline void launch_gemm(
    const bf16* A0h, const bf16* A0l, int K0,
    const bf16* A1h, const bf16* A1l, int K1,
    const bf16* W0h, const bf16* W0l, const bf16* W1h, const bf16* W1l,
    int M, int N,
    const float* bias, const float* bng, const float* bnb,
    const float* bnm, const float* bnv,
    int do_relu, float* Cf, bf16* Ch, bf16* Cl)
{
    if (N >= 128) {
        constexpr int BN_ = 128;
        constexpr int SMEM = NSTAGE * (2 * A_PLANE + 2 * BK * (BN_ + 8)) * 2;
        dim3 grid(N / BN_, (M + BM - 1) / BM);
        gemm_bf16x3<BN_><<<grid, 512, SMEM>>>(
            A0h, A0l, K0, A1h, A1l, K1, W0h, W0l, W1h, W1l, M, N,
            bias, bng, bnb, bnm, bnv, do_relu, Cf, Ch, Cl);
    } else {
        constexpr int BN_ = 64;
        constexpr int SMEM = NSTAGE * (2 * A_PLANE + 2 * BK * (BN_ + 8)) * 2;
        dim3 grid((N + BN_ - 1) / BN_, (M + BM - 1) / BM);
        gemm_bf16x3<BN_><<<grid, 512, SMEM>>>(
            A0h, A0l, K0, A1h, A1l, K1, W0h, W0l, W1h, W1l, M, N,
            bias, bng, bnb, bnm, bnv, do_relu, Cf, Ch, Cl);
    }
}

extern "C" void kernel_launch(void* const* d_in, const int* in_sizes, int n_in,
                              void* d_out, int out_size)
{
    const float* structural = (const float*)d_in[0];
    const float* multimodal = (const float*)d_in[1];
    const int*   src        = (const int*)  d_in[2];
    const int*   dst        = (const int*)  d_in[3];
    const float* enc_w      = (const float*)d_in[4];
    const float* enc_b      = (const float*)d_in[5];
    const float* sage0_ws   = (const float*)d_in[6];
    const float* sage0_wn   = (const float*)d_in[7];
    const float* sage0_b    = (const float*)d_in[8];
    const float* bn0_g      = (const float*)d_in[9];
    const float* bn0_b      = (const float*)d_in[10];
    const float* bn0_m      = (const float*)d_in[11];
    const float* bn0_v      = (const float*)d_in[12];
    const float* sage1_ws   = (const float*)d_in[13];
    const float* sage1_wn   = (const float*)d_in[14];
    const float* sage1_b    = (const float*)d_in[15];
    const float* bn1_g      = (const float*)d_in[16];
    const float* bn1_b      = (const float*)d_in[17];
    const float* bn1_m      = (const float*)d_in[18];
    const float* bn1_v      = (const float*)d_in[19];
    const float* rel_w      = (const float*)d_in[20];
    const float* rel_b      = (const float*)d_in[21];
    const float* cls_w1     = (const float*)d_in[22];
    const float* cls_b1     = (const float*)d_in[23];
    const float* cls_w2     = (const float*)d_in[24];
    const float* cls_b2     = (const float*)d_in[25];
    float* out = (float*)d_out;

#define SYMADDR(var, sym) void* p_##var; cudaGetSymbolAddress(&p_##var, sym);
    SYMADDR(xsh, g_xsh) SYMADDR(xsl, g_xsl) SYMADDR(xmh, g_xmh) SYMADDR(xml, g_xml)
    SYMADDR(h0h, g_h0h) SYMADDR(h0l, g_h0l) SYMADDR(a0h, g_a0h) SYMADDR(a0l, g_a0l)
    SYMADDR(h1h, g_h1h) SYMADDR(h1l, g_h1l) SYMADDR(a1h, g_a1h) SYMADDR(a1l, g_a1l)
    SYMADDR(h2h, g_h2h) SYMADDR(h2l, g_h2l) SYMADDR(hfh, g_hfh) SYMADDR(hfl, g_hfl)
    SYMADDR(c1h, g_c1h) SYMADDR(c1l, g_c1l)
    SYMADDR(wh, g_wh) SYMADDR(wl, g_wl)
    SYMADDR(counts, g_counts) SYMADDR(rowptr, g_rowptr)
    SYMADDR(fill, g_fill) SYMADDR(csr, g_csr)
#undef SYMADDR

    bf16* xsh = (bf16*)p_xsh; bf16* xsl = (bf16*)p_xsl;
    bf16* xmh = (bf16*)p_xmh; bf16* xml = (bf16*)p_xml;
    bf16* h0h = (bf16*)p_h0h; bf16* h0l = (bf16*)p_h0l;
    bf16* a0h = (bf16*)p_a0h; bf16* a0l = (bf16*)p_a0l;
    bf16* h1h = (bf16*)p_h1h; bf16* h1l = (bf16*)p_h1l;
    bf16* a1h = (bf16*)p_a1h; bf16* a1l = (bf16*)p_a1l;
    bf16* h2h = (bf16*)p_h2h; bf16* h2l = (bf16*)p_h2l;
    bf16* hfh = (bf16*)p_hfh; bf16* hfl = (bf16*)p_hfl;
    bf16* c1h = (bf16*)p_c1h; bf16* c1l = (bf16*)p_c1l;
    bf16* wh = (bf16*)p_wh; bf16* wl = (bf16*)p_wl;
    int* counts = (int*)p_counts; int* rowptr = (int*)p_rowptr;
    int* fill   = (int*)p_fill;   int* csr    = (int*)p_csr;

    {
        constexpr int SMEM128 = NSTAGE * (2 * A_PLANE + 2 * BK * (128 + 8)) * 2;
        constexpr int SMEM64  = NSTAGE * (2 * A_PLANE + 2 * BK * (64 + 8)) * 2;
        cudaFuncSetAttribute(gemm_bf16x3<128>,
                             cudaFuncAttributeMaxDynamicSharedMemorySize, SMEM128);
        cudaFuncSetAttribute(gemm_bf16x3<64>,
                             cudaFuncAttributeMaxDynamicSharedMemorySize, SMEM64);
    }

    const int M = N_NODES, E = N_EDGES;

    // ---- CSR build ----
    cudaMemsetAsync(counts, 0, N_NODES * sizeof(int), 0);
    count_deg<<<(E + 255) / 256, 256>>>(dst, counts, E);
    scan_counts<<<1, 1024>>>(counts, rowptr, fill, M);
    fill_csr<<<(E + 255) / 256, 256>>>(src, dst, fill, csr, E);

    // ---- split inputs (2 launches) + all weights (1 launch) ----
    {
        int n4 = (M * 128) / 4;
        split_planes<<<(n4 + 255) / 256, 256>>>(structural, xsh, xsl, n4);
        n4 = (M * 384) / 4;
        split_planes<<<(n4 + 255) / 256, 256>>>(multimodal, xmh, xml, n4);

        WSeg ws;
        ws.src[0] = enc_w;    ws.beg[0] = WOFF_ENC;
        ws.src[1] = sage0_ws; ws.beg[1] = WOFF_S0S;
        ws.src[2] = sage0_wn; ws.beg[2] = WOFF_S0N;
        ws.src[3] = sage1_ws; ws.beg[3] = WOFF_S1S;
        ws.src[4] = sage1_wn; ws.beg[4] = WOFF_S1N;
        ws.src[5] = rel_w;    ws.beg[5] = WOFF_REL;
        ws.src[6] = cls_w1;   ws.beg[6] = WOFF_C1;
        ws.src[7] = cls_w2;   ws.beg[7] = WOFF_C2;
        ws.beg[8] = WOFF_END;
        int w4 = WOFF_END / 4;
        split_weights<<<(w4 + 255) / 256, 256>>>(ws, wh, wl);
    }

    // h0 = relu([xs|xm] @ enc_w + enc_b)
    launch_gemm(xsh, xsl, 128, xmh, xml, 384,
                wh + WOFF_ENC, wl + WOFF_ENC,
                wh + WOFF_ENC + 128 * 128, wl + WOFF_ENC + 128 * 128,
                M, 128, enc_b, nullptr, nullptr, nullptr, nullptr, 1,
                nullptr, h0h, h0l);

    // agg0 = mean h0
    gather_mean<<<(M * 32 + 255) / 256, 256>>>(h0h, h0l, csr, rowptr,
                                               a0h, a0l, M, 128);

    // h1 = relu(bn0(h0 @ ws0 + agg0 @ wn0 + b0))
    launch_gemm(h0h, h0l, 128, a0h, a0l, 128,
                wh + WOFF_S0S, wl + WOFF_S0S, wh + WOFF_S0N, wl + WOFF_S0N,
                M, 256, sage0_b, bn0_g, bn0_b, bn0_m, bn0_v, 1,
                nullptr, h1h, h1l);

    // agg1 = mean h1
    gather_mean<<<(M * 32 + 255) / 256, 256>>>(h1h, h1l, csr, rowptr,
                                               a1h, a1l, M, 256);

    // h2 = relu(bn1(h1 @ ws1 + agg1 @ wn1 + b1))
    launch_gemm(h1h, h1l, 256, a1h, a1l, 256,
                wh + WOFF_S1S, wl + WOFF_S1S, wh + WOFF_S1N, wl + WOFF_S1N,
                M, 128, sage1_b, bn1_g, bn1_b, bn1_m, bn1_v, 1,
                nullptr, h2h, h2l);

    // hf = relu([h0|h2] @ rel_w + rel_b)
    launch_gemm(h0h, h0l, 128, h2h, h2l, 128,
                wh + WOFF_REL, wl + WOFF_REL,
                wh + WOFF_REL + 128 * 128, wl + WOFF_REL + 128 * 128,
                M, 128, rel_b, nullptr, nullptr, nullptr, nullptr, 1,
                nullptr, hfh, hfl);

    // c1 = relu(hf @ cls_w1 + cls_b1)
    launch_gemm(hfh, hfl, 128, hfh, hfl, 0,
                wh + WOFF_C1, wl + WOFF_C1, wh + WOFF_C1, wl + WOFF_C1,
                M, 64, cls_b1, nullptr, nullptr, nullptr, nullptr, 1,
                nullptr, c1h, c1l);

    // out = c1 @ cls_w2 + cls_b2   (fp32)
    launch_gemm(c1h, c1l, 64, c1h, c1l, 0,
                wh + WOFF_C2, wl + WOFF_C2, wh + WOFF_C2, wl + WOFF_C2,
                M, 32, cls_b2, nullptr, nullptr, nullptr, nullptr, 0,
                out, nullptr, nullptr);
}

// round 9
// speedup vs baseline: 1.0783x; 1.0783x over previous
#include <cuda_runtime.h>
#include <cuda_bf16.h>
#include <math.h>
#include <stdint.h>

#define N_NODES 100000
#define N_EDGES 800000

typedef __nv_bfloat16  bf16;
typedef __nv_bfloat162 bf162;

// ---------------- scratch (device globals; no allocs allowed) ----------------
__device__ bf16 g_xsh[(size_t)N_NODES * 128], g_xsl[(size_t)N_NODES * 128];
__device__ bf16 g_xmh[(size_t)N_NODES * 384], g_xml[(size_t)N_NODES * 384];
__device__ bf16 g_h0h[(size_t)N_NODES * 128], g_h0l[(size_t)N_NODES * 128];
__device__ bf16 g_a0h[(size_t)N_NODES * 128], g_a0l[(size_t)N_NODES * 128];
__device__ bf16 g_h1h[(size_t)N_NODES * 256], g_h1l[(size_t)N_NODES * 256];
__device__ bf16 g_a1h[(size_t)N_NODES * 256], g_a1l[(size_t)N_NODES * 256];
__device__ bf16 g_h2h[(size_t)N_NODES * 128], g_h2l[(size_t)N_NODES * 128];
__device__ bf16 g_hfh[(size_t)N_NODES * 128], g_hfl[(size_t)N_NODES * 128];
__device__ bf16 g_c1h[(size_t)N_NODES * 64],  g_c1l[(size_t)N_NODES * 64];
__device__ bf16 g_wh[262144], g_wl[262144];
__device__ int g_counts[N_NODES];
__device__ int g_rowptr[N_NODES + 1];
__device__ int g_fill  [N_NODES];
__device__ int g_csr   [N_EDGES];

// weight plane offsets (elements)
#define WOFF_ENC 0        // 512*128 = 65536
#define WOFF_S0S 65536    // 128*256 = 32768
#define WOFF_S0N 98304
#define WOFF_S1S 131072   // 256*128
#define WOFF_S1N 163840
#define WOFF_REL 196608   // 256*128
#define WOFF_C1  229376   // 128*64 = 8192
#define WOFF_C2  237568   // 64*32  = 2048
#define WOFF_END 239616

// ---------------- bf16x3 tensor-core GEMM, templated block shape ----------------
#define BK 32
#define A_STRIDE 40

__device__ __forceinline__ void cp16(uint32_t dst, const void* src, bool pred) {
    asm volatile("cp.async.cg.shared.global [%0], [%1], 16, %2;"
                 :: "r"(dst), "l"(src), "r"(pred ? 16 : 0));
}

#define LDMX4(r, addr)                                                          \
    asm volatile("ldmatrix.sync.aligned.m8n8.x4.shared.b16 {%0,%1,%2,%3},[%4];" \
                 : "=r"((r)[0]), "=r"((r)[1]), "=r"((r)[2]), "=r"((r)[3])       \
                 : "r"(addr))

#define LDMX4T(r, addr)                                                         \
    asm volatile("ldmatrix.sync.aligned.m8n8.x4.trans.shared.b16 "              \
                 "{%0,%1,%2,%3},[%4];"                                          \
                 : "=r"((r)[0]), "=r"((r)[1]), "=r"((r)[2]), "=r"((r)[3])       \
                 : "r"(addr))

#define MMA_BF16(acc, a, b0, b1)                                                \
    asm volatile(                                                               \
        "mma.sync.aligned.m16n8k16.row.col.f32.bf16.bf16.f32 "                  \
        "{%0,%1,%2,%3},{%4,%5,%6,%7},{%8,%9},{%0,%1,%2,%3};"                    \
        : "+f"((acc)[0]), "+f"((acc)[1]), "+f"((acc)[2]), "+f"((acc)[3])        \
        : "r"((a)[0]), "r"((a)[1]), "r"((a)[2]), "r"((a)[3]),                   \
          "r"(b0), "r"(b1))

template<int BM_, int BN_>
__global__ __launch_bounds__(256, 2) void gemm_bf16x3(
    const bf16* __restrict__ A0h, const bf16* __restrict__ A0l, int K0,
    const bf16* __restrict__ A1h, const bf16* __restrict__ A1l, int K1,
    const bf16* __restrict__ W0h, const bf16* __restrict__ W0l,
    const bf16* __restrict__ W1h, const bf16* __restrict__ W1l,
    int M, int N,
    const float* __restrict__ bias,
    const float* __restrict__ bng, const float* __restrict__ bnb,
    const float* __restrict__ bnm, const float* __restrict__ bnv,
    int do_relu,
    float* __restrict__ Cf, bf16* __restrict__ Ch, bf16* __restrict__ Cl)
{
    constexpr int A_PLANE_ = BM_ * A_STRIDE;
    constexpr int B_STRIDE = BN_ + 8;
    constexpr int B_PLANE  = BK * B_STRIDE;
    constexpr int STAGE_ELEMS = 2 * A_PLANE_ + 2 * B_PLANE;
    constexpr int WROWS  = BM_ / 32;                 // warp rows: 2 or 4
    constexpr int WARP_N = BN_ * WROWS / 8;          // 32 in both configs
    constexpr int NT = WARP_N / 8;                   // 4
    constexpr int P  = WARP_N / 16;                  // 2
    constexpr int NCP = BN_ / 64;                    // B cp16s per thread per plane

    extern __shared__ bf16 smem[];
    const uint32_t smem_u32 = (uint32_t)__cvta_generic_to_shared(smem);

    const int tid  = threadIdx.x;
    const int lane = tid & 31;
    const int wid  = tid >> 5;
    const int wm   = (wid % WROWS) * 32;
    const int wn   = (wid / WROWS) * WARP_N;
    const int brow = blockIdx.y * BM_;
    const int bcol = blockIdx.x * BN_;
    const int K = K0 + K1;
    const int T = K / BK;

    // A loader mapping (one or two cp16s per plane per thread)
    constexpr int ATPR = 256 / BM_;                  // threads per A row: 2 or 4
    const int a_row = tid / ATPR;
    const int a_k   = (tid % ATPR) * (32 / ATPR);
    const int a_gr  = brow + a_row;
    const bool a_ok = (a_gr < M);
    // B loader
    const int b_k  = tid >> 3;
    const int b_n0 = (tid & 7) * (BN_ / 8);

    const int a_lm = (wm + (lane & 15)) * A_STRIDE + (lane >> 4) * 8;
    const int b_lm = ((lane & 7) + ((lane >> 3) & 1) * 8) * B_STRIDE
                     + wn + (lane >> 4) * 8;

    float acc[2][NT][4];
#pragma unroll
    for (int mt = 0; mt < 2; mt++)
#pragma unroll
        for (int nt = 0; nt < NT; nt++)
#pragma unroll
            for (int i = 0; i < 4; i++) acc[mt][nt][i] = 0.f;

#define LOAD_TILE(t, st) do {                                                     \
        const int kt_ = (t) * BK;                                                 \
        { int gk0 = kt_ + a_k;                                                    \
          const bf16 *sph, *spl;                                                  \
          if (gk0 < K0) { sph = A0h + (size_t)a_gr * K0 + gk0;                    \
                          spl = A0l + (size_t)a_gr * K0 + gk0; }                  \
          else          { sph = A1h + (size_t)a_gr * K1 + (gk0 - K0);             \
                          spl = A1l + (size_t)a_gr * K1 + (gk0 - K0); }           \
          uint32_t dh = smem_u32 +                                                \
              ((st) * STAGE_ELEMS + a_row * A_STRIDE + a_k) * 2;                  \
          if (ATPR == 2) {                                                        \
              cp16(dh,      sph,     a_ok);                                       \
              cp16(dh + 16, sph + 8, a_ok);                                       \
              cp16(dh + A_PLANE_ * 2,      spl,     a_ok);                        \
              cp16(dh + A_PLANE_ * 2 + 16, spl + 8, a_ok);                        \
          } else {                                                                \
              cp16(dh,                sph, a_ok);                                 \
              cp16(dh + A_PLANE_ * 2, spl, a_ok);                                 \
          }                                                                       \
        }                                                                         \
        { int gk = kt_ + b_k;                                                     \
          const bf16 *wph, *wpl; int kk2;                                         \
          if (gk < K0) { wph = W0h; wpl = W0l; kk2 = gk; }                        \
          else         { wph = W1h; wpl = W1l; kk2 = gk - K0; }                   \
          uint32_t dbh = smem_u32 +                                               \
              ((st) * STAGE_ELEMS + 2 * A_PLANE_ + b_k * B_STRIDE + b_n0) * 2;    \
          _Pragma("unroll")                                                       \
          for (int cc = 0; cc < NCP; cc++) {                                      \
              int n0 = bcol + b_n0 + cc * 8;                                      \
              bool ok = (n0 < N);                                                 \
              cp16(dbh + cc * 16,               wph + (size_t)kk2 * N + n0, ok);  \
              cp16(dbh + cc * 16 + B_PLANE * 2, wpl + (size_t)kk2 * N + n0, ok);  \
          }                                                                       \
        }                                                                         \
        asm volatile("cp.async.commit_group;");                                   \
    } while (0)

    LOAD_TILE(0, 0);

    for (int t = 0; t < T; ++t) {
        const int st = t & 1;
        if (t + 1 < T) {
            LOAD_TILE(t + 1, st ^ 1);
            asm volatile("cp.async.wait_group 1;");
        } else {
            asm volatile("cp.async.wait_group 0;");
        }
        __syncthreads();

        const uint32_t base = smem_u32 + st * STAGE_ELEMS * 2;
#pragma unroll
        for (int k16 = 0; k16 < 2; k16++) {
            uint32_t ah[2][4], al[2][4], bh[P][4], bl[P][4];
#pragma unroll
            for (int mt = 0; mt < 2; mt++) {
                uint32_t ad = base + (a_lm + mt * 16 * A_STRIDE + k16 * 16) * 2;
                LDMX4(ah[mt], ad);
                LDMX4(al[mt], ad + A_PLANE_ * 2);
            }
#pragma unroll
            for (int p = 0; p < P; p++) {
                uint32_t bd = base + (2 * A_PLANE_ + b_lm + p * 16
                                      + k16 * 16 * B_STRIDE) * 2;
                LDMX4T(bh[p], bd);
                LDMX4T(bl[p], bd + B_PLANE * 2);
            }
#pragma unroll
            for (int mt = 0; mt < 2; mt++)
#pragma unroll
                for (int nt = 0; nt < NT; nt++) {
                    const int p = nt >> 1, q = (nt & 1) * 2;
                    MMA_BF16(acc[mt][nt], al[mt], bh[p][q], bh[p][q + 1]);
                    MMA_BF16(acc[mt][nt], ah[mt], bl[p][q], bl[p][q + 1]);
                    MMA_BF16(acc[mt][nt], ah[mt], bh[p][q], bh[p][q + 1]);
                }
        }
        __syncthreads();
    }

#pragma unroll
    for (int nt = 0; nt < NT; nt++) {
        const int col = bcol + wn + 8 * nt + 2 * (lane & 3);
        if (col >= N) continue;
        float sc0 = 1.f, sh0 = 0.f, sc1 = 1.f, sh1 = 0.f;
        if (bias) { sh0 = bias[col]; sh1 = bias[col + 1]; }
        if (bng) {
            float s0 = bng[col]     * rsqrtf(bnv[col]     + 1e-5f);
            float s1 = bng[col + 1] * rsqrtf(bnv[col + 1] + 1e-5f);
            sh0 = (sh0 - bnm[col])     * s0 + bnb[col];
            sh1 = (sh1 - bnm[col + 1]) * s1 + bnb[col + 1];
            sc0 = s0; sc1 = s1;
        }
#pragma unroll
        for (int mt = 0; mt < 2; mt++) {
#pragma unroll
            for (int half = 0; half < 2; half++) {
                const int row = brow + wm + 16 * mt + (lane >> 2) + 8 * half;
                if (row >= M) continue;
                const float* c = acc[mt][nt] + 2 * half;
                float v0 = c[0] * sc0 + sh0;
                float v1 = c[1] * sc1 + sh1;
                if (do_relu) { v0 = fmaxf(v0, 0.f); v1 = fmaxf(v1, 0.f); }
                if (Ch) {
                    bf162 hi = __float22bfloat162_rn(make_float2(v0, v1));
                    float2 hf2 = __bfloat1622float2(hi);
                    bf162 lo = __float22bfloat162_rn(
                        make_float2(v0 - hf2.x, v1 - hf2.y));
                    *(bf162*)(Ch + (size_t)row * N + col) = hi;
                    *(bf162*)(Cl + (size_t)row * N + col) = lo;
                } else {
                    *(float2*)(Cf + (size_t)row * N + col) = make_float2(v0, v1);
                }
            }
        }
    }
}

// ---------------- split fp32 -> bf16 hi/lo planes (inputs) ----------------
__global__ void split_planes(const float* __restrict__ x,
                             bf16* __restrict__ xh, bf16* __restrict__ xl, int n4)
{
    int i = blockIdx.x * blockDim.x + threadIdx.x;
    if (i >= n4) return;
    float4 v = ((const float4*)x)[i];
    bf162 h0 = __float22bfloat162_rn(make_float2(v.x, v.y));
    bf162 h1 = __float22bfloat162_rn(make_float2(v.z, v.w));
    float2 f0 = __bfloat1622float2(h0);
    float2 f1 = __bfloat1622float2(h1);
    bf162 l0 = __float22bfloat162_rn(make_float2(v.x - f0.x, v.y - f0.y));
    bf162 l1 = __float22bfloat162_rn(make_float2(v.z - f1.x, v.w - f1.y));
    ((bf162*)xh)[i * 2]     = h0;
    ((bf162*)xh)[i * 2 + 1] = h1;
    ((bf162*)xl)[i * 2]     = l0;
    ((bf162*)xl)[i * 2 + 1] = l1;
}

// ---------------- merged weight split: all 8 segments in one launch ----------
struct WSeg { const float* src[8]; int beg[9]; };

__global__ void split_weights(WSeg ws, bf16* __restrict__ wh, bf16* __restrict__ wl)
{
    int i4 = blockIdx.x * blockDim.x + threadIdx.x;
    int i  = i4 * 4;
    if (i >= ws.beg[8]) return;
    int s = 0;
#pragma unroll
    for (int k = 0; k < 7; k++) s += (i >= ws.beg[k + 1]) ? 1 : 0;
    float4 v = *(const float4*)(ws.src[s] + (i - ws.beg[s]));
    bf162 h0 = __float22bfloat162_rn(make_float2(v.x, v.y));
    bf162 h1 = __float22bfloat162_rn(make_float2(v.z, v.w));
    float2 f0 = __bfloat1622float2(h0);
    float2 f1 = __bfloat1622float2(h1);
    bf162 l0 = __float22bfloat162_rn(make_float2(v.x - f0.x, v.y - f0.y));
    bf162 l1 = __float22bfloat162_rn(make_float2(v.z - f1.x, v.w - f1.y));
    ((bf162*)wh)[i4 * 2]     = h0;
    ((bf162*)wh)[i4 * 2 + 1] = h1;
    ((bf162*)wl)[i4 * 2]     = l0;
    ((bf162*)wl)[i4 * 2 + 1] = l1;
}

// ---------------- CSR construction ----------------
__global__ void count_deg(const int* __restrict__ dst, int* __restrict__ counts, int E)
{
    int e = blockIdx.x * blockDim.x + threadIdx.x;
    if (e < E) atomicAdd(&counts[dst[e]], 1);
}

__global__ __launch_bounds__(1024) void scan_counts(
    const int* __restrict__ counts, int* __restrict__ rowptr,
    int* __restrict__ fill, int n)
{
    __shared__ int part[1024];
    const int tid = threadIdx.x;
    const int chunk = (n + 1023) / 1024;
    const int begin = min(tid * chunk, n);
    const int end   = min(begin + chunk, n);
    int s = 0;
    for (int i = begin; i < end; i++) s += counts[i];
    part[tid] = s;
    __syncthreads();
    for (int off = 1; off < 1024; off <<= 1) {
        int v = (tid >= off) ? part[tid - off] : 0;
        __syncthreads();
        part[tid] += v;
        __syncthreads();
    }
    int pre = (tid == 0) ? 0 : part[tid - 1];
    for (int i = begin; i < end; i++) {
        rowptr[i] = pre;
        fill[i]   = pre;
        pre += counts[i];
    }
    if (end == n && begin <= n) rowptr[n] = pre;
}

__global__ void fill_csr(const int* __restrict__ src, const int* __restrict__ dst,
                         int* __restrict__ fill, int* __restrict__ csr, int E)
{
    int e = blockIdx.x * blockDim.x + threadIdx.x;
    if (e < E) {
        int pos = atomicAdd(&fill[dst[e]], 1);
        csr[pos] = src[e];
    }
}

// ---------------- CSR gather mean: warp per dst node, writes planes ----------
__global__ void gather_mean(const bf16* __restrict__ hh, const bf16* __restrict__ hl,
                            const int* __restrict__ csr, const int* __restrict__ rowptr,
                            bf16* __restrict__ oh, bf16* __restrict__ ol,
                            int Nn, int D)
{
    const int warp = (blockIdx.x * blockDim.x + threadIdx.x) >> 5;
    const int lane = threadIdx.x & 31;
    if (warp >= Nn) return;
    const int e0 = rowptr[warp];
    const int e1 = rowptr[warp + 1];
    const float inv = 1.f / (float)max(e1 - e0, 1);
    const int nseg = D >> 7;
    float acc[8];
#pragma unroll
    for (int i = 0; i < 8; i++) acc[i] = 0.f;

    for (int e = e0; e < e1; e++) {
        const int s = csr[e];
        const bf16* rh = hh + (size_t)s * D + lane * 4;
        const bf16* rl = hl + (size_t)s * D + lane * 4;
#pragma unroll
        for (int g = 0; g < 2; g++) {
            if (g < nseg) {
                uint2 vh = *(const uint2*)(rh + g * 128);
                uint2 vl = *(const uint2*)(rl + g * 128);
                float2 a0 = __bfloat1622float2(*(const bf162*)&vh.x);
                float2 a1 = __bfloat1622float2(*(const bf162*)&vh.y);
                float2 b0 = __bfloat1622float2(*(const bf162*)&vl.x);
                float2 b1 = __bfloat1622float2(*(const bf162*)&vl.y);
                acc[g * 4 + 0] += a0.x + b0.x;
                acc[g * 4 + 1] += a0.y + b0.y;
                acc[g * 4 + 2] += a1.x + b1.x;
                acc[g * 4 + 3] += a1.y + b1.y;
            }
        }
    }

#pragma unroll
    for (int g = 0; g < 2; g++) {
        if (g < nseg) {
            float v0 = acc[g * 4 + 0] * inv;
            float v1 = acc[g * 4 + 1] * inv;
            float v2 = acc[g * 4 + 2] * inv;
            float v3 = acc[g * 4 + 3] * inv;
            bf162 h0 = __float22bfloat162_rn(make_float2(v0, v1));
            bf162 h1 = __float22bfloat162_rn(make_float2(v2, v3));
            float2 f0 = __bfloat1622float2(h0);
            float2 f1 = __bfloat1622float2(h1);
            bf162 l0 = __float22bfloat162_rn(make_float2(v0 - f0.x, v1 - f0.y));
            bf162 l1 = __float22bfloat162_rn(make_float2(v2 - f1.x, v3 - f1.y));
            uint2 wh_, wl_;
            wh_.x = *(uint32_t*)&h0; wh_.y = *(uint32_t*)&h1;
            wl_.x = *(uint32_t*)&l0; wl_.y = *(uint32_t*)&l1;
            *(uint2*)(oh + (size_t)warp * D + g * 128 + lane * 4) = wh_;
            *(uint2*)(ol + (size_t)warp * D + g * 128 + lane * 4) = wl_;
        }
    }
}

// ---------------- launch helper ----------------
static inline void launch_gemm(
    const bf16* A0h, const bf16* A0l, int K0,
    const bf16* A1h, const bf16* A1l, int K1,
    const bf16* W0h, const bf16* W0l, const bf16* W1h, const bf16* W1l,
    int M, int N,
    const float* bias, const float* bng, const float* bnb,
    const float* bnm, const float* bnv,
    int do_relu, float* Cf, bf16* Ch, bf16* Cl)
{
    if (N >= 128) {
        constexpr int BM_ = 64, BN_ = 128;
        constexpr int SMEM = 2 * (2 * BM_ * A_STRIDE + 2 * BK * (BN_ + 8)) * 2;
        dim3 grid(N / BN_, (M + BM_ - 1) / BM_);
        gemm_bf16x3<BM_, BN_><<<grid, 256, SMEM>>>(
            A0h, A0l, K0, A1h, A1l, K1, W0h, W0l, W1h, W1l, M, N,
            bias, bng, bnb, bnm, bnv, do_relu, Cf, Ch, Cl);
    } else {
        constexpr int BM_ = 128, BN_ = 64;
        constexpr int SMEM = 2 * (2 * BM_ * A_STRIDE + 2 * BK * (BN_ + 8)) * 2;
        dim3 grid((N + BN_ - 1) / BN_, (M + BM_ - 1) / BM_);
        gemm_bf16x3<BM_, BN_><<<grid, 256, SMEM>>>(
            A0h, A0l, K0, A1h, A1l, K1, W0h, W0l, W1h, W1l, M, N,
            bias, bng, bnb, bnm, bnv, do_relu, Cf, Ch, Cl);
    }
}

extern "C" void kernel_launch(void* const* d_in, const int* in_sizes, int n_in,
                              void* d_out, int out_size)
{
    const float* structural = (const float*)d_in[0];
    const float* multimodal = (const float*)d_in[1];
    const int*   src        = (const int*)  d_in[2];
    const int*   dst        = (const int*)  d_in[3];
    const float* enc_w      = (const float*)d_in[4];
    const float* enc_b      = (const float*)d_in[5];
    const float* sage0_ws   = (const float*)d_in[6];
    const float* sage0_wn   = (const float*)d_in[7];
    const float* sage0_b    = (const float*)d_in[8];
    const float* bn0_g      = (const float*)d_in[9];
    const float* bn0_b      = (const float*)d_in[10];
    const float* bn0_m      = (const float*)d_in[11];
    const float* bn0_v      = (const float*)d_in[12];
    const float* sage1_ws   = (const float*)d_in[13];
    const float* sage1_wn   = (const float*)d_in[14];
    const float* sage1_b    = (const float*)d_in[15];
    const float* bn1_g      = (const float*)d_in[16];
    const float* bn1_b      = (const float*)d_in[17];
    const float* bn1_m      = (const float*)d_in[18];
    const float* bn1_v      = (const float*)d_in[19];
    const float* rel_w      = (const float*)d_in[20];
    const float* rel_b      = (const float*)d_in[21];
    const float* cls_w1     = (const float*)d_in[22];
    const float* cls_b1     = (const float*)d_in[23];
    const float* cls_w2     = (const float*)d_in[24];
    const float* cls_b2     = (const float*)d_in[25];
    float* out = (float*)d_out;

#define SYMADDR(var, sym) void* p_##var; cudaGetSymbolAddress(&p_##var, sym);
    SYMADDR(xsh, g_xsh) SYMADDR(xsl, g_xsl) SYMADDR(xmh, g_xmh) SYMADDR(xml, g_xml)
    SYMADDR(h0h, g_h0h) SYMADDR(h0l, g_h0l) SYMADDR(a0h, g_a0h) SYMADDR(a0l, g_a0l)
    SYMADDR(h1h, g_h1h) SYMADDR(h1l, g_h1l) SYMADDR(a1h, g_a1h) SYMADDR(a1l, g_a1l)
    SYMADDR(h2h, g_h2h) SYMADDR(h2l, g_h2l) SYMADDR(hfh, g_hfh) SYMADDR(hfl, g_hfl)
    SYMADDR(c1h, g_c1h) SYMADDR(c1l, g_c1l)
    SYMADDR(wh, g_wh) SYMADDR(wl, g_wl)
    SYMADDR(counts, g_counts) SYMADDR(rowptr, g_rowptr)
    SYMADDR(fill, g_fill) SYMADDR(csr, g_csr)
#undef SYMADDR

    bf16* xsh = (bf16*)p_xsh; bf16* xsl = (bf16*)p_xsl;
    bf16* xmh = (bf16*)p_xmh; bf16* xml = (bf16*)p_xml;
    bf16* h0h = (bf16*)p_h0h; bf16* h0l = (bf16*)p_h0l;
    bf16* a0h = (bf16*)p_a0h; bf16* a0l = (bf16*)p_a0l;
    bf16* h1h = (bf16*)p_h1h; bf16* h1l = (bf16*)p_h1l;
    bf16* a1h = (bf16*)p_a1h; bf16* a1l = (bf16*)p_a1l;
    bf16* h2h = (bf16*)p_h2h; bf16* h2l = (bf16*)p_h2l;
    bf16* hfh = (bf16*)p_hfh; bf16* hfl = (bf16*)p_hfl;
    bf16* c1h = (bf16*)p_c1h; bf16* c1l = (bf16*)p_c1l;
    bf16* wh = (bf16*)p_wh; bf16* wl = (bf16*)p_wl;
    int* counts = (int*)p_counts; int* rowptr = (int*)p_rowptr;
    int* fill   = (int*)p_fill;   int* csr    = (int*)p_csr;

    {
        constexpr int SMEM_A = 2 * (2 * 64 * A_STRIDE + 2 * BK * (128 + 8)) * 2;
        constexpr int SMEM_B = 2 * (2 * 128 * A_STRIDE + 2 * BK * (64 + 8)) * 2;
        cudaFuncSetAttribute((const void*)gemm_bf16x3<64, 128>,
                             cudaFuncAttributeMaxDynamicSharedMemorySize, SMEM_A);
        cudaFuncSetAttribute((const void*)gemm_bf16x3<128, 64>,
                             cudaFuncAttributeMaxDynamicSharedMemorySize, SMEM_B);
    }

    const int M = N_NODES, E = N_EDGES;

    // ---- CSR build ----
    cudaMemsetAsync(counts, 0, N_NODES * sizeof(int), 0);
    count_deg<<<(E + 255) / 256, 256>>>(dst, counts, E);
    scan_counts<<<1, 1024>>>(counts, rowptr, fill, M);
    fill_csr<<<(E + 255) / 256, 256>>>(src, dst, fill, csr, E);

    // ---- split inputs (2 launches) + all weights (1 launch) ----
    {
        int n4 = (M * 128) / 4;
        split_planes<<<(n4 + 255) / 256, 256>>>(structural, xsh, xsl, n4);
        n4 = (M * 384) / 4;
        split_planes<<<(n4 + 255) / 256, 256>>>(multimodal, xmh, xml, n4);

        WSeg ws;
        ws.src[0] = enc_w;    ws.beg[0] = WOFF_ENC;
        ws.src[1] = sage0_ws; ws.beg[1] = WOFF_S0S;
        ws.src[2] = sage0_wn; ws.beg[2] = WOFF_S0N;
        ws.src[3] = sage1_ws; ws.beg[3] = WOFF_S1S;
        ws.src[4] = sage1_wn; ws.beg[4] = WOFF_S1N;
        ws.src[5] = rel_w;    ws.beg[5] = WOFF_REL;
        ws.src[6] = cls_w1;   ws.beg[6] = WOFF_C1;
        ws.src[7] = cls_w2;   ws.beg[7] = WOFF_C2;
        ws.beg[8] = WOFF_END;
        int w4 = WOFF_END / 4;
        split_weights<<<(w4 + 255) / 256, 256>>>(ws, wh, wl);
    }

    // h0 = relu([xs|xm] @ enc_w + enc_b)
    launch_gemm(xsh, xsl, 128, xmh, xml, 384,
                wh + WOFF_ENC, wl + WOFF_ENC,
                wh + WOFF_ENC + 128 * 128, wl + WOFF_ENC + 128 * 128,
                M, 128, enc_b, nullptr, nullptr, nullptr, nullptr, 1,
                nullptr, h0h, h0l);

    // agg0 = mean h0
    gather_mean<<<(M * 32 + 255) / 256, 256>>>(h0h, h0l, csr, rowptr,
                                               a0h, a0l, M, 128);

    // h1 = relu(bn0(h0 @ ws0 + agg0 @ wn0 + b0))
    launch_gemm(h0h, h0l, 128, a0h, a0l, 128,
                wh + WOFF_S0S, wl + WOFF_S0S, wh + WOFF_S0N, wl + WOFF_S0N,
                M, 256, sage0_b, bn0_g, bn0_b, bn0_m, bn0_v, 1,
                nullptr, h1h, h1l);

    // agg1 = mean h1
    gather_mean<<<(M * 32 + 255) / 256, 256>>>(h1h, h1l, csr, rowptr,
                                               a1h, a1l, M, 256);

    // h2 = relu(bn1(h1 @ ws1 + agg1 @ wn1 + b1))
    launch_gemm(h1h, h1l, 256, a1h, a1l, 256,
                wh + WOFF_S1S, wl + WOFF_S1S, wh + WOFF_S1N, wl + WOFF_S1N,
                M, 128, sage1_b, bn1_g, bn1_b, bn1_m, bn1_v, 1,
                nullptr, h2h, h2l);

    // hf = relu([h0|h2] @ rel_w + rel_b)
    launch_gemm(h0h, h0l, 128, h2h, h2l, 128,
                wh + WOFF_REL, wl + WOFF_REL,
                wh + WOFF_REL + 128 * 128, wl + WOFF_REL + 128 * 128,
                M, 128, rel_b, nullptr, nullptr, nullptr, nullptr, 1,
                nullptr, hfh, hfl);

    // c1 = relu(hf @ cls_w1 + cls_b1)
    launch_gemm(hfh, hfl, 128, hfh, hfl, 0,
                wh + WOFF_C1, wl + WOFF_C1, wh + WOFF_C1, wl + WOFF_C1,
                M, 64, cls_b1, nullptr, nullptr, nullptr, nullptr, 1,
                nullptr, c1h, c1l);

    // out = c1 @ cls_w2 + cls_b2   (fp32)
    launch_gemm(c1h, c1l, 64, c1h, c1l, 0,
                wh + WOFF_C2, wl + WOFF_C2, wh + WOFF_C2, wl + WOFF_C2,
                M, 32, cls_b2, nullptr, nullptr, nullptr, nullptr, 0,
                out, nullptr, nullptr);
}

// round 10
// speedup vs baseline: 1.1071x; 1.0268x over previous
#include <cuda_runtime.h>
#include <cuda_bf16.h>
#include <math.h>
#include <stdint.h>

#define N_NODES 100000
#define N_EDGES 800000

typedef __nv_bfloat16  bf16;
typedef __nv_bfloat162 bf162;

// ---------------- scratch (device globals; no allocs allowed) ----------------
__device__ bf16 g_xsh[(size_t)N_NODES * 128], g_xsl[(size_t)N_NODES * 128];
__device__ bf16 g_xmh[(size_t)N_NODES * 384], g_xml[(size_t)N_NODES * 384];
__device__ bf16 g_h0h[(size_t)N_NODES * 128], g_h0l[(size_t)N_NODES * 128];
__device__ bf16 g_a0h[(size_t)N_NODES * 128], g_a0l[(size_t)N_NODES * 128];
__device__ bf16 g_h1h[(size_t)N_NODES * 256], g_h1l[(size_t)N_NODES * 256];
__device__ bf16 g_h2h[(size_t)N_NODES * 128], g_h2l[(size_t)N_NODES * 128];
__device__ bf16 g_hfh[(size_t)N_NODES * 128], g_hfl[(size_t)N_NODES * 128];
__device__ bf16 g_c1h[(size_t)N_NODES * 64],  g_c1l[(size_t)N_NODES * 64];
__device__ float g_s1f[(size_t)N_NODES * 128];   // h1 @ Ws1  (fp32)
__device__ float g_g1f[(size_t)N_NODES * 128];   // h1 @ Wn1  (fp32)
__device__ bf16 g_wh[262144], g_wl[262144];
__device__ int g_counts[N_NODES];
__device__ int g_rowptr[N_NODES + 1];
__device__ int g_fill  [N_NODES];
__device__ int g_csr   [N_EDGES];

// weight plane offsets (elements)
#define WOFF_ENC 0        // 512*128 = 65536
#define WOFF_S0S 65536    // 128*256 = 32768
#define WOFF_S0N 98304
#define WOFF_S1S 131072   // 256*128
#define WOFF_S1N 163840
#define WOFF_REL 196608   // 256*128
#define WOFF_C1  229376   // 128*64 = 8192
#define WOFF_C2  237568   // 64*32  = 2048
#define WOFF_END 239616

// ---------------- bf16x3 tensor-core GEMM, templated block shape ----------------
#define BK 32
#define A_STRIDE 40

__device__ __forceinline__ void cp16(uint32_t dst, const void* src, bool pred) {
    asm volatile("cp.async.cg.shared.global [%0], [%1], 16, %2;"
                 :: "r"(dst), "l"(src), "r"(pred ? 16 : 0));
}

#define LDMX4(r, addr)                                                          \
    asm volatile("ldmatrix.sync.aligned.m8n8.x4.shared.b16 {%0,%1,%2,%3},[%4];" \
                 : "=r"((r)[0]), "=r"((r)[1]), "=r"((r)[2]), "=r"((r)[3])       \
                 : "r"(addr))

#define LDMX4T(r, addr)                                                         \
    asm volatile("ldmatrix.sync.aligned.m8n8.x4.trans.shared.b16 "              \
                 "{%0,%1,%2,%3},[%4];"                                          \
                 : "=r"((r)[0]), "=r"((r)[1]), "=r"((r)[2]), "=r"((r)[3])       \
                 : "r"(addr))

#define MMA_BF16(acc, a, b0, b1)                                                \
    asm volatile(                                                               \
        "mma.sync.aligned.m16n8k16.row.col.f32.bf16.bf16.f32 "                  \
        "{%0,%1,%2,%3},{%4,%5,%6,%7},{%8,%9},{%0,%1,%2,%3};"                    \
        : "+f"((acc)[0]), "+f"((acc)[1]), "+f"((acc)[2]), "+f"((acc)[3])        \
        : "r"((a)[0]), "r"((a)[1]), "r"((a)[2]), "r"((a)[3]),                   \
          "r"(b0), "r"(b1))

template<int BM_, int BN_>
__global__ __launch_bounds__(256, 2) void gemm_bf16x3(
    const bf16* __restrict__ A0h, const bf16* __restrict__ A0l, int K0,
    const bf16* __restrict__ A1h, const bf16* __restrict__ A1l, int K1,
    const bf16* __restrict__ W0h, const bf16* __restrict__ W0l,
    const bf16* __restrict__ W1h, const bf16* __restrict__ W1l,
    int M, int N,
    const float* __restrict__ bias,
    const float* __restrict__ bng, const float* __restrict__ bnb,
    const float* __restrict__ bnm, const float* __restrict__ bnv,
    int do_relu,
    float* __restrict__ Cf, bf16* __restrict__ Ch, bf16* __restrict__ Cl)
{
    constexpr int A_PLANE_ = BM_ * A_STRIDE;
    constexpr int B_STRIDE = BN_ + 8;
    constexpr int B_PLANE  = BK * B_STRIDE;
    constexpr int STAGE_ELEMS = 2 * A_PLANE_ + 2 * B_PLANE;
    constexpr int WROWS  = BM_ / 32;
    constexpr int WARP_N = BN_ * WROWS / 8;          // 32 in both configs
    constexpr int NT = WARP_N / 8;
    constexpr int P  = WARP_N / 16;
    constexpr int NCP = BN_ / 64;

    extern __shared__ bf16 smem[];
    const uint32_t smem_u32 = (uint32_t)__cvta_generic_to_shared(smem);

    const int tid  = threadIdx.x;
    const int lane = tid & 31;
    const int wid  = tid >> 5;
    const int wm   = (wid % WROWS) * 32;
    const int wn   = (wid / WROWS) * WARP_N;
    const int brow = blockIdx.y * BM_;
    const int bcol = blockIdx.x * BN_;
    const int K = K0 + K1;
    const int T = K / BK;

    constexpr int ATPR = 256 / BM_;
    const int a_row = tid / ATPR;
    const int a_k   = (tid % ATPR) * (32 / ATPR);
    const int a_gr  = brow + a_row;
    const bool a_ok = (a_gr < M);
    const int b_k  = tid >> 3;
    const int b_n0 = (tid & 7) * (BN_ / 8);

    const int a_lm = (wm + (lane & 15)) * A_STRIDE + (lane >> 4) * 8;
    const int b_lm = ((lane & 7) + ((lane >> 3) & 1) * 8) * B_STRIDE
                     + wn + (lane >> 4) * 8;

    float acc[2][NT][4];
#pragma unroll
    for (int mt = 0; mt < 2; mt++)
#pragma unroll
        for (int nt = 0; nt < NT; nt++)
#pragma unroll
            for (int i = 0; i < 4; i++) acc[mt][nt][i] = 0.f;

#define LOAD_TILE(t, st) do {                                                     \
        const int kt_ = (t) * BK;                                                 \
        { int gk0 = kt_ + a_k;                                                    \
          const bf16 *sph, *spl;                                                  \
          if (gk0 < K0) { sph = A0h + (size_t)a_gr * K0 + gk0;                    \
                          spl = A0l + (size_t)a_gr * K0 + gk0; }                  \
          else          { sph = A1h + (size_t)a_gr * K1 + (gk0 - K0);             \
                          spl = A1l + (size_t)a_gr * K1 + (gk0 - K0); }           \
          uint32_t dh = smem_u32 +                                                \
              ((st) * STAGE_ELEMS + a_row * A_STRIDE + a_k) * 2;                  \
          if (ATPR == 2) {                                                        \
              cp16(dh,      sph,     a_ok);                                       \
              cp16(dh + 16, sph + 8, a_ok);                                       \
              cp16(dh + A_PLANE_ * 2,      spl,     a_ok);                        \
              cp16(dh + A_PLANE_ * 2 + 16, spl + 8, a_ok);                        \
          } else {                                                                \
              cp16(dh,                sph, a_ok);                                 \
              cp16(dh + A_PLANE_ * 2, spl, a_ok);                                 \
          }                                                                       \
        }                                                                         \
        { int gk = kt_ + b_k;                                                     \
          const bf16 *wph, *wpl; int kk2;                                         \
          if (gk < K0) { wph = W0h; wpl = W0l; kk2 = gk; }                        \
          else         { wph = W1h; wpl = W1l; kk2 = gk - K0; }                   \
          uint32_t dbh = smem_u32 +                                               \
              ((st) * STAGE_ELEMS + 2 * A_PLANE_ + b_k * B_STRIDE + b_n0) * 2;    \
          _Pragma("unroll")                                                       \
          for (int cc = 0; cc < NCP; cc++) {                                      \
              int n0 = bcol + b_n0 + cc * 8;                                      \
              bool ok = (n0 < N);                                                 \
              cp16(dbh + cc * 16,               wph + (size_t)kk2 * N + n0, ok);  \
              cp16(dbh + cc * 16 + B_PLANE * 2, wpl + (size_t)kk2 * N + n0, ok);  \
          }                                                                       \
        }                                                                         \
        asm volatile("cp.async.commit_group;");                                   \
    } while (0)

    LOAD_TILE(0, 0);

    for (int t = 0; t < T; ++t) {
        const int st = t & 1;
        if (t + 1 < T) {
            LOAD_TILE(t + 1, st ^ 1);
            asm volatile("cp.async.wait_group 1;");
        } else {
            asm volatile("cp.async.wait_group 0;");
        }
        __syncthreads();

        const uint32_t base = smem_u32 + st * STAGE_ELEMS * 2;
#pragma unroll
        for (int k16 = 0; k16 < 2; k16++) {
            uint32_t ah[2][4], al[2][4], bh[P][4], bl[P][4];
#pragma unroll
            for (int mt = 0; mt < 2; mt++) {
                uint32_t ad = base + (a_lm + mt * 16 * A_STRIDE + k16 * 16) * 2;
                LDMX4(ah[mt], ad);
                LDMX4(al[mt], ad + A_PLANE_ * 2);
            }
#pragma unroll
            for (int p = 0; p < P; p++) {
                uint32_t bd = base + (2 * A_PLANE_ + b_lm + p * 16
                                      + k16 * 16 * B_STRIDE) * 2;
                LDMX4T(bh[p], bd);
                LDMX4T(bl[p], bd + B_PLANE * 2);
            }
#pragma unroll
            for (int mt = 0; mt < 2; mt++)
#pragma unroll
                for (int nt = 0; nt < NT; nt++) {
                    const int p = nt >> 1, q = (nt & 1) * 2;
                    MMA_BF16(acc[mt][nt], al[mt], bh[p][q], bh[p][q + 1]);
                    MMA_BF16(acc[mt][nt], ah[mt], bl[p][q], bl[p][q + 1]);
                    MMA_BF16(acc[mt][nt], ah[mt], bh[p][q], bh[p][q + 1]);
                }
        }
        __syncthreads();
    }

#pragma unroll
    for (int nt = 0; nt < NT; nt++) {
        const int col = bcol + wn + 8 * nt + 2 * (lane & 3);
        if (col >= N) continue;
        float sc0 = 1.f, sh0 = 0.f, sc1 = 1.f, sh1 = 0.f;
        if (bias) { sh0 = bias[col]; sh1 = bias[col + 1]; }
        if (bng) {
            float s0 = bng[col]     * rsqrtf(bnv[col]     + 1e-5f);
            float s1 = bng[col + 1] * rsqrtf(bnv[col + 1] + 1e-5f);
            sh0 = (sh0 - bnm[col])     * s0 + bnb[col];
            sh1 = (sh1 - bnm[col + 1]) * s1 + bnb[col + 1];
            sc0 = s0; sc1 = s1;
        }
#pragma unroll
        for (int mt = 0; mt < 2; mt++) {
#pragma unroll
            for (int half = 0; half < 2; half++) {
                const int row = brow + wm + 16 * mt + (lane >> 2) + 8 * half;
                if (row >= M) continue;
                const float* c = acc[mt][nt] + 2 * half;
                float v0 = c[0] * sc0 + sh0;
                float v1 = c[1] * sc1 + sh1;
                if (do_relu) { v0 = fmaxf(v0, 0.f); v1 = fmaxf(v1, 0.f); }
                if (Ch) {
                    bf162 hi = __float22bfloat162_rn(make_float2(v0, v1));
                    float2 hf2 = __bfloat1622float2(hi);
                    bf162 lo = __float22bfloat162_rn(
                        make_float2(v0 - hf2.x, v1 - hf2.y));
                    *(bf162*)(Ch + (size_t)row * N + col) = hi;
                    *(bf162*)(Cl + (size_t)row * N + col) = lo;
                } else {
                    *(float2*)(Cf + (size_t)row * N + col) = make_float2(v0, v1);
                }
            }
        }
    }
}

// ---------------- split fp32 -> bf16 hi/lo planes (inputs) ----------------
__global__ void split_planes(const float* __restrict__ x,
                             bf16* __restrict__ xh, bf16* __restrict__ xl, int n4)
{
    int i = blockIdx.x * blockDim.x + threadIdx.x;
    if (i >= n4) return;
    float4 v = ((const float4*)x)[i];
    bf162 h0 = __float22bfloat162_rn(make_float2(v.x, v.y));
    bf162 h1 = __float22bfloat162_rn(make_float2(v.z, v.w));
    float2 f0 = __bfloat1622float2(h0);
    float2 f1 = __bfloat1622float2(h1);
    bf162 l0 = __float22bfloat162_rn(make_float2(v.x - f0.x, v.y - f0.y));
    bf162 l1 = __float22bfloat162_rn(make_float2(v.z - f1.x, v.w - f1.y));
    ((bf162*)xh)[i * 2]     = h0;
    ((bf162*)xh)[i * 2 + 1] = h1;
    ((bf162*)xl)[i * 2]     = l0;
    ((bf162*)xl)[i * 2 + 1] = l1;
}

// ---------------- merged weight split: all 8 segments in one launch ----------
struct WSeg { const float* src[8]; int beg[9]; };

__global__ void split_weights(WSeg ws, bf16* __restrict__ wh, bf16* __restrict__ wl)
{
    int i4 = blockIdx.x * blockDim.x + threadIdx.x;
    int i  = i4 * 4;
    if (i >= ws.beg[8]) return;
    int s = 0;
#pragma unroll
    for (int k = 0; k < 7; k++) s += (i >= ws.beg[k + 1]) ? 1 : 0;
    float4 v = *(const float4*)(ws.src[s] + (i - ws.beg[s]));
    bf162 h0 = __float22bfloat162_rn(make_float2(v.x, v.y));
    bf162 h1 = __float22bfloat162_rn(make_float2(v.z, v.w));
    float2 f0 = __bfloat1622float2(h0);
    float2 f1 = __bfloat1622float2(h1);
    bf162 l0 = __float22bfloat162_rn(make_float2(v.x - f0.x, v.y - f0.y));
    bf162 l1 = __float22bfloat162_rn(make_float2(v.z - f1.x, v.w - f1.y));
    ((bf162*)wh)[i4 * 2]     = h0;
    ((bf162*)wh)[i4 * 2 + 1] = h1;
    ((bf162*)wl)[i4 * 2]     = l0;
    ((bf162*)wl)[i4 * 2 + 1] = l1;
}

// ---------------- CSR construction ----------------
__global__ void count_deg(const int* __restrict__ dst, int* __restrict__ counts, int E)
{
    int e = blockIdx.x * blockDim.x + threadIdx.x;
    if (e < E) atomicAdd(&counts[dst[e]], 1);
}

__global__ __launch_bounds__(1024) void scan_counts(
    const int* __restrict__ counts, int* __restrict__ rowptr,
    int* __restrict__ fill, int n)
{
    __shared__ int part[1024];
    const int tid = threadIdx.x;
    const int chunk = (n + 1023) / 1024;
    const int begin = min(tid * chunk, n);
    const int end   = min(begin + chunk, n);
    int s = 0;
    for (int i = begin; i < end; i++) s += counts[i];
    part[tid] = s;
    __syncthreads();
    for (int off = 1; off < 1024; off <<= 1) {
        int v = (tid >= off) ? part[tid - off] : 0;
        __syncthreads();
        part[tid] += v;
        __syncthreads();
    }
    int pre = (tid == 0) ? 0 : part[tid - 1];
    for (int i = begin; i < end; i++) {
        rowptr[i] = pre;
        fill[i]   = pre;
        pre += counts[i];
    }
    if (end == n && begin <= n) rowptr[n] = pre;
}

__global__ void fill_csr(const int* __restrict__ src, const int* __restrict__ dst,
                         int* __restrict__ fill, int* __restrict__ csr, int E)
{
    int e = blockIdx.x * blockDim.x + threadIdx.x;
    if (e < E) {
        int pos = atomicAdd(&fill[dst[e]], 1);
        csr[pos] = src[e];
    }
}

// ---------------- CSR gather mean over bf16 planes (layer-0) ----------------
__global__ void gather_mean(const bf16* __restrict__ hh, const bf16* __restrict__ hl,
                            const int* __restrict__ csr, const int* __restrict__ rowptr,
                            bf16* __restrict__ oh, bf16* __restrict__ ol,
                            int Nn, int D)
{
    const int warp = (blockIdx.x * blockDim.x + threadIdx.x) >> 5;
    const int lane = threadIdx.x & 31;
    if (warp >= Nn) return;
    const int e0 = rowptr[warp];
    const int e1 = rowptr[warp + 1];
    const float inv = 1.f / (float)max(e1 - e0, 1);
    const int nseg = D >> 7;
    float acc[8];
#pragma unroll
    for (int i = 0; i < 8; i++) acc[i] = 0.f;

    for (int e = e0; e < e1; e++) {
        const int s = csr[e];
        const bf16* rh = hh + (size_t)s * D + lane * 4;
        const bf16* rl = hl + (size_t)s * D + lane * 4;
#pragma unroll
        for (int g = 0; g < 2; g++) {
            if (g < nseg) {
                uint2 vh = *(const uint2*)(rh + g * 128);
                uint2 vl = *(const uint2*)(rl + g * 128);
                float2 a0 = __bfloat1622float2(*(const bf162*)&vh.x);
                float2 a1 = __bfloat1622float2(*(const bf162*)&vh.y);
                float2 b0 = __bfloat1622float2(*(const bf162*)&vl.x);
                float2 b1 = __bfloat1622float2(*(const bf162*)&vl.y);
                acc[g * 4 + 0] += a0.x + b0.x;
                acc[g * 4 + 1] += a0.y + b0.y;
                acc[g * 4 + 2] += a1.x + b1.x;
                acc[g * 4 + 3] += a1.y + b1.y;
            }
        }
    }

#pragma unroll
    for (int g = 0; g < 2; g++) {
        if (g < nseg) {
            float v0 = acc[g * 4 + 0] * inv;
            float v1 = acc[g * 4 + 1] * inv;
            float v2 = acc[g * 4 + 2] * inv;
            float v3 = acc[g * 4 + 3] * inv;
            bf162 h0 = __float22bfloat162_rn(make_float2(v0, v1));
            bf162 h1 = __float22bfloat162_rn(make_float2(v2, v3));
            float2 f0 = __bfloat1622float2(h0);
            float2 f1 = __bfloat1622float2(h1);
            bf162 l0 = __float22bfloat162_rn(make_float2(v0 - f0.x, v1 - f0.y));
            bf162 l1 = __float22bfloat162_rn(make_float2(v2 - f1.x, v3 - f1.y));
            uint2 wh_, wl_;
            wh_.x = *(uint32_t*)&h0; wh_.y = *(uint32_t*)&h1;
            wl_.x = *(uint32_t*)&l0; wl_.y = *(uint32_t*)&l1;
            *(uint2*)(oh + (size_t)warp * D + g * 128 + lane * 4) = wh_;
            *(uint2*)(ol + (size_t)warp * D + g * 128 + lane * 4) = wl_;
        }
    }
}

// ---------------- layer-1 fused gather: mean(G1)+S1, bias+bn+relu -> planes ----
// h2 = relu(bn1(S1 + mean_neighbors(G1) + b));  D = 128 fixed.
__global__ void gather_fuse_bn(const float* __restrict__ S1,
                               const float* __restrict__ G1,
                               const int* __restrict__ csr,
                               const int* __restrict__ rowptr,
                               const float* __restrict__ bias,
                               const float* __restrict__ bng,
                               const float* __restrict__ bnb,
                               const float* __restrict__ bnm,
                               const float* __restrict__ bnv,
                               bf16* __restrict__ oh, bf16* __restrict__ ol,
                               int Nn)
{
    const int warp = (blockIdx.x * blockDim.x + threadIdx.x) >> 5;
    const int lane = threadIdx.x & 31;
    if (warp >= Nn) return;
    const int e0 = rowptr[warp];
    const int e1 = rowptr[warp + 1];
    const float inv = 1.f / (float)max(e1 - e0, 1);
    const int col = lane * 4;

    float acc0 = 0.f, acc1 = 0.f, acc2 = 0.f, acc3 = 0.f;
    for (int e = e0; e < e1; e++) {
        const float4 v = *(const float4*)(G1 + (size_t)csr[e] * 128 + col);
        acc0 += v.x; acc1 += v.y; acc2 += v.z; acc3 += v.w;
    }
    const float4 s = *(const float4*)(S1 + (size_t)warp * 128 + col);

    float vo[4];
    const float* sp = &s.x;
    float ac[4] = {acc0, acc1, acc2, acc3};
#pragma unroll
    for (int j = 0; j < 4; j++) {
        const float sc = bng[col + j] * rsqrtf(bnv[col + j] + 1e-5f);
        const float sh = (bias[col + j] - bnm[col + j]) * sc + bnb[col + j];
        float x = (sp[j] + ac[j] * inv) * sc + sh;
        vo[j] = fmaxf(x, 0.f);
    }

    bf162 h0 = __float22bfloat162_rn(make_float2(vo[0], vo[1]));
    bf162 h1 = __float22bfloat162_rn(make_float2(vo[2], vo[3]));
    float2 f0 = __bfloat1622float2(h0);
    float2 f1 = __bfloat1622float2(h1);
    bf162 l0 = __float22bfloat162_rn(make_float2(vo[0] - f0.x, vo[1] - f0.y));
    bf162 l1 = __float22bfloat162_rn(make_float2(vo[2] - f1.x, vo[3] - f1.y));
    uint2 wh_, wl_;
    wh_.x = *(uint32_t*)&h0; wh_.y = *(uint32_t*)&h1;
    wl_.x = *(uint32_t*)&l0; wl_.y = *(uint32_t*)&l1;
    *(uint2*)(oh + (size_t)warp * 128 + col) = wh_;
    *(uint2*)(ol + (size_t)warp * 128 + col) = wl_;
}

// ---------------- launch helper ----------------
static inline void launch_gemm(
    const bf16* A0h, const bf16* A0l, int K0,
    const bf16* A1h, const bf16* A1l, int K1,
    const bf16* W0h, const bf16* W0l, const bf16* W1h, const bf16* W1l,
    int M, int N,
    const float* bias, const float* bng, const float* bnb,
    const float* bnm, const float* bnv,
    int do_relu, float* Cf, bf16* Ch, bf16* Cl)
{
    if (N >= 128) {
        constexpr int BM_ = 64, BN_ = 128;
        constexpr int SMEM = 2 * (2 * BM_ * A_STRIDE + 2 * BK * (BN_ + 8)) * 2;
        dim3 grid(N / BN_, (M + BM_ - 1) / BM_);
        gemm_bf16x3<BM_, BN_><<<grid, 256, SMEM>>>(
            A0h, A0l, K0, A1h, A1l, K1, W0h, W0l, W1h, W1l, M, N,
            bias, bng, bnb, bnm, bnv, do_relu, Cf, Ch, Cl);
    } else {
        constexpr int BM_ = 128, BN_ = 64;
        constexpr int SMEM = 2 * (2 * BM_ * A_STRIDE + 2 * BK * (BN_ + 8)) * 2;
        dim3 grid((N + BN_ - 1) / BN_, (M + BM_ - 1) / BM_);
        gemm_bf16x3<BM_, BN_><<<grid, 256, SMEM>>>(
            A0h, A0l, K0, A1h, A1l, K1, W0h, W0l, W1h, W1l, M, N,
            bias, bng, bnb, bnm, bnv, do_relu, Cf, Ch, Cl);
    }
}

extern "C" void kernel_launch(void* const* d_in, const int* in_sizes, int n_in,
                              void* d_out, int out_size)
{
    const float* structural = (const float*)d_in[0];
    const float* multimodal = (const float*)d_in[1];
    const int*   src        = (const int*)  d_in[2];
    const int*   dst        = (const int*)  d_in[3];
    const float* enc_w      = (const float*)d_in[4];
    const float* enc_b      = (const float*)d_in[5];
    const float* sage0_ws   = (const float*)d_in[6];
    const float* sage0_wn   = (const float*)d_in[7];
    const float* sage0_b    = (const float*)d_in[8];
    const float* bn0_g      = (const float*)d_in[9];
    const float* bn0_b      = (const float*)d_in[10];
    const float* bn0_m      = (const float*)d_in[11];
    const float* bn0_v      = (const float*)d_in[12];
    const float* sage1_ws   = (const float*)d_in[13];
    const float* sage1_wn   = (const float*)d_in[14];
    const float* sage1_b    = (const float*)d_in[15];
    const float* bn1_g      = (const float*)d_in[16];
    const float* bn1_b      = (const float*)d_in[17];
    const float* bn1_m      = (const float*)d_in[18];
    const float* bn1_v      = (const float*)d_in[19];
    const float* rel_w      = (const float*)d_in[20];
    const float* rel_b      = (const float*)d_in[21];
    const float* cls_w1     = (const float*)d_in[22];
    const float* cls_b1     = (const float*)d_in[23];
    const float* cls_w2     = (const float*)d_in[24];
    const float* cls_b2     = (const float*)d_in[25];
    float* out = (float*)d_out;

#define SYMADDR(var, sym) void* p_##var; cudaGetSymbolAddress(&p_##var, sym);
    SYMADDR(xsh, g_xsh) SYMADDR(xsl, g_xsl) SYMADDR(xmh, g_xmh) SYMADDR(xml, g_xml)
    SYMADDR(h0h, g_h0h) SYMADDR(h0l, g_h0l) SYMADDR(a0h, g_a0h) SYMADDR(a0l, g_a0l)
    SYMADDR(h1h, g_h1h) SYMADDR(h1l, g_h1l)
    SYMADDR(h2h, g_h2h) SYMADDR(h2l, g_h2l) SYMADDR(hfh, g_hfh) SYMADDR(hfl, g_hfl)
    SYMADDR(c1h, g_c1h) SYMADDR(c1l, g_c1l)
    SYMADDR(s1f, g_s1f) SYMADDR(g1f, g_g1f)
    SYMADDR(wh, g_wh) SYMADDR(wl, g_wl)
    SYMADDR(counts, g_counts) SYMADDR(rowptr, g_rowptr)
    SYMADDR(fill, g_fill) SYMADDR(csr, g_csr)
#undef SYMADDR

    bf16* xsh = (bf16*)p_xsh; bf16* xsl = (bf16*)p_xsl;
    bf16* xmh = (bf16*)p_xmh; bf16* xml = (bf16*)p_xml;
    bf16* h0h = (bf16*)p_h0h; bf16* h0l = (bf16*)p_h0l;
    bf16* a0h = (bf16*)p_a0h; bf16* a0l = (bf16*)p_a0l;
    bf16* h1h = (bf16*)p_h1h; bf16* h1l = (bf16*)p_h1l;
    bf16* h2h = (bf16*)p_h2h; bf16* h2l = (bf16*)p_h2l;
    bf16* hfh = (bf16*)p_hfh; bf16* hfl = (bf16*)p_hfl;
    bf16* c1h = (bf16*)p_c1h; bf16* c1l = (bf16*)p_c1l;
    float* s1f = (float*)p_s1f; float* g1f = (float*)p_g1f;
    bf16* wh = (bf16*)p_wh; bf16* wl = (bf16*)p_wl;
    int* counts = (int*)p_counts; int* rowptr = (int*)p_rowptr;
    int* fill   = (int*)p_fill;   int* csr    = (int*)p_csr;

    {
        constexpr int SMEM_A = 2 * (2 * 64 * A_STRIDE + 2 * BK * (128 + 8)) * 2;
        constexpr int SMEM_B = 2 * (2 * 128 * A_STRIDE + 2 * BK * (64 + 8)) * 2;
        cudaFuncSetAttribute((const void*)gemm_bf16x3<64, 128>,
                             cudaFuncAttributeMaxDynamicSharedMemorySize, SMEM_A);
        cudaFuncSetAttribute((const void*)gemm_bf16x3<128, 64>,
                             cudaFuncAttributeMaxDynamicSharedMemorySize, SMEM_B);
    }

    const int M = N_NODES, E = N_EDGES;

    // ---- CSR build ----
    cudaMemsetAsync(counts, 0, N_NODES * sizeof(int), 0);
    count_deg<<<(E + 255) / 256, 256>>>(dst, counts, E);
    scan_counts<<<1, 1024>>>(counts, rowptr, fill, M);
    fill_csr<<<(E + 255) / 256, 256>>>(src, dst, fill, csr, E);

    // ---- split inputs (2 launches) + all weights (1 launch) ----
    {
        int n4 = (M * 128) / 4;
        split_planes<<<(n4 + 255) / 256, 256>>>(structural, xsh, xsl, n4);
        n4 = (M * 384) / 4;
        split_planes<<<(n4 + 255) / 256, 256>>>(multimodal, xmh, xml, n4);

        WSeg ws;
        ws.src[0] = enc_w;    ws.beg[0] = WOFF_ENC;
        ws.src[1] = sage0_ws; ws.beg[1] = WOFF_S0S;
        ws.src[2] = sage0_wn; ws.beg[2] = WOFF_S0N;
        ws.src[3] = sage1_ws; ws.beg[3] = WOFF_S1S;
        ws.src[4] = sage1_wn; ws.beg[4] = WOFF_S1N;
        ws.src[5] = rel_w;    ws.beg[5] = WOFF_REL;
        ws.src[6] = cls_w1;   ws.beg[6] = WOFF_C1;
        ws.src[7] = cls_w2;   ws.beg[7] = WOFF_C2;
        ws.beg[8] = WOFF_END;
        int w4 = WOFF_END / 4;
        split_weights<<<(w4 + 255) / 256, 256>>>(ws, wh, wl);
    }

    // h0 = relu([xs|xm] @ enc_w + enc_b)
    launch_gemm(xsh, xsl, 128, xmh, xml, 384,
                wh + WOFF_ENC, wl + WOFF_ENC,
                wh + WOFF_ENC + 128 * 128, wl + WOFF_ENC + 128 * 128,
                M, 128, enc_b, nullptr, nullptr, nullptr, nullptr, 1,
                nullptr, h0h, h0l);

    // agg0 = mean h0  (gather over planes)
    gather_mean<<<(M * 32 + 255) / 256, 256>>>(h0h, h0l, csr, rowptr,
                                               a0h, a0l, M, 128);

    // h1 = relu(bn0(h0 @ ws0 + agg0 @ wn0 + b0))
    launch_gemm(h0h, h0l, 128, a0h, a0l, 128,
                wh + WOFF_S0S, wl + WOFF_S0S, wh + WOFF_S0N, wl + WOFF_S0N,
                M, 256, sage0_b, bn0_g, bn0_b, bn0_m, bn0_v, 1,
                nullptr, h1h, h1l);

    // ---- sage1, commuted: mean(h1) @ Wn1 == mean(h1 @ Wn1) ----
    // G1 = h1 @ Wn1   (fp32, 128-wide)
    launch_gemm(h1h, h1l, 256, h1h, h1l, 0,
                wh + WOFF_S1N, wl + WOFF_S1N, wh + WOFF_S1N, wl + WOFF_S1N,
                M, 128, nullptr, nullptr, nullptr, nullptr, nullptr, 0,
                g1f, nullptr, nullptr);
    // S1 = h1 @ Ws1   (fp32, 128-wide)
    launch_gemm(h1h, h1l, 256, h1h, h1l, 0,
                wh + WOFF_S1S, wl + WOFF_S1S, wh + WOFF_S1S, wl + WOFF_S1S,
                M, 128, nullptr, nullptr, nullptr, nullptr, nullptr, 0,
                s1f, nullptr, nullptr);
    // h2 = relu(bn1(S1 + mean(G1) + b1)) -> planes
    gather_fuse_bn<<<(M * 32 + 255) / 256, 256>>>(
        s1f, g1f, csr, rowptr, sage1_b, bn1_g, bn1_b, bn1_m, bn1_v,
        h2h, h2l, M);

    // hf = relu([h0|h2] @ rel_w + rel_b)
    launch_gemm(h0h, h0l, 128, h2h, h2l, 128,
                wh + WOFF_REL, wl + WOFF_REL,
                wh + WOFF_REL + 128 * 128, wl + WOFF_REL + 128 * 128,
                M, 128, rel_b, nullptr, nullptr, nullptr, nullptr, 1,
                nullptr, hfh, hfl);

    // c1 = relu(hf @ cls_w1 + cls_b1)
    launch_gemm(hfh, hfl, 128, hfh, hfl, 0,
                wh + WOFF_C1, wl + WOFF_C1, wh + WOFF_C1, wl + WOFF_C1,
                M, 64, cls_b1, nullptr, nullptr, nullptr, nullptr, 1,
                nullptr, c1h, c1l);

    // out = c1 @ cls_w2 + cls_b2   (fp32)
    launch_gemm(c1h, c1l, 64, c1h, c1l, 0,
                wh + WOFF_C2, wl + WOFF_C2, wh + WOFF_C2, wl + WOFF_C2,
                M, 32, cls_b2, nullptr, nullptr, nullptr, nullptr, 0,
                out, nullptr, nullptr);
}

// round 11
// speedup vs baseline: 1.1566x; 1.0446x over previous
#include <cuda_runtime.h>
#include <cuda_bf16.h>
#include <math.h>
#include <stdint.h>

#define N_NODES 100000
#define N_EDGES 800000

typedef __nv_bfloat16  bf16;
typedef __nv_bfloat162 bf162;

// ---------------- scratch (device globals; no allocs allowed) ----------------
__device__ bf16 g_h0h[(size_t)N_NODES * 128], g_h0l[(size_t)N_NODES * 128];
__device__ bf16 g_a0h[(size_t)N_NODES * 128], g_a0l[(size_t)N_NODES * 128];
__device__ bf16 g_h1h[(size_t)N_NODES * 256], g_h1l[(size_t)N_NODES * 256];
__device__ bf16 g_h2h[(size_t)N_NODES * 128], g_h2l[(size_t)N_NODES * 128];
__device__ bf16 g_hfh[(size_t)N_NODES * 128], g_hfl[(size_t)N_NODES * 128];
__device__ bf16 g_c1h[(size_t)N_NODES * 64],  g_c1l[(size_t)N_NODES * 64];
__device__ float g_s1f[(size_t)N_NODES * 128];   // h1 @ Ws1  (fp32)
__device__ float g_g1f[(size_t)N_NODES * 128];   // h1 @ Wn1  (fp32)
__device__ bf16 g_wh[262144], g_wl[262144];
__device__ int g_counts[N_NODES];
__device__ int g_rowptr[N_NODES + 1];
__device__ int g_fill  [N_NODES];
__device__ int g_csr   [N_EDGES];

// weight plane offsets (elements)
#define WOFF_ENC 0        // 512*128 = 65536
#define WOFF_S0S 65536    // 128*256 = 32768
#define WOFF_S0N 98304
#define WOFF_S1S 131072   // 256*128
#define WOFF_S1N 163840
#define WOFF_REL 196608   // 256*128
#define WOFF_C1  229376   // 128*64 = 8192
#define WOFF_C2  237568   // 64*32  = 2048
#define WOFF_END 239616

// ---------------- bf16x3 tensor-core GEMM, templated block shape ----------------
#define BK 32
#define A_STRIDE 40

__device__ __forceinline__ void cp16(uint32_t dst, const void* src, bool pred) {
    asm volatile("cp.async.cg.shared.global [%0], [%1], 16, %2;"
                 :: "r"(dst), "l"(src), "r"(pred ? 16 : 0));
}

#define LDMX4(r, addr)                                                          \
    asm volatile("ldmatrix.sync.aligned.m8n8.x4.shared.b16 {%0,%1,%2,%3},[%4];" \
                 : "=r"((r)[0]), "=r"((r)[1]), "=r"((r)[2]), "=r"((r)[3])       \
                 : "r"(addr))

#define LDMX4T(r, addr)                                                         \
    asm volatile("ldmatrix.sync.aligned.m8n8.x4.trans.shared.b16 "              \
                 "{%0,%1,%2,%3},[%4];"                                          \
                 : "=r"((r)[0]), "=r"((r)[1]), "=r"((r)[2]), "=r"((r)[3])       \
                 : "r"(addr))

#define MMA_BF16(acc, a, b0, b1)                                                \
    asm volatile(                                                               \
        "mma.sync.aligned.m16n8k16.row.col.f32.bf16.bf16.f32 "                  \
        "{%0,%1,%2,%3},{%4,%5,%6,%7},{%8,%9},{%0,%1,%2,%3};"                    \
        : "+f"((acc)[0]), "+f"((acc)[1]), "+f"((acc)[2]), "+f"((acc)[3])        \
        : "r"((a)[0]), "r"((a)[1]), "r"((a)[2]), "r"((a)[3]),                   \
          "r"(b0), "r"(b1))

// convert 8 fp32 -> 8 bf16 hi + 8 bf16 lo (packed as uint4 each)
__device__ __forceinline__ void cvt8_planes(float4 v0, float4 v1,
                                            uint4& hi, uint4& lo)
{
    bf162 h0 = __float22bfloat162_rn(make_float2(v0.x, v0.y));
    bf162 h1 = __float22bfloat162_rn(make_float2(v0.z, v0.w));
    bf162 h2 = __float22bfloat162_rn(make_float2(v1.x, v1.y));
    bf162 h3 = __float22bfloat162_rn(make_float2(v1.z, v1.w));
    float2 f0 = __bfloat1622float2(h0);
    float2 f1 = __bfloat1622float2(h1);
    float2 f2 = __bfloat1622float2(h2);
    float2 f3 = __bfloat1622float2(h3);
    bf162 l0 = __float22bfloat162_rn(make_float2(v0.x - f0.x, v0.y - f0.y));
    bf162 l1 = __float22bfloat162_rn(make_float2(v0.z - f1.x, v0.w - f1.y));
    bf162 l2 = __float22bfloat162_rn(make_float2(v1.x - f2.x, v1.y - f2.y));
    bf162 l3 = __float22bfloat162_rn(make_float2(v1.z - f3.x, v1.w - f3.y));
    hi.x = *(uint32_t*)&h0; hi.y = *(uint32_t*)&h1;
    hi.z = *(uint32_t*)&h2; hi.w = *(uint32_t*)&h3;
    lo.x = *(uint32_t*)&l0; lo.y = *(uint32_t*)&l1;
    lo.z = *(uint32_t*)&l2; lo.w = *(uint32_t*)&l3;
}

template<int BM_, int BN_, int AF32>
__global__ __launch_bounds__(256, 2) void gemm_bf16x3(
    const bf16* __restrict__ A0h, const bf16* __restrict__ A0l, int K0,
    const bf16* __restrict__ A1h, const bf16* __restrict__ A1l, int K1,
    const float* __restrict__ Af0, const float* __restrict__ Af1,
    const bf16* __restrict__ W0h, const bf16* __restrict__ W0l,
    const bf16* __restrict__ W1h, const bf16* __restrict__ W1l,
    int M, int N,
    const float* __restrict__ bias,
    const float* __restrict__ bng, const float* __restrict__ bnb,
    const float* __restrict__ bnm, const float* __restrict__ bnv,
    int do_relu,
    float* __restrict__ Cf, bf16* __restrict__ Ch, bf16* __restrict__ Cl)
{
    constexpr int A_PLANE_ = BM_ * A_STRIDE;
    constexpr int B_STRIDE = BN_ + 8;
    constexpr int B_PLANE  = BK * B_STRIDE;
    constexpr int STAGE_ELEMS = 2 * A_PLANE_ + 2 * B_PLANE;
    constexpr int WROWS  = BM_ / 32;
    constexpr int WARP_N = BN_ * WROWS / 8;          // 32 in both configs
    constexpr int NT = WARP_N / 8;
    constexpr int P  = WARP_N / 16;
    constexpr int NCP = BN_ / 64;

    extern __shared__ bf16 smem[];
    const uint32_t smem_u32 = (uint32_t)__cvta_generic_to_shared(smem);

    const int tid  = threadIdx.x;
    const int lane = tid & 31;
    const int wid  = tid >> 5;
    const int wm   = (wid % WROWS) * 32;
    const int wn   = (wid / WROWS) * WARP_N;
    const int brow = blockIdx.y * BM_;
    const int bcol = blockIdx.x * BN_;
    const int K = K0 + K1;
    const int T = K / BK;

    constexpr int ATPR = 256 / BM_;
    const int a_row = tid / ATPR;
    const int a_k   = (tid % ATPR) * (32 / ATPR);
    const int a_gr  = brow + a_row;
    const bool a_ok = (a_gr < M);
    const int b_k  = tid >> 3;
    const int b_n0 = (tid & 7) * (BN_ / 8);

    const int a_lm = (wm + (lane & 15)) * A_STRIDE + (lane >> 4) * 8;
    const int b_lm = ((lane & 7) + ((lane >> 3) & 1) * 8) * B_STRIDE
                     + wn + (lane >> 4) * 8;

    float acc[2][NT][4];
#pragma unroll
    for (int mt = 0; mt < 2; mt++)
#pragma unroll
        for (int nt = 0; nt < NT; nt++)
#pragma unroll
            for (int i = 0; i < 4; i++) acc[mt][nt][i] = 0.f;

#define LOAD_TILE(t, st) do {                                                     \
        const int kt_ = (t) * BK;                                                 \
        if (AF32) {                                                               \
          /* fp32 A path: LDG + convert-to-planes + STS (ATPR==4, 8 elems) */     \
          int gk0 = kt_ + a_k;                                                    \
          const float* sp;                                                        \
          if (gk0 < K0) sp = Af0 + (size_t)a_gr * K0 + gk0;                       \
          else          sp = Af1 + (size_t)a_gr * K1 + (gk0 - K0);                \
          float4 v0 = make_float4(0.f, 0.f, 0.f, 0.f), v1 = v0;                   \
          if (a_ok) { v0 = *(const float4*)sp; v1 = *(const float4*)(sp + 4); }   \
          uint4 hi_, lo_;                                                         \
          cvt8_planes(v0, v1, hi_, lo_);                                          \
          bf16* ap = smem + (st) * STAGE_ELEMS + a_row * A_STRIDE + a_k;          \
          *(uint4*)ap = hi_;                                                      \
          *(uint4*)(ap + A_PLANE_) = lo_;                                         \
        } else {                                                                  \
          int gk0 = kt_ + a_k;                                                    \
          const bf16 *sph, *spl;                                                  \
          if (gk0 < K0) { sph = A0h + (size_t)a_gr * K0 + gk0;                    \
                          spl = A0l + (size_t)a_gr * K0 + gk0; }                  \
          else          { sph = A1h + (size_t)a_gr * K1 + (gk0 - K0);             \
                          spl = A1l + (size_t)a_gr * K1 + (gk0 - K0); }           \
          uint32_t dh = smem_u32 +                                                \
              ((st) * STAGE_ELEMS + a_row * A_STRIDE + a_k) * 2;                  \
          if (ATPR == 2) {                                                        \
              cp16(dh,      sph,     a_ok);                                       \
              cp16(dh + 16, sph + 8, a_ok);                                       \
              cp16(dh + A_PLANE_ * 2,      spl,     a_ok);                        \
              cp16(dh + A_PLANE_ * 2 + 16, spl + 8, a_ok);                        \
          } else {                                                                \
              cp16(dh,                sph, a_ok);                                 \
              cp16(dh + A_PLANE_ * 2, spl, a_ok);                                 \
          }                                                                       \
        }                                                                         \
        { int gk = kt_ + b_k;                                                     \
          const bf16 *wph, *wpl; int kk2;                                         \
          if (gk < K0) { wph = W0h; wpl = W0l; kk2 = gk; }                        \
          else         { wph = W1h; wpl = W1l; kk2 = gk - K0; }                   \
          uint32_t dbh = smem_u32 +                                               \
              ((st) * STAGE_ELEMS + 2 * A_PLANE_ + b_k * B_STRIDE + b_n0) * 2;    \
          _Pragma("unroll")                                                       \
          for (int cc = 0; cc < NCP; cc++) {                                      \
              int n0 = bcol + b_n0 + cc * 8;                                      \
              bool ok = (n0 < N);                                                 \
              cp16(dbh + cc * 16,               wph + (size_t)kk2 * N + n0, ok);  \
              cp16(dbh + cc * 16 + B_PLANE * 2, wpl + (size_t)kk2 * N + n0, ok);  \
          }                                                                       \
        }                                                                         \
        asm volatile("cp.async.commit_group;");                                   \
    } while (0)

    LOAD_TILE(0, 0);

    for (int t = 0; t < T; ++t) {
        const int st = t & 1;
        if (t + 1 < T) {
            LOAD_TILE(t + 1, st ^ 1);
            asm volatile("cp.async.wait_group 1;");
        } else {
            asm volatile("cp.async.wait_group 0;");
        }
        __syncthreads();

        const uint32_t base = smem_u32 + st * STAGE_ELEMS * 2;
#pragma unroll
        for (int k16 = 0; k16 < 2; k16++) {
            uint32_t ah[2][4], al[2][4], bh[P][4], bl[P][4];
#pragma unroll
            for (int mt = 0; mt < 2; mt++) {
                uint32_t ad = base + (a_lm + mt * 16 * A_STRIDE + k16 * 16) * 2;
                LDMX4(ah[mt], ad);
                LDMX4(al[mt], ad + A_PLANE_ * 2);
            }
#pragma unroll
            for (int p = 0; p < P; p++) {
                uint32_t bd = base + (2 * A_PLANE_ + b_lm + p * 16
                                      + k16 * 16 * B_STRIDE) * 2;
                LDMX4T(bh[p], bd);
                LDMX4T(bl[p], bd + B_PLANE * 2);
            }
#pragma unroll
            for (int mt = 0; mt < 2; mt++)
#pragma unroll
                for (int nt = 0; nt < NT; nt++) {
                    const int p = nt >> 1, q = (nt & 1) * 2;
                    MMA_BF16(acc[mt][nt], al[mt], bh[p][q], bh[p][q + 1]);
                    MMA_BF16(acc[mt][nt], ah[mt], bl[p][q], bl[p][q + 1]);
                    MMA_BF16(acc[mt][nt], ah[mt], bh[p][q], bh[p][q + 1]);
                }
        }
        __syncthreads();
    }

#pragma unroll
    for (int nt = 0; nt < NT; nt++) {
        const int col = bcol + wn + 8 * nt + 2 * (lane & 3);
        if (col >= N) continue;
        float sc0 = 1.f, sh0 = 0.f, sc1 = 1.f, sh1 = 0.f;
        if (bias) { sh0 = bias[col]; sh1 = bias[col + 1]; }
        if (bng) {
            float s0 = bng[col]     * rsqrtf(bnv[col]     + 1e-5f);
            float s1 = bng[col + 1] * rsqrtf(bnv[col + 1] + 1e-5f);
            sh0 = (sh0 - bnm[col])     * s0 + bnb[col];
            sh1 = (sh1 - bnm[col + 1]) * s1 + bnb[col + 1];
            sc0 = s0; sc1 = s1;
        }
#pragma unroll
        for (int mt = 0; mt < 2; mt++) {
#pragma unroll
            for (int half = 0; half < 2; half++) {
                const int row = brow + wm + 16 * mt + (lane >> 2) + 8 * half;
                if (row >= M) continue;
                const float* c = acc[mt][nt] + 2 * half;
                float v0 = c[0] * sc0 + sh0;
                float v1 = c[1] * sc1 + sh1;
                if (do_relu) { v0 = fmaxf(v0, 0.f); v1 = fmaxf(v1, 0.f); }
                if (Ch) {
                    bf162 hi = __float22bfloat162_rn(make_float2(v0, v1));
                    float2 hf2 = __bfloat1622float2(hi);
                    bf162 lo = __float22bfloat162_rn(
                        make_float2(v0 - hf2.x, v1 - hf2.y));
                    *(bf162*)(Ch + (size_t)row * N + col) = hi;
                    *(bf162*)(Cl + (size_t)row * N + col) = lo;
                } else {
                    *(float2*)(Cf + (size_t)row * N + col) = make_float2(v0, v1);
                }
            }
        }
    }
}

// ---------------- merged weight split: all 8 segments in one launch ----------
struct WSeg { const float* src[8]; int beg[9]; };

__global__ void split_weights(WSeg ws, bf16* __restrict__ wh, bf16* __restrict__ wl)
{
    int i4 = blockIdx.x * blockDim.x + threadIdx.x;
    int i  = i4 * 4;
    if (i >= ws.beg[8]) return;
    int s = 0;
#pragma unroll
    for (int k = 0; k < 7; k++) s += (i >= ws.beg[k + 1]) ? 1 : 0;
    float4 v = *(const float4*)(ws.src[s] + (i - ws.beg[s]));
    bf162 h0 = __float22bfloat162_rn(make_float2(v.x, v.y));
    bf162 h1 = __float22bfloat162_rn(make_float2(v.z, v.w));
    float2 f0 = __bfloat1622float2(h0);
    float2 f1 = __bfloat1622float2(h1);
    bf162 l0 = __float22bfloat162_rn(make_float2(v.x - f0.x, v.y - f0.y));
    bf162 l1 = __float22bfloat162_rn(make_float2(v.z - f1.x, v.w - f1.y));
    ((bf162*)wh)[i4 * 2]     = h0;
    ((bf162*)wh)[i4 * 2 + 1] = h1;
    ((bf162*)wl)[i4 * 2]     = l0;
    ((bf162*)wl)[i4 * 2 + 1] = l1;
}

// ---------------- CSR construction ----------------
__global__ void count_deg(const int* __restrict__ dst, int* __restrict__ counts, int E)
{
    int e = blockIdx.x * blockDim.x + threadIdx.x;
    if (e < E) atomicAdd(&counts[dst[e]], 1);
}

__global__ __launch_bounds__(1024) void scan_counts(
    const int* __restrict__ counts, int* __restrict__ rowptr,
    int* __restrict__ fill, int n)
{
    __shared__ int part[1024];
    const int tid = threadIdx.x;
    const int chunk = (n + 1023) / 1024;
    const int begin = min(tid * chunk, n);
    const int end   = min(begin + chunk, n);
    int s = 0;
    for (int i = begin; i < end; i++) s += counts[i];
    part[tid] = s;
    __syncthreads();
    for (int off = 1; off < 1024; off <<= 1) {
        int v = (tid >= off) ? part[tid - off] : 0;
        __syncthreads();
        part[tid] += v;
        __syncthreads();
    }
    int pre = (tid == 0) ? 0 : part[tid - 1];
    for (int i = begin; i < end; i++) {
        rowptr[i] = pre;
        fill[i]   = pre;
        pre += counts[i];
    }
    if (end == n && begin <= n) rowptr[n] = pre;
}

__global__ void fill_csr(const int* __restrict__ src, const int* __restrict__ dst,
                         int* __restrict__ fill, int* __restrict__ csr, int E)
{
    int e = blockIdx.x * blockDim.x + threadIdx.x;
    if (e < E) {
        int pos = atomicAdd(&fill[dst[e]], 1);
        csr[pos] = src[e];
    }
}

// ---------------- CSR gather mean over bf16 planes (layer-0) ----------------
__global__ void gather_mean(const bf16* __restrict__ hh, const bf16* __restrict__ hl,
                            const int* __restrict__ csr, const int* __restrict__ rowptr,
                            bf16* __restrict__ oh, bf16* __restrict__ ol,
                            int Nn, int D)
{
    const int warp = (blockIdx.x * blockDim.x + threadIdx.x) >> 5;
    const int lane = threadIdx.x & 31;
    if (warp >= Nn) return;
    const int e0 = rowptr[warp];
    const int e1 = rowptr[warp + 1];
    const float inv = 1.f / (float)max(e1 - e0, 1);
    const int nseg = D >> 7;
    float acc[8];
#pragma unroll
    for (int i = 0; i < 8; i++) acc[i] = 0.f;

    for (int e = e0; e < e1; e++) {
        const int s = csr[e];
        const bf16* rh = hh + (size_t)s * D + lane * 4;
        const bf16* rl = hl + (size_t)s * D + lane * 4;
#pragma unroll
        for (int g = 0; g < 2; g++) {
            if (g < nseg) {
                uint2 vh = *(const uint2*)(rh + g * 128);
                uint2 vl = *(const uint2*)(rl + g * 128);
                float2 a0 = __bfloat1622float2(*(const bf162*)&vh.x);
                float2 a1 = __bfloat1622float2(*(const bf162*)&vh.y);
                float2 b0 = __bfloat1622float2(*(const bf162*)&vl.x);
                float2 b1 = __bfloat1622float2(*(const bf162*)&vl.y);
                acc[g * 4 + 0] += a0.x + b0.x;
                acc[g * 4 + 1] += a0.y + b0.y;
                acc[g * 4 + 2] += a1.x + b1.x;
                acc[g * 4 + 3] += a1.y + b1.y;
            }
        }
    }

#pragma unroll
    for (int g = 0; g < 2; g++) {
        if (g < nseg) {
            float v0 = acc[g * 4 + 0] * inv;
            float v1 = acc[g * 4 + 1] * inv;
            float v2 = acc[g * 4 + 2] * inv;
            float v3 = acc[g * 4 + 3] * inv;
            bf162 h0 = __float22bfloat162_rn(make_float2(v0, v1));
            bf162 h1 = __float22bfloat162_rn(make_float2(v2, v3));
            float2 f0 = __bfloat1622float2(h0);
            float2 f1 = __bfloat1622float2(h1);
            bf162 l0 = __float22bfloat162_rn(make_float2(v0 - f0.x, v1 - f0.y));
            bf162 l1 = __float22bfloat162_rn(make_float2(v2 - f1.x, v3 - f1.y));
            uint2 wh_, wl_;
            wh_.x = *(uint32_t*)&h0; wh_.y = *(uint32_t*)&h1;
            wl_.x = *(uint32_t*)&l0; wl_.y = *(uint32_t*)&l1;
            *(uint2*)(oh + (size_t)warp * D + g * 128 + lane * 4) = wh_;
            *(uint2*)(ol + (size_t)warp * D + g * 128 + lane * 4) = wl_;
        }
    }
}

// ---------------- layer-1 fused gather: mean(G1)+S1, bias+bn+relu -> planes ----
__global__ void gather_fuse_bn(const float* __restrict__ S1,
                               const float* __restrict__ G1,
                               const int* __restrict__ csr,
                               const int* __restrict__ rowptr,
                               const float* __restrict__ bias,
                               const float* __restrict__ bng,
                               const float* __restrict__ bnb,
                               const float* __restrict__ bnm,
                               const float* __restrict__ bnv,
                               bf16* __restrict__ oh, bf16* __restrict__ ol,
                               int Nn)
{
    const int warp = (blockIdx.x * blockDim.x + threadIdx.x) >> 5;
    const int lane = threadIdx.x & 31;
    if (warp >= Nn) return;
    const int e0 = rowptr[warp];
    const int e1 = rowptr[warp + 1];
    const float inv = 1.f / (float)max(e1 - e0, 1);
    const int col = lane * 4;

    float acc0 = 0.f, acc1 = 0.f, acc2 = 0.f, acc3 = 0.f;
    for (int e = e0; e < e1; e++) {
        const float4 v = *(const float4*)(G1 + (size_t)csr[e] * 128 + col);
        acc0 += v.x; acc1 += v.y; acc2 += v.z; acc3 += v.w;
    }
    const float4 s = *(const float4*)(S1 + (size_t)warp * 128 + col);

    float vo[4];
    const float* sp = &s.x;
    float ac[4] = {acc0, acc1, acc2, acc3};
#pragma unroll
    for (int j = 0; j < 4; j++) {
        const float sc = bng[col + j] * rsqrtf(bnv[col + j] + 1e-5f);
        const float sh = (bias[col + j] - bnm[col + j]) * sc + bnb[col + j];
        float x = (sp[j] + ac[j] * inv) * sc + sh;
        vo[j] = fmaxf(x, 0.f);
    }

    bf162 h0 = __float22bfloat162_rn(make_float2(vo[0], vo[1]));
    bf162 h1 = __float22bfloat162_rn(make_float2(vo[2], vo[3]));
    float2 f0 = __bfloat1622float2(h0);
    float2 f1 = __bfloat1622float2(h1);
    bf162 l0 = __float22bfloat162_rn(make_float2(vo[0] - f0.x, vo[1] - f0.y));
    bf162 l1 = __float22bfloat162_rn(make_float2(vo[2] - f1.x, vo[3] - f1.y));
    uint2 wh_, wl_;
    wh_.x = *(uint32_t*)&h0; wh_.y = *(uint32_t*)&h1;
    wl_.x = *(uint32_t*)&l0; wl_.y = *(uint32_t*)&l1;
    *(uint2*)(oh + (size_t)warp * 128 + col) = wh_;
    *(uint2*)(ol + (size_t)warp * 128 + col) = wl_;
}

// ---------------- launch helpers ----------------
static inline void launch_gemm(
    const bf16* A0h, const bf16* A0l, int K0,
    const bf16* A1h, const bf16* A1l, int K1,
    const bf16* W0h, const bf16* W0l, const bf16* W1h, const bf16* W1l,
    int M, int N,
    const float* bias, const float* bng, const float* bnb,
    const float* bnm, const float* bnv,
    int do_relu, float* Cf, bf16* Ch, bf16* Cl)
{
    if (N >= 128) {
        constexpr int BM_ = 64, BN_ = 128;
        constexpr int SMEM = 2 * (2 * BM_ * A_STRIDE + 2 * BK * (BN_ + 8)) * 2;
        dim3 grid(N / BN_, (M + BM_ - 1) / BM_);
        gemm_bf16x3<BM_, BN_, 0><<<grid, 256, SMEM>>>(
            A0h, A0l, K0, A1h, A1l, K1, nullptr, nullptr,
            W0h, W0l, W1h, W1l, M, N,
            bias, bng, bnb, bnm, bnv, do_relu, Cf, Ch, Cl);
    } else {
        constexpr int BM_ = 128, BN_ = 64;
        constexpr int SMEM = 2 * (2 * BM_ * A_STRIDE + 2 * BK * (BN_ + 8)) * 2;
        dim3 grid((N + BN_ - 1) / BN_, (M + BM_ - 1) / BM_);
        gemm_bf16x3<BM_, BN_, 0><<<grid, 256, SMEM>>>(
            A0h, A0l, K0, A1h, A1l, K1, nullptr, nullptr,
            W0h, W0l, W1h, W1l, M, N,
            bias, bng, bnb, bnm, bnv, do_relu, Cf, Ch, Cl);
    }
}

// enc GEMM: A read directly as fp32 (split fused into loader). N must be 128.
static inline void launch_gemm_f32(
    const float* Af0, int K0, const float* Af1, int K1,
    const bf16* W0h, const bf16* W0l, const bf16* W1h, const bf16* W1l,
    int M, int N, const float* bias, int do_relu, bf16* Ch, bf16* Cl)
{
    constexpr int BM_ = 64, BN_ = 128;
    constexpr int SMEM = 2 * (2 * BM_ * A_STRIDE + 2 * BK * (BN_ + 8)) * 2;
    dim3 grid(N / BN_, (M + BM_ - 1) / BM_);
    gemm_bf16x3<BM_, BN_, 1><<<grid, 256, SMEM>>>(
        nullptr, nullptr, K0, nullptr, nullptr, K1, Af0, Af1,
        W0h, W0l, W1h, W1l, M, N,
        bias, nullptr, nullptr, nullptr, nullptr, do_relu, nullptr, Ch, Cl);
}

extern "C" void kernel_launch(void* const* d_in, const int* in_sizes, int n_in,
                              void* d_out, int out_size)
{
    const float* structural = (const float*)d_in[0];
    const float* multimodal = (const float*)d_in[1];
    const int*   src        = (const int*)  d_in[2];
    const int*   dst        = (const int*)  d_in[3];
    const float* enc_w      = (const float*)d_in[4];
    const float* enc_b      = (const float*)d_in[5];
    const float* sage0_ws   = (const float*)d_in[6];
    const float* sage0_wn   = (const float*)d_in[7];
    const float* sage0_b    = (const float*)d_in[8];
    const float* bn0_g      = (const float*)d_in[9];
    const float* bn0_b      = (const float*)d_in[10];
    const float* bn0_m      = (const float*)d_in[11];
    const float* bn0_v      = (const float*)d_in[12];
    const float* sage1_ws   = (const float*)d_in[13];
    const float* sage1_wn   = (const float*)d_in[14];
    const float* sage1_b    = (const float*)d_in[15];
    const float* bn1_g      = (const float*)d_in[16];
    const float* bn1_b      = (const float*)d_in[17];
    const float* bn1_m      = (const float*)d_in[18];
    const float* bn1_v      = (const float*)d_in[19];
    const float* rel_w      = (const float*)d_in[20];
    const float* rel_b      = (const float*)d_in[21];
    const float* cls_w1     = (const float*)d_in[22];
    const float* cls_b1     = (const float*)d_in[23];
    const float* cls_w2     = (const float*)d_in[24];
    const float* cls_b2     = (const float*)d_in[25];
    float* out = (float*)d_out;

#define SYMADDR(var, sym) void* p_##var; cudaGetSymbolAddress(&p_##var, sym);
    SYMADDR(h0h, g_h0h) SYMADDR(h0l, g_h0l) SYMADDR(a0h, g_a0h) SYMADDR(a0l, g_a0l)
    SYMADDR(h1h, g_h1h) SYMADDR(h1l, g_h1l)
    SYMADDR(h2h, g_h2h) SYMADDR(h2l, g_h2l) SYMADDR(hfh, g_hfh) SYMADDR(hfl, g_hfl)
    SYMADDR(c1h, g_c1h) SYMADDR(c1l, g_c1l)
    SYMADDR(s1f, g_s1f) SYMADDR(g1f, g_g1f)
    SYMADDR(wh, g_wh) SYMADDR(wl, g_wl)
    SYMADDR(counts, g_counts) SYMADDR(rowptr, g_rowptr)
    SYMADDR(fill, g_fill) SYMADDR(csr, g_csr)
#undef SYMADDR

    bf16* h0h = (bf16*)p_h0h; bf16* h0l = (bf16*)p_h0l;
    bf16* a0h = (bf16*)p_a0h; bf16* a0l = (bf16*)p_a0l;
    bf16* h1h = (bf16*)p_h1h; bf16* h1l = (bf16*)p_h1l;
    bf16* h2h = (bf16*)p_h2h; bf16* h2l = (bf16*)p_h2l;
    bf16* hfh = (bf16*)p_hfh; bf16* hfl = (bf16*)p_hfl;
    bf16* c1h = (bf16*)p_c1h; bf16* c1l = (bf16*)p_c1l;
    float* s1f = (float*)p_s1f; float* g1f = (float*)p_g1f;
    bf16* wh = (bf16*)p_wh; bf16* wl = (bf16*)p_wl;
    int* counts = (int*)p_counts; int* rowptr = (int*)p_rowptr;
    int* fill   = (int*)p_fill;   int* csr    = (int*)p_csr;

    {
        constexpr int SMEM_A = 2 * (2 * 64 * A_STRIDE + 2 * BK * (128 + 8)) * 2;
        constexpr int SMEM_B = 2 * (2 * 128 * A_STRIDE + 2 * BK * (64 + 8)) * 2;
        cudaFuncSetAttribute((const void*)gemm_bf16x3<64, 128, 0>,
                             cudaFuncAttributeMaxDynamicSharedMemorySize, SMEM_A);
        cudaFuncSetAttribute((const void*)gemm_bf16x3<64, 128, 1>,
                             cudaFuncAttributeMaxDynamicSharedMemorySize, SMEM_A);
        cudaFuncSetAttribute((const void*)gemm_bf16x3<128, 64, 0>,
                             cudaFuncAttributeMaxDynamicSharedMemorySize, SMEM_B);
    }

    const int M = N_NODES, E = N_EDGES;

    // ---- CSR build ----
    cudaMemsetAsync(counts, 0, N_NODES * sizeof(int), 0);
    count_deg<<<(E + 255) / 256, 256>>>(dst, counts, E);
    scan_counts<<<1, 1024>>>(counts, rowptr, fill, M);
    fill_csr<<<(E + 255) / 256, 256>>>(src, dst, fill, csr, E);

    // ---- split all weights (1 launch; inputs no longer split) ----
    {
        WSeg ws;
        ws.src[0] = enc_w;    ws.beg[0] = WOFF_ENC;
        ws.src[1] = sage0_ws; ws.beg[1] = WOFF_S0S;
        ws.src[2] = sage0_wn; ws.beg[2] = WOFF_S0N;
        ws.src[3] = sage1_ws; ws.beg[3] = WOFF_S1S;
        ws.src[4] = sage1_wn; ws.beg[4] = WOFF_S1N;
        ws.src[5] = rel_w;    ws.beg[5] = WOFF_REL;
        ws.src[6] = cls_w1;   ws.beg[6] = WOFF_C1;
        ws.src[7] = cls_w2;   ws.beg[7] = WOFF_C2;
        ws.beg[8] = WOFF_END;
        int w4 = WOFF_END / 4;
        split_weights<<<(w4 + 255) / 256, 256>>>(ws, wh, wl);
    }

    // h0 = relu([structural|multimodal] @ enc_w + enc_b)  (fp32 A path)
    launch_gemm_f32(structural, 128, multimodal, 384,
                    wh + WOFF_ENC, wl + WOFF_ENC,
                    wh + WOFF_ENC + 128 * 128, wl + WOFF_ENC + 128 * 128,
                    M, 128, enc_b, 1, h0h, h0l);

    // agg0 = mean h0  (gather over planes)
    gather_mean<<<(M * 32 + 255) / 256, 256>>>(h0h, h0l, csr, rowptr,
                                               a0h, a0l, M, 128);

    // h1 = relu(bn0(h0 @ ws0 + agg0 @ wn0 + b0))
    launch_gemm(h0h, h0l, 128, a0h, a0l, 128,
                wh + WOFF_S0S, wl + WOFF_S0S, wh + WOFF_S0N, wl + WOFF_S0N,
                M, 256, sage0_b, bn0_g, bn0_b, bn0_m, bn0_v, 1,
                nullptr, h1h, h1l);

    // ---- sage1, commuted: mean(h1) @ Wn1 == mean(h1 @ Wn1) ----
    launch_gemm(h1h, h1l, 256, h1h, h1l, 0,
                wh + WOFF_S1N, wl + WOFF_S1N, wh + WOFF_S1N, wl + WOFF_S1N,
                M, 128, nullptr, nullptr, nullptr, nullptr, nullptr, 0,
                g1f, nullptr, nullptr);
    launch_gemm(h1h, h1l, 256, h1h, h1l, 0,
                wh + WOFF_S1S, wl + WOFF_S1S, wh + WOFF_S1S, wl + WOFF_S1S,
                M, 128, nullptr, nullptr, nullptr, nullptr, nullptr, 0,
                s1f, nullptr, nullptr);
    gather_fuse_bn<<<(M * 32 + 255) / 256, 256>>>(
        s1f, g1f, csr, rowptr, sage1_b, bn1_g, bn1_b, bn1_m, bn1_v,
        h2h, h2l, M);

    // hf = relu([h0|h2] @ rel_w + rel_b)
    launch_gemm(h0h, h0l, 128, h2h, h2l, 128,
                wh + WOFF_REL, wl + WOFF_REL,
                wh + WOFF_REL + 128 * 128, wl + WOFF_REL + 128 * 128,
                M, 128, rel_b, nullptr, nullptr, nullptr, nullptr, 1,
                nullptr, hfh, hfl);

    // c1 = relu(hf @ cls_w1 + cls_b1)
    launch_gemm(hfh, hfl, 128, hfh, hfl, 0,
                wh + WOFF_C1, wl + WOFF_C1, wh + WOFF_C1, wl + WOFF_C1,
                M, 64, cls_b1, nullptr, nullptr, nullptr, nullptr, 1,
                nullptr, c1h, c1l);

    // out = c1 @ cls_w2 + cls_b2   (fp32)
    launch_gemm(c1h, c1l, 64, c1h, c1l, 0,
                wh + WOFF_C2, wl + WOFF_C2, wh + WOFF_C2, wl + WOFF_C2,
                M, 32, cls_b2, nullptr, nullptr, nullptr, nullptr, 0,
                out, nullptr, nullptr);
}

// round 12
// speedup vs baseline: 1.3057x; 1.1290x over previous
#include <cuda_runtime.h>
#include <cuda_fp16.h>
#include <math.h>
#include <stdint.h>

#define N_NODES 100000
#define N_EDGES 800000

typedef __half  fp16;
typedef __half2 fp162;

// ---------------- scratch (device globals; no allocs allowed) ----------------
__device__ fp16 g_h0h[(size_t)N_NODES * 128], g_h0l[(size_t)N_NODES * 128];
__device__ fp16 g_a0h[(size_t)N_NODES * 128], g_a0l[(size_t)N_NODES * 128];
__device__ fp16 g_h1h[(size_t)N_NODES * 256], g_h1l[(size_t)N_NODES * 256];
__device__ fp16 g_h2h[(size_t)N_NODES * 128], g_h2l[(size_t)N_NODES * 128];
__device__ fp16 g_hfh[(size_t)N_NODES * 128], g_hfl[(size_t)N_NODES * 128];
__device__ fp16 g_c1h[(size_t)N_NODES * 64],  g_c1l[(size_t)N_NODES * 64];
__device__ float g_s1f[(size_t)N_NODES * 128];   // h1 @ Ws1  (fp32)
__device__ float g_g1f[(size_t)N_NODES * 128];   // h1 @ Wn1  (fp32)
__device__ fp16 g_wh[262144];                    // single fp16 weight plane
__device__ int g_counts[N_NODES];
__device__ int g_rowptr[N_NODES + 1];
__device__ int g_fill  [N_NODES];
__device__ int g_csr   [N_EDGES];

// weight plane offsets (elements)
#define WOFF_ENC 0        // 512*128 = 65536
#define WOFF_S0S 65536    // 128*256 = 32768
#define WOFF_S0N 98304
#define WOFF_S1S 131072   // 256*128
#define WOFF_S1N 163840
#define WOFF_REL 196608   // 256*128
#define WOFF_C1  229376   // 128*64 = 8192
#define WOFF_C2  237568   // 64*32  = 2048
#define WOFF_END 239616

// ---------------- fp16x2 tensor-core GEMM (A hi/lo split, B single) ----------
#define BK 32
#define A_STRIDE 40

__device__ __forceinline__ void cp16(uint32_t dst, const void* src, bool pred) {
    asm volatile("cp.async.cg.shared.global [%0], [%1], 16, %2;"
                 :: "r"(dst), "l"(src), "r"(pred ? 16 : 0));
}

#define LDMX4(r, addr)                                                          \
    asm volatile("ldmatrix.sync.aligned.m8n8.x4.shared.b16 {%0,%1,%2,%3},[%4];" \
                 : "=r"((r)[0]), "=r"((r)[1]), "=r"((r)[2]), "=r"((r)[3])       \
                 : "r"(addr))

#define LDMX4T(r, addr)                                                         \
    asm volatile("ldmatrix.sync.aligned.m8n8.x4.trans.shared.b16 "              \
                 "{%0,%1,%2,%3},[%4];"                                          \
                 : "=r"((r)[0]), "=r"((r)[1]), "=r"((r)[2]), "=r"((r)[3])       \
                 : "r"(addr))

#define MMA_FP16(acc, a, b0, b1)                                                \
    asm volatile(                                                               \
        "mma.sync.aligned.m16n8k16.row.col.f32.f16.f16.f32 "                    \
        "{%0,%1,%2,%3},{%4,%5,%6,%7},{%8,%9},{%0,%1,%2,%3};"                    \
        : "+f"((acc)[0]), "+f"((acc)[1]), "+f"((acc)[2]), "+f"((acc)[3])        \
        : "r"((a)[0]), "r"((a)[1]), "r"((a)[2]), "r"((a)[3]),                   \
          "r"(b0), "r"(b1))

// convert 8 fp32 -> 8 fp16 hi + 8 fp16 lo (packed as uint4 each)
__device__ __forceinline__ void cvt8_planes(float4 v0, float4 v1,
                                            uint4& hi, uint4& lo)
{
    fp162 h0 = __float22half2_rn(make_float2(v0.x, v0.y));
    fp162 h1 = __float22half2_rn(make_float2(v0.z, v0.w));
    fp162 h2 = __float22half2_rn(make_float2(v1.x, v1.y));
    fp162 h3 = __float22half2_rn(make_float2(v1.z, v1.w));
    float2 f0 = __half22float2(h0);
    float2 f1 = __half22float2(h1);
    float2 f2 = __half22float2(h2);
    float2 f3 = __half22float2(h3);
    fp162 l0 = __float22half2_rn(make_float2(v0.x - f0.x, v0.y - f0.y));
    fp162 l1 = __float22half2_rn(make_float2(v0.z - f1.x, v0.w - f1.y));
    fp162 l2 = __float22half2_rn(make_float2(v1.x - f2.x, v1.y - f2.y));
    fp162 l3 = __float22half2_rn(make_float2(v1.z - f3.x, v1.w - f3.y));
    hi.x = *(uint32_t*)&h0; hi.y = *(uint32_t*)&h1;
    hi.z = *(uint32_t*)&h2; hi.w = *(uint32_t*)&h3;
    lo.x = *(uint32_t*)&l0; lo.y = *(uint32_t*)&l1;
    lo.z = *(uint32_t*)&l2; lo.w = *(uint32_t*)&l3;
}

template<int BM_, int BN_, int AF32>
__global__ __launch_bounds__(256, 2) void gemm_fp16x2(
    const fp16* __restrict__ A0h, const fp16* __restrict__ A0l, int K0,
    const fp16* __restrict__ A1h, const fp16* __restrict__ A1l, int K1,
    const float* __restrict__ Af0, const float* __restrict__ Af1,
    const fp16* __restrict__ W0, const fp16* __restrict__ W1,
    int M, int N,
    const float* __restrict__ bias,
    const float* __restrict__ bng, const float* __restrict__ bnb,
    const float* __restrict__ bnm, const float* __restrict__ bnv,
    int do_relu,
    float* __restrict__ Cf, fp16* __restrict__ Ch, fp16* __restrict__ Cl)
{
    constexpr int A_PLANE_ = BM_ * A_STRIDE;
    constexpr int B_STRIDE = BN_ + 8;
    constexpr int B_PLANE  = BK * B_STRIDE;
    constexpr int STAGE_ELEMS = 2 * A_PLANE_ + B_PLANE;
    constexpr int WROWS  = BM_ / 32;
    constexpr int WARP_N = BN_ * WROWS / 8;          // 32 in both configs
    constexpr int NT = WARP_N / 8;
    constexpr int P  = WARP_N / 16;
    constexpr int NCP = BN_ / 64;

    extern __shared__ fp16 smem[];
    const uint32_t smem_u32 = (uint32_t)__cvta_generic_to_shared(smem);

    const int tid  = threadIdx.x;
    const int lane = tid & 31;
    const int wid  = tid >> 5;
    const int wm   = (wid % WROWS) * 32;
    const int wn   = (wid / WROWS) * WARP_N;
    const int brow = blockIdx.y * BM_;
    const int bcol = blockIdx.x * BN_;
    const int K = K0 + K1;
    const int T = K / BK;

    constexpr int ATPR = 256 / BM_;
    const int a_row = tid / ATPR;
    const int a_k   = (tid % ATPR) * (32 / ATPR);
    const int a_gr  = brow + a_row;
    const bool a_ok = (a_gr < M);
    const int b_k  = tid >> 3;
    const int b_n0 = (tid & 7) * (BN_ / 8);

    const int a_lm = (wm + (lane & 15)) * A_STRIDE + (lane >> 4) * 8;
    const int b_lm = ((lane & 7) + ((lane >> 3) & 1) * 8) * B_STRIDE
                     + wn + (lane >> 4) * 8;

    float acc[2][NT][4];
#pragma unroll
    for (int mt = 0; mt < 2; mt++)
#pragma unroll
        for (int nt = 0; nt < NT; nt++)
#pragma unroll
            for (int i = 0; i < 4; i++) acc[mt][nt][i] = 0.f;

#define LOAD_TILE(t, st) do {                                                     \
        const int kt_ = (t) * BK;                                                 \
        if (AF32) {                                                               \
          int gk0 = kt_ + a_k;                                                    \
          const float* sp;                                                        \
          if (gk0 < K0) sp = Af0 + (size_t)a_gr * K0 + gk0;                       \
          else          sp = Af1 + (size_t)a_gr * K1 + (gk0 - K0);                \
          float4 v0 = make_float4(0.f, 0.f, 0.f, 0.f), v1 = v0;                   \
          if (a_ok) { v0 = *(const float4*)sp; v1 = *(const float4*)(sp + 4); }   \
          uint4 hi_, lo_;                                                         \
          cvt8_planes(v0, v1, hi_, lo_);                                          \
          fp16* ap = smem + (st) * STAGE_ELEMS + a_row * A_STRIDE + a_k;          \
          *(uint4*)ap = hi_;                                                      \
          *(uint4*)(ap + A_PLANE_) = lo_;                                         \
        } else {                                                                  \
          int gk0 = kt_ + a_k;                                                    \
          const fp16 *sph, *spl;                                                  \
          if (gk0 < K0) { sph = A0h + (size_t)a_gr * K0 + gk0;                    \
                          spl = A0l + (size_t)a_gr * K0 + gk0; }                  \
          else          { sph = A1h + (size_t)a_gr * K1 + (gk0 - K0);             \
                          spl = A1l + (size_t)a_gr * K1 + (gk0 - K0); }           \
          uint32_t dh = smem_u32 +                                                \
              ((st) * STAGE_ELEMS + a_row * A_STRIDE + a_k) * 2;                  \
          if (ATPR == 2) {                                                        \
              cp16(dh,      sph,     a_ok);                                       \
              cp16(dh + 16, sph + 8, a_ok);                                       \
              cp16(dh + A_PLANE_ * 2,      spl,     a_ok);                        \
              cp16(dh + A_PLANE_ * 2 + 16, spl + 8, a_ok);                        \
          } else {                                                                \
              cp16(dh,                sph, a_ok);                                 \
              cp16(dh + A_PLANE_ * 2, spl, a_ok);                                 \
          }                                                                       \
        }                                                                         \
        { int gk = kt_ + b_k;                                                     \
          const fp16 *wp; int kk2;                                                \
          if (gk < K0) { wp = W0; kk2 = gk; }                                     \
          else         { wp = W1; kk2 = gk - K0; }                                \
          uint32_t dbh = smem_u32 +                                               \
              ((st) * STAGE_ELEMS + 2 * A_PLANE_ + b_k * B_STRIDE + b_n0) * 2;    \
          _Pragma("unroll")                                                       \
          for (int cc = 0; cc < NCP; cc++) {                                      \
              int n0 = bcol + b_n0 + cc * 8;                                      \
              bool ok = (n0 < N);                                                 \
              cp16(dbh + cc * 16, wp + (size_t)kk2 * N + n0, ok);                 \
          }                                                                       \
        }                                                                         \
        asm volatile("cp.async.commit_group;");                                   \
    } while (0)

    LOAD_TILE(0, 0);

    for (int t = 0; t < T; ++t) {
        const int st = t & 1;
        if (t + 1 < T) {
            LOAD_TILE(t + 1, st ^ 1);
            asm volatile("cp.async.wait_group 1;");
        } else {
            asm volatile("cp.async.wait_group 0;");
        }
        __syncthreads();

        const uint32_t base = smem_u32 + st * STAGE_ELEMS * 2;
#pragma unroll
        for (int k16 = 0; k16 < 2; k16++) {
            uint32_t ah[2][4], al[2][4], bh[P][4];
#pragma unroll
            for (int mt = 0; mt < 2; mt++) {
                uint32_t ad = base + (a_lm + mt * 16 * A_STRIDE + k16 * 16) * 2;
                LDMX4(ah[mt], ad);
                LDMX4(al[mt], ad + A_PLANE_ * 2);
            }
#pragma unroll
            for (int p = 0; p < P; p++) {
                uint32_t bd = base + (2 * A_PLANE_ + b_lm + p * 16
                                      + k16 * 16 * B_STRIDE) * 2;
                LDMX4T(bh[p], bd);
            }
#pragma unroll
            for (int mt = 0; mt < 2; mt++)
#pragma unroll
                for (int nt = 0; nt < NT; nt++) {
                    const int p = nt >> 1, q = (nt & 1) * 2;
                    MMA_FP16(acc[mt][nt], al[mt], bh[p][q], bh[p][q + 1]);
                    MMA_FP16(acc[mt][nt], ah[mt], bh[p][q], bh[p][q + 1]);
                }
        }
        __syncthreads();
    }

#pragma unroll
    for (int nt = 0; nt < NT; nt++) {
        const int col = bcol + wn + 8 * nt + 2 * (lane & 3);
        if (col >= N) continue;
        float sc0 = 1.f, sh0 = 0.f, sc1 = 1.f, sh1 = 0.f;
        if (bias) { sh0 = bias[col]; sh1 = bias[col + 1]; }
        if (bng) {
            float s0 = bng[col]     * rsqrtf(bnv[col]     + 1e-5f);
            float s1 = bng[col + 1] * rsqrtf(bnv[col + 1] + 1e-5f);
            sh0 = (sh0 - bnm[col])     * s0 + bnb[col];
            sh1 = (sh1 - bnm[col + 1]) * s1 + bnb[col + 1];
            sc0 = s0; sc1 = s1;
        }
#pragma unroll
        for (int mt = 0; mt < 2; mt++) {
#pragma unroll
            for (int half = 0; half < 2; half++) {
                const int row = brow + wm + 16 * mt + (lane >> 2) + 8 * half;
                if (row >= M) continue;
                const float* c = acc[mt][nt] + 2 * half;
                float v0 = c[0] * sc0 + sh0;
                float v1 = c[1] * sc1 + sh1;
                if (do_relu) { v0 = fmaxf(v0, 0.f); v1 = fmaxf(v1, 0.f); }
                if (Ch) {
                    fp162 hi = __float22half2_rn(make_float2(v0, v1));
                    float2 hf2 = __half22float2(hi);
                    fp162 lo = __float22half2_rn(
                        make_float2(v0 - hf2.x, v1 - hf2.y));
                    *(fp162*)(Ch + (size_t)row * N + col) = hi;
                    *(fp162*)(Cl + (size_t)row * N + col) = lo;
                } else {
                    *(float2*)(Cf + (size_t)row * N + col) = make_float2(v0, v1);
                }
            }
        }
    }
}

// ---------------- merged weight split: all 8 segments, single fp16 plane ------
struct WSeg { const float* src[8]; int beg[9]; };

__global__ void split_weights(WSeg ws, fp16* __restrict__ wh)
{
    int i4 = blockIdx.x * blockDim.x + threadIdx.x;
    int i  = i4 * 4;
    if (i >= ws.beg[8]) return;
    int s = 0;
#pragma unroll
    for (int k = 0; k < 7; k++) s += (i >= ws.beg[k + 1]) ? 1 : 0;
    float4 v = *(const float4*)(ws.src[s] + (i - ws.beg[s]));
    fp162 h0 = __float22half2_rn(make_float2(v.x, v.y));
    fp162 h1 = __float22half2_rn(make_float2(v.z, v.w));
    ((fp162*)wh)[i4 * 2]     = h0;
    ((fp162*)wh)[i4 * 2 + 1] = h1;
}

// ---------------- CSR construction ----------------
__global__ void count_deg(const int* __restrict__ dst, int* __restrict__ counts, int E)
{
    int e = blockIdx.x * blockDim.x + threadIdx.x;
    if (e < E) atomicAdd(&counts[dst[e]], 1);
}

__global__ __launch_bounds__(1024) void scan_counts(
    const int* __restrict__ counts, int* __restrict__ rowptr,
    int* __restrict__ fill, int n)
{
    __shared__ int part[1024];
    const int tid = threadIdx.x;
    const int chunk = (n + 1023) / 1024;
    const int begin = min(tid * chunk, n);
    const int end   = min(begin + chunk, n);
    int s = 0;
    for (int i = begin; i < end; i++) s += counts[i];
    part[tid] = s;
    __syncthreads();
    for (int off = 1; off < 1024; off <<= 1) {
        int v = (tid >= off) ? part[tid - off] : 0;
        __syncthreads();
        part[tid] += v;
        __syncthreads();
    }
    int pre = (tid == 0) ? 0 : part[tid - 1];
    for (int i = begin; i < end; i++) {
        rowptr[i] = pre;
        fill[i]   = pre;
        pre += counts[i];
    }
    if (end == n && begin <= n) rowptr[n] = pre;
}

__global__ void fill_csr(const int* __restrict__ src, const int* __restrict__ dst,
                         int* __restrict__ fill, int* __restrict__ csr, int E)
{
    int e = blockIdx.x * blockDim.x + threadIdx.x;
    if (e < E) {
        int pos = atomicAdd(&fill[dst[e]], 1);
        csr[pos] = src[e];
    }
}

// ---------------- CSR gather mean over fp16 planes (layer-0) ----------------
__global__ void gather_mean(const fp16* __restrict__ hh, const fp16* __restrict__ hl,
                            const int* __restrict__ csr, const int* __restrict__ rowptr,
                            fp16* __restrict__ oh, fp16* __restrict__ ol,
                            int Nn, int D)
{
    const int warp = (blockIdx.x * blockDim.x + threadIdx.x) >> 5;
    const int lane = threadIdx.x & 31;
    if (warp >= Nn) return;
    const int e0 = rowptr[warp];
    const int e1 = rowptr[warp + 1];
    const float inv = 1.f / (float)max(e1 - e0, 1);
    const int nseg = D >> 7;
    float acc[8];
#pragma unroll
    for (int i = 0; i < 8; i++) acc[i] = 0.f;

    for (int e = e0; e < e1; e++) {
        const int s = csr[e];
        const fp16* rh = hh + (size_t)s * D + lane * 4;
        const fp16* rl = hl + (size_t)s * D + lane * 4;
#pragma unroll
        for (int g = 0; g < 2; g++) {
            if (g < nseg) {
                uint2 vh = *(const uint2*)(rh + g * 128);
                uint2 vl = *(const uint2*)(rl + g * 128);
                float2 a0 = __half22float2(*(const fp162*)&vh.x);
                float2 a1 = __half22float2(*(const fp162*)&vh.y);
                float2 b0 = __half22float2(*(const fp162*)&vl.x);
                float2 b1 = __half22float2(*(const fp162*)&vl.y);
                acc[g * 4 + 0] += a0.x + b0.x;
                acc[g * 4 + 1] += a0.y + b0.y;
                acc[g * 4 + 2] += a1.x + b1.x;
                acc[g * 4 + 3] += a1.y + b1.y;
            }
        }
    }

#pragma unroll
    for (int g = 0; g < 2; g++) {
        if (g < nseg) {
            float v0 = acc[g * 4 + 0] * inv;
            float v1 = acc[g * 4 + 1] * inv;
            float v2 = acc[g * 4 + 2] * inv;
            float v3 = acc[g * 4 + 3] * inv;
            fp162 h0 = __float22half2_rn(make_float2(v0, v1));
            fp162 h1 = __float22half2_rn(make_float2(v2, v3));
            float2 f0 = __half22float2(h0);
            float2 f1 = __half22float2(h1);
            fp162 l0 = __float22half2_rn(make_float2(v0 - f0.x, v1 - f0.y));
            fp162 l1 = __float22half2_rn(make_float2(v2 - f1.x, v3 - f1.y));
            uint2 wh_, wl_;
            wh_.x = *(uint32_t*)&h0; wh_.y = *(uint32_t*)&h1;
            wl_.x = *(uint32_t*)&l0; wl_.y = *(uint32_t*)&l1;
            *(uint2*)(oh + (size_t)warp * D + g * 128 + lane * 4) = wh_;
            *(uint2*)(ol + (size_t)warp * D + g * 128 + lane * 4) = wl_;
        }
    }
}

// ---------------- layer-1 fused gather: mean(G1)+S1, bias+bn+relu -> planes ----
__global__ void gather_fuse_bn(const float* __restrict__ S1,
                               const float* __restrict__ G1,
                               const int* __restrict__ csr,
                               const int* __restrict__ rowptr,
                               const float* __restrict__ bias,
                               const float* __restrict__ bng,
                               const float* __restrict__ bnb,
                               const float* __restrict__ bnm,
                               const float* __restrict__ bnv,
                               fp16* __restrict__ oh, fp16* __restrict__ ol,
                               int Nn)
{
    const int warp = (blockIdx.x * blockDim.x + threadIdx.x) >> 5;
    const int lane = threadIdx.x & 31;
    if (warp >= Nn) return;
    const int e0 = rowptr[warp];
    const int e1 = rowptr[warp + 1];
    const float inv = 1.f / (float)max(e1 - e0, 1);
    const int col = lane * 4;

    float acc0 = 0.f, acc1 = 0.f, acc2 = 0.f, acc3 = 0.f;
    for (int e = e0; e < e1; e++) {
        const float4 v = *(const float4*)(G1 + (size_t)csr[e] * 128 + col);
        acc0 += v.x; acc1 += v.y; acc2 += v.z; acc3 += v.w;
    }
    const float4 s = *(const float4*)(S1 + (size_t)warp * 128 + col);

    float vo[4];
    const float* sp = &s.x;
    float ac[4] = {acc0, acc1, acc2, acc3};
#pragma unroll
    for (int j = 0; j < 4; j++) {
        const float sc = bng[col + j] * rsqrtf(bnv[col + j] + 1e-5f);
        const float sh = (bias[col + j] - bnm[col + j]) * sc + bnb[col + j];
        float x = (sp[j] + ac[j] * inv) * sc + sh;
        vo[j] = fmaxf(x, 0.f);
    }

    fp162 h0 = __float22half2_rn(make_float2(vo[0], vo[1]));
    fp162 h1 = __float22half2_rn(make_float2(vo[2], vo[3]));
    float2 f0 = __half22float2(h0);
    float2 f1 = __half22float2(h1);
    fp162 l0 = __float22half2_rn(make_float2(vo[0] - f0.x, vo[1] - f0.y));
    fp162 l1 = __float22half2_rn(make_float2(vo[2] - f1.x, vo[3] - f1.y));
    uint2 wh_, wl_;
    wh_.x = *(uint32_t*)&h0; wh_.y = *(uint32_t*)&h1;
    wl_.x = *(uint32_t*)&l0; wl_.y = *(uint32_t*)&l1;
    *(uint2*)(oh + (size_t)warp * 128 + col) = wh_;
    *(uint2*)(ol + (size_t)warp * 128 + col) = wl_;
}

// ---------------- launch helpers ----------------
static inline void launch_gemm(
    const fp16* A0h, const fp16* A0l, int K0,
    const fp16* A1h, const fp16* A1l, int K1,
    const fp16* W0, const fp16* W1,
    int M, int N,
    const float* bias, const float* bng, const float* bnb,
    const float* bnm, const float* bnv,
    int do_relu, float* Cf, fp16* Ch, fp16* Cl)
{
    if (N >= 128) {
        constexpr int BM_ = 64, BN_ = 128;
        constexpr int SMEM = 2 * (2 * BM_ * A_STRIDE + BK * (BN_ + 8)) * 2;
        dim3 grid(N / BN_, (M + BM_ - 1) / BM_);
        gemm_fp16x2<BM_, BN_, 0><<<grid, 256, SMEM>>>(
            A0h, A0l, K0, A1h, A1l, K1, nullptr, nullptr,
            W0, W1, M, N,
            bias, bng, bnb, bnm, bnv, do_relu, Cf, Ch, Cl);
    } else {
        constexpr int BM_ = 128, BN_ = 64;
        constexpr int SMEM = 2 * (2 * BM_ * A_STRIDE + BK * (BN_ + 8)) * 2;
        dim3 grid((N + BN_ - 1) / BN_, (M + BM_ - 1) / BM_);
        gemm_fp16x2<BM_, BN_, 0><<<grid, 256, SMEM>>>(
            A0h, A0l, K0, A1h, A1l, K1, nullptr, nullptr,
            W0, W1, M, N,
            bias, bng, bnb, bnm, bnv, do_relu, Cf, Ch, Cl);
    }
}

// enc GEMM: A read directly as fp32 (split fused into loader). N must be 128.
static inline void launch_gemm_f32(
    const float* Af0, int K0, const float* Af1, int K1,
    const fp16* W0, const fp16* W1,
    int M, int N, const float* bias, int do_relu, fp16* Ch, fp16* Cl)
{
    constexpr int BM_ = 64, BN_ = 128;
    constexpr int SMEM = 2 * (2 * BM_ * A_STRIDE + BK * (BN_ + 8)) * 2;
    dim3 grid(N / BN_, (M + BM_ - 1) / BM_);
    gemm_fp16x2<BM_, BN_, 1><<<grid, 256, SMEM>>>(
        nullptr, nullptr, K0, nullptr, nullptr, K1, Af0, Af1,
        W0, W1, M, N,
        bias, nullptr, nullptr, nullptr, nullptr, do_relu, nullptr, Ch, Cl);
}

extern "C" void kernel_launch(void* const* d_in, const int* in_sizes, int n_in,
                              void* d_out, int out_size)
{
    const float* structural = (const float*)d_in[0];
    const float* multimodal = (const float*)d_in[1];
    const int*   src        = (const int*)  d_in[2];
    const int*   dst        = (const int*)  d_in[3];
    const float* enc_w      = (const float*)d_in[4];
    const float* enc_b      = (const float*)d_in[5];
    const float* sage0_ws   = (const float*)d_in[6];
    const float* sage0_wn   = (const float*)d_in[7];
    const float* sage0_b    = (const float*)d_in[8];
    const float* bn0_g      = (const float*)d_in[9];
    const float* bn0_b      = (const float*)d_in[10];
    const float* bn0_m      = (const float*)d_in[11];
    const float* bn0_v      = (const float*)d_in[12];
    const float* sage1_ws   = (const float*)d_in[13];
    const float* sage1_wn   = (const float*)d_in[14];
    const float* sage1_b    = (const float*)d_in[15];
    const float* bn1_g      = (const float*)d_in[16];
    const float* bn1_b      = (const float*)d_in[17];
    const float* bn1_m      = (const float*)d_in[18];
    const float* bn1_v      = (const float*)d_in[19];
    const float* rel_w      = (const float*)d_in[20];
    const float* rel_b      = (const float*)d_in[21];
    const float* cls_w1     = (const float*)d_in[22];
    const float* cls_b1     = (const float*)d_in[23];
    const float* cls_w2     = (const float*)d_in[24];
    const float* cls_b2     = (const float*)d_in[25];
    float* out = (float*)d_out;

#define SYMADDR(var, sym) void* p_##var; cudaGetSymbolAddress(&p_##var, sym);
    SYMADDR(h0h, g_h0h) SYMADDR(h0l, g_h0l) SYMADDR(a0h, g_a0h) SYMADDR(a0l, g_a0l)
    SYMADDR(h1h, g_h1h) SYMADDR(h1l, g_h1l)
    SYMADDR(h2h, g_h2h) SYMADDR(h2l, g_h2l) SYMADDR(hfh, g_hfh) SYMADDR(hfl, g_hfl)
    SYMADDR(c1h, g_c1h) SYMADDR(c1l, g_c1l)
    SYMADDR(s1f, g_s1f) SYMADDR(g1f, g_g1f)
    SYMADDR(wh, g_wh)
    SYMADDR(counts, g_counts) SYMADDR(rowptr, g_rowptr)
    SYMADDR(fill, g_fill) SYMADDR(csr, g_csr)
#undef SYMADDR

    fp16* h0h = (fp16*)p_h0h; fp16* h0l = (fp16*)p_h0l;
    fp16* a0h = (fp16*)p_a0h; fp16* a0l = (fp16*)p_a0l;
    fp16* h1h = (fp16*)p_h1h; fp16* h1l = (fp16*)p_h1l;
    fp16* h2h = (fp16*)p_h2h; fp16* h2l = (fp16*)p_h2l;
    fp16* hfh = (fp16*)p_hfh; fp16* hfl = (fp16*)p_hfl;
    fp16* c1h = (fp16*)p_c1h; fp16* c1l = (fp16*)p_c1l;
    float* s1f = (float*)p_s1f; float* g1f = (float*)p_g1f;
    fp16* wh = (fp16*)p_wh;
    int* counts = (int*)p_counts; int* rowptr = (int*)p_rowptr;
    int* fill   = (int*)p_fill;   int* csr    = (int*)p_csr;

    {
        constexpr int SMEM_A = 2 * (2 * 64 * A_STRIDE + BK * (128 + 8)) * 2;
        constexpr int SMEM_B = 2 * (2 * 128 * A_STRIDE + BK * (64 + 8)) * 2;
        cudaFuncSetAttribute((const void*)gemm_fp16x2<64, 128, 0>,
                             cudaFuncAttributeMaxDynamicSharedMemorySize, SMEM_A);
        cudaFuncSetAttribute((const void*)gemm_fp16x2<64, 128, 1>,
                             cudaFuncAttributeMaxDynamicSharedMemorySize, SMEM_A);
        cudaFuncSetAttribute((const void*)gemm_fp16x2<128, 64, 0>,
                             cudaFuncAttributeMaxDynamicSharedMemorySize, SMEM_B);
    }

    const int M = N_NODES, E = N_EDGES;

    // ---- CSR build ----
    cudaMemsetAsync(counts, 0, N_NODES * sizeof(int), 0);
    count_deg<<<(E + 255) / 256, 256>>>(dst, counts, E);
    scan_counts<<<1, 1024>>>(counts, rowptr, fill, M);
    fill_csr<<<(E + 255) / 256, 256>>>(src, dst, fill, csr, E);

    // ---- split all weights to single fp16 plane (1 launch) ----
    {
        WSeg ws;
        ws.src[0] = enc_w;    ws.beg[0] = WOFF_ENC;
        ws.src[1] = sage0_ws; ws.beg[1] = WOFF_S0S;
        ws.src[2] = sage0_wn; ws.beg[2] = WOFF_S0N;
        ws.src[3] = sage1_ws; ws.beg[3] = WOFF_S1S;
        ws.src[4] = sage1_wn; ws.beg[4] = WOFF_S1N;
        ws.src[5] = rel_w;    ws.beg[5] = WOFF_REL;
        ws.src[6] = cls_w1;   ws.beg[6] = WOFF_C1;
        ws.src[7] = cls_w2;   ws.beg[7] = WOFF_C2;
        ws.beg[8] = WOFF_END;
        int w4 = WOFF_END / 4;
        split_weights<<<(w4 + 255) / 256, 256>>>(ws, wh);
    }

    // h0 = relu([structural|multimodal] @ enc_w + enc_b)  (fp32 A path)
    launch_gemm_f32(structural, 128, multimodal, 384,
                    wh + WOFF_ENC, wh + WOFF_ENC + 128 * 128,
                    M, 128, enc_b, 1, h0h, h0l);

    // agg0 = mean h0  (gather over planes)
    gather_mean<<<(M * 32 + 255) / 256, 256>>>(h0h, h0l, csr, rowptr,
                                               a0h, a0l, M, 128);

    // h1 = relu(bn0(h0 @ ws0 + agg0 @ wn0 + b0))
    launch_gemm(h0h, h0l, 128, a0h, a0l, 128,
                wh + WOFF_S0S, wh + WOFF_S0N,
                M, 256, sage0_b, bn0_g, bn0_b, bn0_m, bn0_v, 1,
                nullptr, h1h, h1l);

    // ---- sage1, commuted: mean(h1) @ Wn1 == mean(h1 @ Wn1) ----
    launch_gemm(h1h, h1l, 256, h1h, h1l, 0,
                wh + WOFF_S1N, wh + WOFF_S1N,
                M, 128, nullptr, nullptr, nullptr, nullptr, nullptr, 0,
                g1f, nullptr, nullptr);
    launch_gemm(h1h, h1l, 256, h1h, h1l, 0,
                wh + WOFF_S1S, wh + WOFF_S1S,
                M, 128, nullptr, nullptr, nullptr, nullptr, nullptr, 0,
                s1f, nullptr, nullptr);
    gather_fuse_bn<<<(M * 32 + 255) / 256, 256>>>(
        s1f, g1f, csr, rowptr, sage1_b, bn1_g, bn1_b, bn1_m, bn1_v,
        h2h, h2l, M);

    // hf = relu([h0|h2] @ rel_w + rel_b)
    launch_gemm(h0h, h0l, 128, h2h, h2l, 128,
                wh + WOFF_REL, wh + WOFF_REL + 128 * 128,
                M, 128, rel_b, nullptr, nullptr, nullptr, nullptr, 1,
                nullptr, hfh, hfl);

    // c1 = relu(hf @ cls_w1 + cls_b1)
    launch_gemm(hfh, hfl, 128, hfh, hfl, 0,
                wh + WOFF_C1, wh + WOFF_C1,
                M, 64, cls_b1, nullptr, nullptr, nullptr, nullptr, 1,
                nullptr, c1h, c1l);

    // out = c1 @ cls_w2 + cls_b2   (fp32)
    launch_gemm(c1h, c1l, 64, c1h, c1l, 0,
                wh + WOFF_C2, wh + WOFF_C2,
                M, 32, cls_b2, nullptr, nullptr, nullptr, nullptr, 0,
                out, nullptr, nullptr);
}

// round 13
// speedup vs baseline: 1.4552x; 1.1145x over previous
#include <cuda_runtime.h>
#include <cuda_fp16.h>
#include <math.h>
#include <stdint.h>

#define N_NODES 100000
#define N_EDGES 800000

typedef __half  fp16;
typedef __half2 fp162;

// ---------------- scratch (device globals; no allocs allowed) ----------------
__device__ fp16 g_h0h[(size_t)N_NODES * 128], g_h0l[(size_t)N_NODES * 128];
__device__ fp16 g_a0h[(size_t)N_NODES * 128], g_a0l[(size_t)N_NODES * 128];
__device__ fp16 g_h1h[(size_t)N_NODES * 256], g_h1l[(size_t)N_NODES * 256];
__device__ fp16 g_h2h[(size_t)N_NODES * 128], g_h2l[(size_t)N_NODES * 128];
__device__ fp16 g_hfh[(size_t)N_NODES * 128], g_hfl[(size_t)N_NODES * 128];
__device__ fp16 g_c1h[(size_t)N_NODES * 64],  g_c1l[(size_t)N_NODES * 64];
__device__ float g_s1f[(size_t)N_NODES * 128];   // h1 @ Ws1  (fp32)
__device__ float g_g1f[(size_t)N_NODES * 128];   // h1 @ Wn1  (fp32)
__device__ fp16 g_wh[262144];                    // single fp16 weight plane
__device__ int g_counts[N_NODES];
__device__ int g_rowptr[N_NODES + 1];
__device__ int g_fill  [N_NODES];
__device__ int g_csr   [N_EDGES];

// weight plane offsets (elements)
#define WOFF_ENC 0        // 512*128 = 65536
#define WOFF_S0S 65536    // 128*256 = 32768
#define WOFF_S0N 98304
#define WOFF_S1S 131072   // 256*128
#define WOFF_S1N 163840
#define WOFF_REL 196608   // 256*128
#define WOFF_C1  229376   // 128*64 = 8192
#define WOFF_C2  237568   // 64*32  = 2048
#define WOFF_END 239616

// ---------------- fp16x2 tensor-core GEMM (A hi/lo split, B single) ----------
#define BK 32
#define A_STRIDE 40

__device__ __forceinline__ void cp16(uint32_t dst, const void* src, bool pred) {
    asm volatile("cp.async.cg.shared.global [%0], [%1], 16, %2;"
                 :: "r"(dst), "l"(src), "r"(pred ? 16 : 0));
}

#define LDMX4(r, addr)                                                          \
    asm volatile("ldmatrix.sync.aligned.m8n8.x4.shared.b16 {%0,%1,%2,%3},[%4];" \
                 : "=r"((r)[0]), "=r"((r)[1]), "=r"((r)[2]), "=r"((r)[3])       \
                 : "r"(addr))

#define LDMX4T(r, addr)                                                         \
    asm volatile("ldmatrix.sync.aligned.m8n8.x4.trans.shared.b16 "              \
                 "{%0,%1,%2,%3},[%4];"                                          \
                 : "=r"((r)[0]), "=r"((r)[1]), "=r"((r)[2]), "=r"((r)[3])       \
                 : "r"(addr))

#define MMA_FP16(acc, a, b0, b1)                                                \
    asm volatile(                                                               \
        "mma.sync.aligned.m16n8k16.row.col.f32.f16.f16.f32 "                    \
        "{%0,%1,%2,%3},{%4,%5,%6,%7},{%8,%9},{%0,%1,%2,%3};"                    \
        : "+f"((acc)[0]), "+f"((acc)[1]), "+f"((acc)[2]), "+f"((acc)[3])        \
        : "r"((a)[0]), "r"((a)[1]), "r"((a)[2]), "r"((a)[3]),                   \
          "r"(b0), "r"(b1))

// convert 8 fp32 -> 8 fp16 hi + 8 fp16 lo (packed as uint4 each)
__device__ __forceinline__ void cvt8_planes(float4 v0, float4 v1,
                                            uint4& hi, uint4& lo)
{
    fp162 h0 = __float22half2_rn(make_float2(v0.x, v0.y));
    fp162 h1 = __float22half2_rn(make_float2(v0.z, v0.w));
    fp162 h2 = __float22half2_rn(make_float2(v1.x, v1.y));
    fp162 h3 = __float22half2_rn(make_float2(v1.z, v1.w));
    float2 f0 = __half22float2(h0);
    float2 f1 = __half22float2(h1);
    float2 f2 = __half22float2(h2);
    float2 f3 = __half22float2(h3);
    fp162 l0 = __float22half2_rn(make_float2(v0.x - f0.x, v0.y - f0.y));
    fp162 l1 = __float22half2_rn(make_float2(v0.z - f1.x, v0.w - f1.y));
    fp162 l2 = __float22half2_rn(make_float2(v1.x - f2.x, v1.y - f2.y));
    fp162 l3 = __float22half2_rn(make_float2(v1.z - f3.x, v1.w - f3.y));
    hi.x = *(uint32_t*)&h0; hi.y = *(uint32_t*)&h1;
    hi.z = *(uint32_t*)&h2; hi.w = *(uint32_t*)&h3;
    lo.x = *(uint32_t*)&l0; lo.y = *(uint32_t*)&l1;
    lo.z = *(uint32_t*)&l2; lo.w = *(uint32_t*)&l3;
}

template<int BM_, int BN_, int AF32>
__global__ __launch_bounds__(256, 3) void gemm_fp16x2(
    const fp16* __restrict__ A0h, const fp16* __restrict__ A0l, int K0,
    const fp16* __restrict__ A1h, const fp16* __restrict__ A1l, int K1,
    const float* __restrict__ Af0, const float* __restrict__ Af1,
    const fp16* __restrict__ W0, const fp16* __restrict__ W1,
    int M, int N,
    const float* __restrict__ bias,
    const float* __restrict__ bng, const float* __restrict__ bnb,
    const float* __restrict__ bnm, const float* __restrict__ bnv,
    int do_relu,
    float* __restrict__ Cf, fp16* __restrict__ Ch, fp16* __restrict__ Cl)
{
    constexpr int A_PLANE_ = BM_ * A_STRIDE;
    constexpr int B_STRIDE = BN_ + 8;
    constexpr int B_PLANE  = BK * B_STRIDE;
    constexpr int STAGE_ELEMS = 2 * A_PLANE_ + B_PLANE;
    constexpr int WROWS  = BM_ / 32;
    constexpr int WARP_N = BN_ * WROWS / 8;          // 32 in both configs
    constexpr int NT = WARP_N / 8;
    constexpr int P  = WARP_N / 16;
    constexpr int NCP = BN_ / 64;

    extern __shared__ fp16 smem[];
    const uint32_t smem_u32 = (uint32_t)__cvta_generic_to_shared(smem);

    const int tid  = threadIdx.x;
    const int lane = tid & 31;
    const int wid  = tid >> 5;
    const int wm   = (wid % WROWS) * 32;
    const int wn   = (wid / WROWS) * WARP_N;
    const int brow = blockIdx.y * BM_;
    const int bcol = blockIdx.x * BN_;
    const int K = K0 + K1;
    const int T = K / BK;

    constexpr int ATPR = 256 / BM_;
    const int a_row = tid / ATPR;
    const int a_k   = (tid % ATPR) * (32 / ATPR);
    const int a_gr  = brow + a_row;
    const bool a_ok = (a_gr < M);
    const int b_k  = tid >> 3;
    const int b_n0 = (tid & 7) * (BN_ / 8);

    const int a_lm = (wm + (lane & 15)) * A_STRIDE + (lane >> 4) * 8;
    const int b_lm = ((lane & 7) + ((lane >> 3) & 1) * 8) * B_STRIDE
                     + wn + (lane >> 4) * 8;

    float acc[2][NT][4];
#pragma unroll
    for (int mt = 0; mt < 2; mt++)
#pragma unroll
        for (int nt = 0; nt < NT; nt++)
#pragma unroll
            for (int i = 0; i < 4; i++) acc[mt][nt][i] = 0.f;

#define LOAD_TILE(t, st) do {                                                     \
        const int kt_ = (t) * BK;                                                 \
        if (AF32) {                                                               \
          int gk0 = kt_ + a_k;                                                    \
          const float* sp;                                                        \
          if (gk0 < K0) sp = Af0 + (size_t)a_gr * K0 + gk0;                       \
          else          sp = Af1 + (size_t)a_gr * K1 + (gk0 - K0);                \
          float4 v0 = make_float4(0.f, 0.f, 0.f, 0.f), v1 = v0;                   \
          if (a_ok) { v0 = *(const float4*)sp; v1 = *(const float4*)(sp + 4); }   \
          uint4 hi_, lo_;                                                         \
          cvt8_planes(v0, v1, hi_, lo_);                                          \
          fp16* ap = smem + (st) * STAGE_ELEMS + a_row * A_STRIDE + a_k;          \
          *(uint4*)ap = hi_;                                                      \
          *(uint4*)(ap + A_PLANE_) = lo_;                                         \
        } else {                                                                  \
          int gk0 = kt_ + a_k;                                                    \
          const fp16 *sph, *spl;                                                  \
          if (gk0 < K0) { sph = A0h + (size_t)a_gr * K0 + gk0;                    \
                          spl = A0l + (size_t)a_gr * K0 + gk0; }                  \
          else          { sph = A1h + (size_t)a_gr * K1 + (gk0 - K0);             \
                          spl = A1l + (size_t)a_gr * K1 + (gk0 - K0); }           \
          uint32_t dh = smem_u32 +                                                \
              ((st) * STAGE_ELEMS + a_row * A_STRIDE + a_k) * 2;                  \
          if (ATPR == 2) {                                                        \
              cp16(dh,      sph,     a_ok);                                       \
              cp16(dh + 16, sph + 8, a_ok);                                       \
              cp16(dh + A_PLANE_ * 2,      spl,     a_ok);                        \
              cp16(dh + A_PLANE_ * 2 + 16, spl + 8, a_ok);                        \
          } else {                                                                \
              cp16(dh,                sph, a_ok);                                 \
              cp16(dh + A_PLANE_ * 2, spl, a_ok);                                 \
          }                                                                       \
        }                                                                         \
        { int gk = kt_ + b_k;                                                     \
          const fp16 *wp; int kk2;                                                \
          if (gk < K0) { wp = W0; kk2 = gk; }                                     \
          else         { wp = W1; kk2 = gk - K0; }                                \
          uint32_t dbh = smem_u32 +                                               \
              ((st) * STAGE_ELEMS + 2 * A_PLANE_ + b_k * B_STRIDE + b_n0) * 2;    \
          _Pragma("unroll")                                                       \
          for (int cc = 0; cc < NCP; cc++) {                                      \
              int n0 = bcol + b_n0 + cc * 8;                                      \
              bool ok = (n0 < N);                                                 \
              cp16(dbh + cc * 16, wp + (size_t)kk2 * N + n0, ok);                 \
          }                                                                       \
        }                                                                         \
        asm volatile("cp.async.commit_group;");                                   \
    } while (0)

    LOAD_TILE(0, 0);

    for (int t = 0; t < T; ++t) {
        const int st = t & 1;
        if (t + 1 < T) {
            LOAD_TILE(t + 1, st ^ 1);
            asm volatile("cp.async.wait_group 1;");
        } else {
            asm volatile("cp.async.wait_group 0;");
        }
        __syncthreads();

        const uint32_t base = smem_u32 + st * STAGE_ELEMS * 2;
#pragma unroll
        for (int k16 = 0; k16 < 2; k16++) {
            uint32_t ah[2][4], al[2][4], bh[P][4];
#pragma unroll
            for (int mt = 0; mt < 2; mt++) {
                uint32_t ad = base + (a_lm + mt * 16 * A_STRIDE + k16 * 16) * 2;
                LDMX4(ah[mt], ad);
                LDMX4(al[mt], ad + A_PLANE_ * 2);
            }
#pragma unroll
            for (int p = 0; p < P; p++) {
                uint32_t bd = base + (2 * A_PLANE_ + b_lm + p * 16
                                      + k16 * 16 * B_STRIDE) * 2;
                LDMX4T(bh[p], bd);
            }
#pragma unroll
            for (int mt = 0; mt < 2; mt++)
#pragma unroll
                for (int nt = 0; nt < NT; nt++) {
                    const int p = nt >> 1, q = (nt & 1) * 2;
                    MMA_FP16(acc[mt][nt], al[mt], bh[p][q], bh[p][q + 1]);
                    MMA_FP16(acc[mt][nt], ah[mt], bh[p][q], bh[p][q + 1]);
                }
        }
        __syncthreads();
    }

#pragma unroll
    for (int nt = 0; nt < NT; nt++) {
        const int col = bcol + wn + 8 * nt + 2 * (lane & 3);
        if (col >= N) continue;
        float sc0 = 1.f, sh0 = 0.f, sc1 = 1.f, sh1 = 0.f;
        if (bias) { sh0 = bias[col]; sh1 = bias[col + 1]; }
        if (bng) {
            float s0 = bng[col]     * rsqrtf(bnv[col]     + 1e-5f);
            float s1 = bng[col + 1] * rsqrtf(bnv[col + 1] + 1e-5f);
            sh0 = (sh0 - bnm[col])     * s0 + bnb[col];
            sh1 = (sh1 - bnm[col + 1]) * s1 + bnb[col + 1];
            sc0 = s0; sc1 = s1;
        }
#pragma unroll
        for (int mt = 0; mt < 2; mt++) {
#pragma unroll
            for (int half = 0; half < 2; half++) {
                const int row = brow + wm + 16 * mt + (lane >> 2) + 8 * half;
                if (row >= M) continue;
                const float* c = acc[mt][nt] + 2 * half;
                float v0 = c[0] * sc0 + sh0;
                float v1 = c[1] * sc1 + sh1;
                if (do_relu) { v0 = fmaxf(v0, 0.f); v1 = fmaxf(v1, 0.f); }
                if (Ch) {
                    fp162 hi = __float22half2_rn(make_float2(v0, v1));
                    float2 hf2 = __half22float2(hi);
                    fp162 lo = __float22half2_rn(
                        make_float2(v0 - hf2.x, v1 - hf2.y));
                    *(fp162*)(Ch + (size_t)row * N + col) = hi;
                    *(fp162*)(Cl + (size_t)row * N + col) = lo;
                } else {
                    *(float2*)(Cf + (size_t)row * N + col) = make_float2(v0, v1);
                }
            }
        }
    }
}

// ---------------- merged weight split: all 8 segments, single fp16 plane ------
struct WSeg { const float* src[8]; int beg[9]; };

__global__ void split_weights(WSeg ws, fp16* __restrict__ wh)
{
    int i4 = blockIdx.x * blockDim.x + threadIdx.x;
    int i  = i4 * 4;
    if (i >= ws.beg[8]) return;
    int s = 0;
#pragma unroll
    for (int k = 0; k < 7; k++) s += (i >= ws.beg[k + 1]) ? 1 : 0;
    float4 v = *(const float4*)(ws.src[s] + (i - ws.beg[s]));
    fp162 h0 = __float22half2_rn(make_float2(v.x, v.y));
    fp162 h1 = __float22half2_rn(make_float2(v.z, v.w));
    ((fp162*)wh)[i4 * 2]     = h0;
    ((fp162*)wh)[i4 * 2 + 1] = h1;
}

// ---------------- CSR construction ----------------
__global__ void count_deg(const int* __restrict__ dst, int* __restrict__ counts, int E)
{
    int e = blockIdx.x * blockDim.x + threadIdx.x;
    if (e < E) atomicAdd(&counts[dst[e]], 1);
}

__global__ __launch_bounds__(1024) void scan_counts(
    const int* __restrict__ counts, int* __restrict__ rowptr,
    int* __restrict__ fill, int n)
{
    __shared__ int part[1024];
    const int tid = threadIdx.x;
    const int chunk = (n + 1023) / 1024;
    const int begin = min(tid * chunk, n);
    const int end   = min(begin + chunk, n);
    int s = 0;
    for (int i = begin; i < end; i++) s += counts[i];
    part[tid] = s;
    __syncthreads();
    for (int off = 1; off < 1024; off <<= 1) {
        int v = (tid >= off) ? part[tid - off] : 0;
        __syncthreads();
        part[tid] += v;
        __syncthreads();
    }
    int pre = (tid == 0) ? 0 : part[tid - 1];
    for (int i = begin; i < end; i++) {
        rowptr[i] = pre;
        fill[i]   = pre;
        pre += counts[i];
    }
    if (end == n && begin <= n) rowptr[n] = pre;
}

__global__ void fill_csr(const int* __restrict__ src, const int* __restrict__ dst,
                         int* __restrict__ fill, int* __restrict__ csr, int E)
{
    int e = blockIdx.x * blockDim.x + threadIdx.x;
    if (e < E) {
        int pos = atomicAdd(&fill[dst[e]], 1);
        csr[pos] = src[e];
    }
}

// ---------------- CSR gather mean over fp16 planes (layer-0), 2-edge unroll ---
__global__ void gather_mean(const fp16* __restrict__ hh, const fp16* __restrict__ hl,
                            const int* __restrict__ csr, const int* __restrict__ rowptr,
                            fp16* __restrict__ oh, fp16* __restrict__ ol,
                            int Nn, int D)
{
    const int warp = (blockIdx.x * blockDim.x + threadIdx.x) >> 5;
    const int lane = threadIdx.x & 31;
    if (warp >= Nn) return;
    const int e0 = rowptr[warp];
    const int e1 = rowptr[warp + 1];
    const float inv = 1.f / (float)max(e1 - e0, 1);
    const int nseg = D >> 7;
    float acc[8];
#pragma unroll
    for (int i = 0; i < 8; i++) acc[i] = 0.f;

    int e = e0;
    for (; e + 1 < e1; e += 2) {
        const int s0 = csr[e];
        const int s1 = csr[e + 1];
        const fp16* rh0 = hh + (size_t)s0 * D + lane * 4;
        const fp16* rl0 = hl + (size_t)s0 * D + lane * 4;
        const fp16* rh1 = hh + (size_t)s1 * D + lane * 4;
        const fp16* rl1 = hl + (size_t)s1 * D + lane * 4;
#pragma unroll
        for (int g = 0; g < 2; g++) {
            if (g < nseg) {
                uint2 vh0 = *(const uint2*)(rh0 + g * 128);
                uint2 vl0 = *(const uint2*)(rl0 + g * 128);
                uint2 vh1 = *(const uint2*)(rh1 + g * 128);
                uint2 vl1 = *(const uint2*)(rl1 + g * 128);
                float2 a0 = __half22float2(*(const fp162*)&vh0.x);
                float2 a1 = __half22float2(*(const fp162*)&vh0.y);
                float2 b0 = __half22float2(*(const fp162*)&vl0.x);
                float2 b1 = __half22float2(*(const fp162*)&vl0.y);
                float2 c0 = __half22float2(*(const fp162*)&vh1.x);
                float2 c1 = __half22float2(*(const fp162*)&vh1.y);
                float2 d0 = __half22float2(*(const fp162*)&vl1.x);
                float2 d1 = __half22float2(*(const fp162*)&vl1.y);
                acc[g * 4 + 0] += (a0.x + b0.x) + (c0.x + d0.x);
                acc[g * 4 + 1] += (a0.y + b0.y) + (c0.y + d0.y);
                acc[g * 4 + 2] += (a1.x + b1.x) + (c1.x + d1.x);
                acc[g * 4 + 3] += (a1.y + b1.y) + (c1.y + d1.y);
            }
        }
    }
    if (e < e1) {
        const int s = csr[e];
        const fp16* rh = hh + (size_t)s * D + lane * 4;
        const fp16* rl = hl + (size_t)s * D + lane * 4;
#pragma unroll
        for (int g = 0; g < 2; g++) {
            if (g < nseg) {
                uint2 vh = *(const uint2*)(rh + g * 128);
                uint2 vl = *(const uint2*)(rl + g * 128);
                float2 a0 = __half22float2(*(const fp162*)&vh.x);
                float2 a1 = __half22float2(*(const fp162*)&vh.y);
                float2 b0 = __half22float2(*(const fp162*)&vl.x);
                float2 b1 = __half22float2(*(const fp162*)&vl.y);
                acc[g * 4 + 0] += a0.x + b0.x;
                acc[g * 4 + 1] += a0.y + b0.y;
                acc[g * 4 + 2] += a1.x + b1.x;
                acc[g * 4 + 3] += a1.y + b1.y;
            }
        }
    }

#pragma unroll
    for (int g = 0; g < 2; g++) {
        if (g < nseg) {
            float v0 = acc[g * 4 + 0] * inv;
            float v1 = acc[g * 4 + 1] * inv;
            float v2 = acc[g * 4 + 2] * inv;
            float v3 = acc[g * 4 + 3] * inv;
            fp162 h0 = __float22half2_rn(make_float2(v0, v1));
            fp162 h1 = __float22half2_rn(make_float2(v2, v3));
            float2 f0 = __half22float2(h0);
            float2 f1 = __half22float2(h1);
            fp162 l0 = __float22half2_rn(make_float2(v0 - f0.x, v1 - f0.y));
            fp162 l1 = __float22half2_rn(make_float2(v2 - f1.x, v3 - f1.y));
            uint2 wh_, wl_;
            wh_.x = *(uint32_t*)&h0; wh_.y = *(uint32_t*)&h1;
            wl_.x = *(uint32_t*)&l0; wl_.y = *(uint32_t*)&l1;
            *(uint2*)(oh + (size_t)warp * D + g * 128 + lane * 4) = wh_;
            *(uint2*)(ol + (size_t)warp * D + g * 128 + lane * 4) = wl_;
        }
    }
}

// ---------------- layer-1 fused gather (2-edge unroll): mean(G1)+S1+bn+relu ---
__global__ void gather_fuse_bn(const float* __restrict__ S1,
                               const float* __restrict__ G1,
                               const int* __restrict__ csr,
                               const int* __restrict__ rowptr,
                               const float* __restrict__ bias,
                               const float* __restrict__ bng,
                               const float* __restrict__ bnb,
                               const float* __restrict__ bnm,
                               const float* __restrict__ bnv,
                               fp16* __restrict__ oh, fp16* __restrict__ ol,
                               int Nn)
{
    const int warp = (blockIdx.x * blockDim.x + threadIdx.x) >> 5;
    const int lane = threadIdx.x & 31;
    if (warp >= Nn) return;
    const int e0 = rowptr[warp];
    const int e1 = rowptr[warp + 1];
    const float inv = 1.f / (float)max(e1 - e0, 1);
    const int col = lane * 4;

    float acc0 = 0.f, acc1 = 0.f, acc2 = 0.f, acc3 = 0.f;
    int e = e0;
    for (; e + 1 < e1; e += 2) {
        const float4 v0 = *(const float4*)(G1 + (size_t)csr[e] * 128 + col);
        const float4 v1 = *(const float4*)(G1 + (size_t)csr[e + 1] * 128 + col);
        acc0 += v0.x + v1.x; acc1 += v0.y + v1.y;
        acc2 += v0.z + v1.z; acc3 += v0.w + v1.w;
    }
    if (e < e1) {
        const float4 v = *(const float4*)(G1 + (size_t)csr[e] * 128 + col);
        acc0 += v.x; acc1 += v.y; acc2 += v.z; acc3 += v.w;
    }
    const float4 s = *(const float4*)(S1 + (size_t)warp * 128 + col);

    float vo[4];
    const float* sp = &s.x;
    float ac[4] = {acc0, acc1, acc2, acc3};
#pragma unroll
    for (int j = 0; j < 4; j++) {
        const float sc = bng[col + j] * rsqrtf(bnv[col + j] + 1e-5f);
        const float sh = (bias[col + j] - bnm[col + j]) * sc + bnb[col + j];
        float x = (sp[j] + ac[j] * inv) * sc + sh;
        vo[j] = fmaxf(x, 0.f);
    }

    fp162 h0 = __float22half2_rn(make_float2(vo[0], vo[1]));
    fp162 h1 = __float22half2_rn(make_float2(vo[2], vo[3]));
    float2 f0 = __half22float2(h0);
    float2 f1 = __half22float2(h1);
    fp162 l0 = __float22half2_rn(make_float2(vo[0] - f0.x, vo[1] - f0.y));
    fp162 l1 = __float22half2_rn(make_float2(vo[2] - f1.x, vo[3] - f1.y));
    uint2 wh_, wl_;
    wh_.x = *(uint32_t*)&h0; wh_.y = *(uint32_t*)&h1;
    wl_.x = *(uint32_t*)&l0; wl_.y = *(uint32_t*)&l1;
    *(uint2*)(oh + (size_t)warp * 128 + col) = wh_;
    *(uint2*)(ol + (size_t)warp * 128 + col) = wl_;
}

// ---------------- launch helpers ----------------
static inline void launch_gemm(
    const fp16* A0h, const fp16* A0l, int K0,
    const fp16* A1h, const fp16* A1l, int K1,
    const fp16* W0, const fp16* W1,
    int M, int N,
    const float* bias, const float* bng, const float* bnb,
    const float* bnm, const float* bnv,
    int do_relu, float* Cf, fp16* Ch, fp16* Cl)
{
    if (N >= 128) {
        constexpr int BM_ = 64, BN_ = 128;
        constexpr int SMEM = 2 * (2 * BM_ * A_STRIDE + BK * (BN_ + 8)) * 2;
        dim3 grid(N / BN_, (M + BM_ - 1) / BM_);
        gemm_fp16x2<BM_, BN_, 0><<<grid, 256, SMEM>>>(
            A0h, A0l, K0, A1h, A1l, K1, nullptr, nullptr,
            W0, W1, M, N,
            bias, bng, bnb, bnm, bnv, do_relu, Cf, Ch, Cl);
    } else {
        constexpr int BM_ = 128, BN_ = 64;
        constexpr int SMEM = 2 * (2 * BM_ * A_STRIDE + BK * (BN_ + 8)) * 2;
        dim3 grid((N + BN_ - 1) / BN_, (M + BM_ - 1) / BM_);
        gemm_fp16x2<BM_, BN_, 0><<<grid, 256, SMEM>>>(
            A0h, A0l, K0, A1h, A1l, K1, nullptr, nullptr,
            W0, W1, M, N,
            bias, bng, bnb, bnm, bnv, do_relu, Cf, Ch, Cl);
    }
}

// enc GEMM: A read directly as fp32 (split fused into loader). N must be 128.
static inline void launch_gemm_f32(
    const float* Af0, int K0, const float* Af1, int K1,
    const fp16* W0, const fp16* W1,
    int M, int N, const float* bias, int do_relu, fp16* Ch, fp16* Cl)
{
    constexpr int BM_ = 64, BN_ = 128;
    constexpr int SMEM = 2 * (2 * BM_ * A_STRIDE + BK * (BN_ + 8)) * 2;
    dim3 grid(N / BN_, (M + BM_ - 1) / BM_);
    gemm_fp16x2<BM_, BN_, 1><<<grid, 256, SMEM>>>(
        nullptr, nullptr, K0, nullptr, nullptr, K1, Af0, Af1,
        W0, W1, M, N,
        bias, nullptr, nullptr, nullptr, nullptr, do_relu, nullptr, Ch, Cl);
}

extern "C" void kernel_launch(void* const* d_in, const int* in_sizes, int n_in,
                              void* d_out, int out_size)
{
    const float* structural = (const float*)d_in[0];
    const float* multimodal = (const float*)d_in[1];
    const int*   src        = (const int*)  d_in[2];
    const int*   dst        = (const int*)  d_in[3];
    const float* enc_w      = (const float*)d_in[4];
    const float* enc_b      = (const float*)d_in[5];
    const float* sage0_ws   = (const float*)d_in[6];
    const float* sage0_wn   = (const float*)d_in[7];
    const float* sage0_b    = (const float*)d_in[8];
    const float* bn0_g      = (const float*)d_in[9];
    const float* bn0_b      = (const float*)d_in[10];
    const float* bn0_m      = (const float*)d_in[11];
    const float* bn0_v      = (const float*)d_in[12];
    const float* sage1_ws   = (const float*)d_in[13];
    const float* sage1_wn   = (const float*)d_in[14];
    const float* sage1_b    = (const float*)d_in[15];
    const float* bn1_g      = (const float*)d_in[16];
    const float* bn1_b      = (const float*)d_in[17];
    const float* bn1_m      = (const float*)d_in[18];
    const float* bn1_v      = (const float*)d_in[19];
    const float* rel_w      = (const float*)d_in[20];
    const float* rel_b      = (const float*)d_in[21];
    const float* cls_w1     = (const float*)d_in[22];
    const float* cls_b1     = (const float*)d_in[23];
    const float* cls_w2     = (const float*)d_in[24];
    const float* cls_b2     = (const float*)d_in[25];
    float* out = (float*)d_out;

#define SYMADDR(var, sym) void* p_##var; cudaGetSymbolAddress(&p_##var, sym);
    SYMADDR(h0h, g_h0h) SYMADDR(h0l, g_h0l) SYMADDR(a0h, g_a0h) SYMADDR(a0l, g_a0l)
    SYMADDR(h1h, g_h1h) SYMADDR(h1l, g_h1l)
    SYMADDR(h2h, g_h2h) SYMADDR(h2l, g_h2l) SYMADDR(hfh, g_hfh) SYMADDR(hfl, g_hfl)
    SYMADDR(c1h, g_c1h) SYMADDR(c1l, g_c1l)
    SYMADDR(s1f, g_s1f) SYMADDR(g1f, g_g1f)
    SYMADDR(wh, g_wh)
    SYMADDR(counts, g_counts) SYMADDR(rowptr, g_rowptr)
    SYMADDR(fill, g_fill) SYMADDR(csr, g_csr)
#undef SYMADDR

    fp16* h0h = (fp16*)p_h0h; fp16* h0l = (fp16*)p_h0l;
    fp16* a0h = (fp16*)p_a0h; fp16* a0l = (fp16*)p_a0l;
    fp16* h1h = (fp16*)p_h1h; fp16* h1l = (fp16*)p_h1l;
    fp16* h2h = (fp16*)p_h2h; fp16* h2l = (fp16*)p_h2l;
    fp16* hfh = (fp16*)p_hfh; fp16* hfl = (fp16*)p_hfl;
    fp16* c1h = (fp16*)p_c1h; fp16* c1l = (fp16*)p_c1l;
    float* s1f = (float*)p_s1f; float* g1f = (float*)p_g1f;
    fp16* wh = (fp16*)p_wh;
    int* counts = (int*)p_counts; int* rowptr = (int*)p_rowptr;
    int* fill   = (int*)p_fill;   int* csr    = (int*)p_csr;

    {
        constexpr int SMEM_A = 2 * (2 * 64 * A_STRIDE + BK * (128 + 8)) * 2;
        constexpr int SMEM_B = 2 * (2 * 128 * A_STRIDE + BK * (64 + 8)) * 2;
        cudaFuncSetAttribute((const void*)gemm_fp16x2<64, 128, 0>,
                             cudaFuncAttributeMaxDynamicSharedMemorySize, SMEM_A);
        cudaFuncSetAttribute((const void*)gemm_fp16x2<64, 128, 1>,
                             cudaFuncAttributeMaxDynamicSharedMemorySize, SMEM_A);
        cudaFuncSetAttribute((const void*)gemm_fp16x2<128, 64, 0>,
                             cudaFuncAttributeMaxDynamicSharedMemorySize, SMEM_B);
    }

    const int M = N_NODES, E = N_EDGES;

    // ---- CSR build ----
    cudaMemsetAsync(counts, 0, N_NODES * sizeof(int), 0);
    count_deg<<<(E + 255) / 256, 256>>>(dst, counts, E);
    scan_counts<<<1, 1024>>>(counts, rowptr, fill, M);
    fill_csr<<<(E + 255) / 256, 256>>>(src, dst, fill, csr, E);

    // ---- split all weights to single fp16 plane (1 launch) ----
    {
        WSeg ws;
        ws.src[0] = enc_w;    ws.beg[0] = WOFF_ENC;
        ws.src[1] = sage0_ws; ws.beg[1] = WOFF_S0S;
        ws.src[2] = sage0_wn; ws.beg[2] = WOFF_S0N;
        ws.src[3] = sage1_ws; ws.beg[3] = WOFF_S1S;
        ws.src[4] = sage1_wn; ws.beg[4] = WOFF_S1N;
        ws.src[5] = rel_w;    ws.beg[5] = WOFF_REL;
        ws.src[6] = cls_w1;   ws.beg[6] = WOFF_C1;
        ws.src[7] = cls_w2;   ws.beg[7] = WOFF_C2;
        ws.beg[8] = WOFF_END;
        int w4 = WOFF_END / 4;
        split_weights<<<(w4 + 255) / 256, 256>>>(ws, wh);
    }

    // h0 = relu([structural|multimodal] @ enc_w + enc_b)  (fp32 A path)
    launch_gemm_f32(structural, 128, multimodal, 384,
                    wh + WOFF_ENC, wh + WOFF_ENC + 128 * 128,
                    M, 128, enc_b, 1, h0h, h0l);

    // agg0 = mean h0  (gather over planes)
    gather_mean<<<(M * 32 + 255) / 256, 256>>>(h0h, h0l, csr, rowptr,
                                               a0h, a0l, M, 128);

    // h1 = relu(bn0(h0 @ ws0 + agg0 @ wn0 + b0))
    launch_gemm(h0h, h0l, 128, a0h, a0l, 128,
                wh + WOFF_S0S, wh + WOFF_S0N,
                M, 256, sage0_b, bn0_g, bn0_b, bn0_m, bn0_v, 1,
                nullptr, h1h, h1l);

    // ---- sage1, commuted: mean(h1) @ Wn1 == mean(h1 @ Wn1) ----
    launch_gemm(h1h, h1l, 256, h1h, h1l, 0,
                wh + WOFF_S1N, wh + WOFF_S1N,
                M, 128, nullptr, nullptr, nullptr, nullptr, nullptr, 0,
                g1f, nullptr, nullptr);
    launch_gemm(h1h, h1l, 256, h1h, h1l, 0,
                wh + WOFF_S1S, wh + WOFF_S1S,
                M, 128, nullptr, nullptr, nullptr, nullptr, nullptr, 0,
                s1f, nullptr, nullptr);
    gather_fuse_bn<<<(M * 32 + 255) / 256, 256>>>(
        s1f, g1f, csr, rowptr, sage1_b, bn1_g, bn1_b, bn1_m, bn1_v,
        h2h, h2l, M);

    // hf = relu([h0|h2] @ rel_w + rel_b)
    launch_gemm(h0h, h0l, 128, h2h, h2l, 128,
                wh + WOFF_REL, wh + WOFF_REL + 128 * 128,
                M, 128, rel_b, nullptr, nullptr, nullptr, nullptr, 1,
                nullptr, hfh, hfl);

    // c1 = relu(hf @ cls_w1 + cls_b1)
    launch_gemm(hfh, hfl, 128, hfh, hfl, 0,
                wh + WOFF_C1, wh + WOFF_C1,
                M, 64, cls_b1, nullptr, nullptr, nullptr, nullptr, 1,
                nullptr, c1h, c1l);

    // out = c1 @ cls_w2 + cls_b2   (fp32)
    launch_gemm(c1h, c1l, 64, c1h, c1l, 0,
                wh + WOFF_C2, wh + WOFF_C2,
                M, 32, cls_b2, nullptr, nullptr, nullptr, nullptr, 0,
                out, nullptr, nullptr);
}

// round 15
// speedup vs baseline: 1.5068x; 1.0354x over previous
#include <cuda_runtime.h>
#include <cuda_fp16.h>
#include <math.h>
#include <stdint.h>

#define N_NODES 100000
#define N_EDGES 800000

typedef __half  fp16;
typedef __half2 fp162;

// ---------------- scratch (device globals; no allocs allowed) ----------------
__device__ fp16 g_h0h[(size_t)N_NODES * 128], g_h0l[(size_t)N_NODES * 128];
__device__ fp16 g_a0h[(size_t)N_NODES * 128], g_a0l[(size_t)N_NODES * 128];
__device__ fp16 g_h1h[(size_t)N_NODES * 256], g_h1l[(size_t)N_NODES * 256];
__device__ fp16 g_h2h[(size_t)N_NODES * 128], g_h2l[(size_t)N_NODES * 128];
__device__ fp16 g_hfh[(size_t)N_NODES * 128], g_hfl[(size_t)N_NODES * 128];
__device__ fp16 g_c1h[(size_t)N_NODES * 64],  g_c1l[(size_t)N_NODES * 64];
__device__ float g_s1f[(size_t)N_NODES * 128];
__device__ float g_g1f[(size_t)N_NODES * 128];
__device__ fp16 g_wh[262144];
__device__ int g_counts[N_NODES];
__device__ int g_rowptr[N_NODES + 1];
__device__ int g_fill  [N_NODES];
__device__ int g_csr   [N_EDGES];

#define WOFF_ENC 0
#define WOFF_S0S 65536
#define WOFF_S0N 98304
#define WOFF_S1S 131072
#define WOFF_S1N 163840
#define WOFF_REL 196608
#define WOFF_C1  229376
#define WOFF_C2  237568
#define WOFF_END 239616

#define BK 32
#define A_STRIDE 40

__device__ __forceinline__ void cp16(uint32_t dst, const void* src, bool pred) {
    asm volatile("cp.async.cg.shared.global [%0], [%1], 16, %2;"
                 :: "r"(dst), "l"(src), "r"(pred ? 16 : 0));
}

#define LDMX4(r, addr)                                                          \
    asm volatile("ldmatrix.sync.aligned.m8n8.x4.shared.b16 {%0,%1,%2,%3},[%4];" \
                 : "=r"((r)[0]), "=r"((r)[1]), "=r"((r)[2]), "=r"((r)[3])       \
                 : "r"(addr))

#define LDMX4T(r, addr)                                                         \
    asm volatile("ldmatrix.sync.aligned.m8n8.x4.trans.shared.b16 "              \
                 "{%0,%1,%2,%3},[%4];"                                          \
                 : "=r"((r)[0]), "=r"((r)[1]), "=r"((r)[2]), "=r"((r)[3])       \
                 : "r"(addr))

#define MMA_FP16(acc, a, b0, b1)                                                \
    asm volatile(                                                               \
        "mma.sync.aligned.m16n8k16.row.col.f32.f16.f16.f32 "                    \
        "{%0,%1,%2,%3},{%4,%5,%6,%7},{%8,%9},{%0,%1,%2,%3};"                    \
        : "+f"((acc)[0]), "+f"((acc)[1]), "+f"((acc)[2]), "+f"((acc)[3])        \
        : "r"((a)[0]), "r"((a)[1]), "r"((a)[2]), "r"((a)[3]),                   \
          "r"(b0), "r"(b1))

__device__ __forceinline__ void cvt8_planes(float4 v0, float4 v1,
                                            uint4& hi, uint4& lo)
{
    fp162 h0 = __float22half2_rn(make_float2(v0.x, v0.y));
    fp162 h1 = __float22half2_rn(make_float2(v0.z, v0.w));
    fp162 h2 = __float22half2_rn(make_float2(v1.x, v1.y));
    fp162 h3 = __float22half2_rn(make_float2(v1.z, v1.w));
    float2 f0 = __half22float2(h0);
    float2 f1 = __half22float2(h1);
    float2 f2 = __half22float2(h2);
    float2 f3 = __half22float2(h3);
    fp162 l0 = __float22half2_rn(make_float2(v0.x - f0.x, v0.y - f0.y));
    fp162 l1 = __float22half2_rn(make_float2(v0.z - f1.x, v0.w - f1.y));
    fp162 l2 = __float22half2_rn(make_float2(v1.x - f2.x, v1.y - f2.y));
    fp162 l3 = __float22half2_rn(make_float2(v1.z - f3.x, v1.w - f3.y));
    hi.x = *(uint32_t*)&h0; hi.y = *(uint32_t*)&h1;
    hi.z = *(uint32_t*)&h2; hi.w = *(uint32_t*)&h3;
    lo.x = *(uint32_t*)&l0; lo.y = *(uint32_t*)&l1;
    lo.z = *(uint32_t*)&l2; lo.w = *(uint32_t*)&l3;
}

// ---------------- fp16x2 tensor-core GEMM (A hi/lo split, B single) ----------
template<int BM_, int BN_, int AF32>
__global__ __launch_bounds__(256, 3) void gemm_fp16x2(
    const fp16* __restrict__ A0h, const fp16* __restrict__ A0l, int K0,
    const fp16* __restrict__ A1h, const fp16* __restrict__ A1l, int K1,
    const float* __restrict__ Af0, const float* __restrict__ Af1,
    const fp16* __restrict__ W0, const fp16* __restrict__ W1,
    int M, int N,
    const float* __restrict__ bias,
    const float* __restrict__ bng, const float* __restrict__ bnb,
    const float* __restrict__ bnm, const float* __restrict__ bnv,
    int do_relu,
    float* __restrict__ Cf, fp16* __restrict__ Ch, fp16* __restrict__ Cl)
{
    constexpr int A_PLANE_ = BM_ * A_STRIDE;
    constexpr int B_STRIDE = BN_ + 8;
    constexpr int B_PLANE  = BK * B_STRIDE;
    constexpr int STAGE_ELEMS = 2 * A_PLANE_ + B_PLANE;
    constexpr int WROWS  = BM_ / 32;
    constexpr int WARP_N = BN_ * WROWS / 8;
    constexpr int NT = WARP_N / 8;
    constexpr int P  = WARP_N / 16;
    constexpr int NCP = BN_ / 64;

    extern __shared__ fp16 smem[];
    const uint32_t smem_u32 = (uint32_t)__cvta_generic_to_shared(smem);

    const int tid  = threadIdx.x;
    const int lane = tid & 31;
    const int wid  = tid >> 5;
    const int wm   = (wid % WROWS) * 32;
    const int wn   = (wid / WROWS) * WARP_N;
    const int brow = blockIdx.y * BM_;
    const int bcol = blockIdx.x * BN_;
    const int K = K0 + K1;
    const int T = K / BK;

    constexpr int ATPR = 256 / BM_;
    const int a_row = tid / ATPR;
    const int a_k   = (tid % ATPR) * (32 / ATPR);
    const int a_gr  = brow + a_row;
    const bool a_ok = (a_gr < M);
    const int b_k  = tid >> 3;
    const int b_n0 = (tid & 7) * (BN_ / 8);

    const int a_lm = (wm + (lane & 15)) * A_STRIDE + (lane >> 4) * 8;
    const int b_lm = ((lane & 7) + ((lane >> 3) & 1) * 8) * B_STRIDE
                     + wn + (lane >> 4) * 8;

    float acc[2][NT][4];
#pragma unroll
    for (int mt = 0; mt < 2; mt++)
#pragma unroll
        for (int nt = 0; nt < NT; nt++)
#pragma unroll
            for (int i = 0; i < 4; i++) acc[mt][nt][i] = 0.f;

// B-tile cp.async loads for tile t into stage stv (no commit)
#define B_LOAD(t, stv) do {                                                       \
        int gk = (t) * BK + b_k;                                                  \
        const fp16 *wp; int kk2;                                                  \
        if (gk < K0) { wp = W0; kk2 = gk; }                                       \
        else         { wp = W1; kk2 = gk - K0; }                                  \
        uint32_t dbh = smem_u32 +                                                 \
            ((stv) * STAGE_ELEMS + 2 * A_PLANE_ + b_k * B_STRIDE + b_n0) * 2;     \
        _Pragma("unroll")                                                         \
        for (int cc = 0; cc < NCP; cc++) {                                        \
            int n0 = bcol + b_n0 + cc * 8;                                        \
            bool ok = (n0 < N);                                                   \
            cp16(dbh + cc * 16, wp + (size_t)kk2 * N + n0, ok);                   \
        }                                                                         \
    } while (0)

// legacy fp16-plane A load + B for tile t, stage stv (with commit)
#define LOAD_TILE(t, stv) do {                                                    \
        int gk0 = (t) * BK + a_k;                                                 \
        const fp16 *sph, *spl;                                                    \
        if (gk0 < K0) { sph = A0h + (size_t)a_gr * K0 + gk0;                      \
                        spl = A0l + (size_t)a_gr * K0 + gk0; }                    \
        else          { sph = A1h + (size_t)a_gr * K1 + (gk0 - K0);               \
                        spl = A1l + (size_t)a_gr * K1 + (gk0 - K0); }             \
        uint32_t dh = smem_u32 +                                                  \
            ((stv) * STAGE_ELEMS + a_row * A_STRIDE + a_k) * 2;                   \
        if (ATPR == 2) {                                                          \
            cp16(dh,      sph,     a_ok);                                         \
            cp16(dh + 16, sph + 8, a_ok);                                         \
            cp16(dh + A_PLANE_ * 2,      spl,     a_ok);                          \
            cp16(dh + A_PLANE_ * 2 + 16, spl + 8, a_ok);                          \
        } else {                                                                  \
            cp16(dh,                sph, a_ok);                                   \
            cp16(dh + A_PLANE_ * 2, spl, a_ok);                                   \
        }                                                                         \
        B_LOAD(t, stv);                                                           \
        asm volatile("cp.async.commit_group;");                                   \
    } while (0)

// fp32 A register load for tile t (AF32 path; ATPR==4 -> 8 floats)
#define A_LDG(t) do {                                                             \
        int gk0 = (t) * BK + a_k;                                                 \
        const float* sp;                                                          \
        if (gk0 < K0) sp = Af0 + (size_t)a_gr * K0 + gk0;                         \
        else          sp = Af1 + (size_t)a_gr * K1 + (gk0 - K0);                  \
        if (a_ok) { cv0 = *(const float4*)sp; cv1 = *(const float4*)(sp + 4); }   \
        else { cv0 = make_float4(0.f,0.f,0.f,0.f); cv1 = cv0; }                   \
    } while (0)

// convert regs -> fp16 planes -> STS into stage stv (AF32 path)
#define A_STS(stv) do {                                                           \
        uint4 hi_, lo_;                                                           \
        cvt8_planes(cv0, cv1, hi_, lo_);                                          \
        fp16* ap = smem + (stv) * STAGE_ELEMS + a_row * A_STRIDE + a_k;           \
        *(uint4*)ap = hi_;                                                        \
        *(uint4*)(ap + A_PLANE_) = lo_;                                           \
    } while (0)

#define MMA_STEP(stv) do {                                                        \
        const uint32_t base = smem_u32 + (stv) * STAGE_ELEMS * 2;                 \
        _Pragma("unroll")                                                         \
        for (int k16 = 0; k16 < 2; k16++) {                                       \
            uint32_t ah[2][4], al[2][4], bh[P][4];                                \
            _Pragma("unroll")                                                     \
            for (int mt = 0; mt < 2; mt++) {                                      \
                uint32_t ad = base + (a_lm + mt * 16 * A_STRIDE + k16 * 16) * 2;  \
                LDMX4(ah[mt], ad);                                                \
                LDMX4(al[mt], ad + A_PLANE_ * 2);                                 \
            }                                                                     \
            _Pragma("unroll")                                                     \
            for (int p = 0; p < P; p++) {                                         \
                uint32_t bd = base + (2 * A_PLANE_ + b_lm + p * 16                \
                                      + k16 * 16 * B_STRIDE) * 2;                 \
                LDMX4T(bh[p], bd);                                                \
            }                                                                     \
            _Pragma("unroll")                                                     \
            for (int mt = 0; mt < 2; mt++)                                        \
                _Pragma("unroll")                                                 \
                for (int nt = 0; nt < NT; nt++) {                                 \
                    const int p = nt >> 1, q = (nt & 1) * 2;                      \
                    MMA_FP16(acc[mt][nt], al[mt], bh[p][q], bh[p][q + 1]);        \
                    MMA_FP16(acc[mt][nt], ah[mt], bh[p][q], bh[p][q + 1]);        \
                }                                                                 \
        }                                                                         \
    } while (0)

    if (AF32) {
        // software-pipelined fp32 A path: LDG(t+2) hidden behind MMAs(t)
        float4 cv0, cv1;
        A_LDG(0);
        A_STS(0);
        B_LOAD(0, 0);
        asm volatile("cp.async.commit_group;");
        A_LDG(1);
        B_LOAD(1, 1);
        asm volatile("cp.async.commit_group;");

        for (int t = 0; t < T; ++t) {
            const int st = t & 1;
            if (t + 1 < T) {
                asm volatile("cp.async.wait_group 1;");
            } else {
                asm volatile("cp.async.wait_group 0;");
            }
            __syncthreads();
            MMA_STEP(st);
            __syncthreads();
            if (t + 1 < T) {
                A_STS(st ^ 1);            // tile t+1 from regs
                if (t + 2 < T) {
                    A_LDG(t + 2);
                    B_LOAD(t + 2, st);
                    asm volatile("cp.async.commit_group;");
                }
            }
        }
    } else {
        LOAD_TILE(0, 0);
        for (int t = 0; t < T; ++t) {
            const int st = t & 1;
            if (t + 1 < T) {
                LOAD_TILE(t + 1, st ^ 1);
                asm volatile("cp.async.wait_group 1;");
            } else {
                asm volatile("cp.async.wait_group 0;");
            }
            __syncthreads();
            MMA_STEP(st);
            __syncthreads();
        }
    }

#pragma unroll
    for (int nt = 0; nt < NT; nt++) {
        const int col = bcol + wn + 8 * nt + 2 * (lane & 3);
        if (col >= N) continue;
        float sc0 = 1.f, sh0 = 0.f, sc1 = 1.f, sh1 = 0.f;
        if (bias) { sh0 = bias[col]; sh1 = bias[col + 1]; }
        if (bng) {
            float s0 = bng[col]     * rsqrtf(bnv[col]     + 1e-5f);
            float s1 = bng[col + 1] * rsqrtf(bnv[col + 1] + 1e-5f);
            sh0 = (sh0 - bnm[col])     * s0 + bnb[col];
            sh1 = (sh1 - bnm[col + 1]) * s1 + bnb[col + 1];
            sc0 = s0; sc1 = s1;
        }
#pragma unroll
        for (int mt = 0; mt < 2; mt++) {
#pragma unroll
            for (int half = 0; half < 2; half++) {
                const int row = brow + wm + 16 * mt + (lane >> 2) + 8 * half;
                if (row >= M) continue;
                const float* c = acc[mt][nt] + 2 * half;
                float v0 = c[0] * sc0 + sh0;
                float v1 = c[1] * sc1 + sh1;
                if (do_relu) { v0 = fmaxf(v0, 0.f); v1 = fmaxf(v1, 0.f); }
                if (Ch) {
                    fp162 hi = __float22half2_rn(make_float2(v0, v1));
                    float2 hf2 = __half22float2(hi);
                    fp162 lo = __float22half2_rn(
                        make_float2(v0 - hf2.x, v1 - hf2.y));
                    *(fp162*)(Ch + (size_t)row * N + col) = hi;
                    *(fp162*)(Cl + (size_t)row * N + col) = lo;
                } else {
                    *(float2*)(Cf + (size_t)row * N + col) = make_float2(v0, v1);
                }
            }
        }
    }
}

// ---------------- merged weight split ----------------
struct WSeg { const float* src[8]; int beg[9]; };

__global__ void split_weights(WSeg ws, fp16* __restrict__ wh)
{
    int i4 = blockIdx.x * blockDim.x + threadIdx.x;
    int i  = i4 * 4;
    if (i >= ws.beg[8]) return;
    int s = 0;
#pragma unroll
    for (int k = 0; k < 7; k++) s += (i >= ws.beg[k + 1]) ? 1 : 0;
    float4 v = *(const float4*)(ws.src[s] + (i - ws.beg[s]));
    fp162 h0 = __float22half2_rn(make_float2(v.x, v.y));
    fp162 h1 = __float22half2_rn(make_float2(v.z, v.w));
    ((fp162*)wh)[i4 * 2]     = h0;
    ((fp162*)wh)[i4 * 2 + 1] = h1;
}

// ---------------- CSR construction ----------------
__global__ void count_deg(const int* __restrict__ dst, int* __restrict__ counts, int E)
{
    int e = blockIdx.x * blockDim.x + threadIdx.x;
    if (e < E) atomicAdd(&counts[dst[e]], 1);
}

__global__ __launch_bounds__(1024) void scan_counts(
    const int* __restrict__ counts, int* __restrict__ rowptr,
    int* __restrict__ fill, int n)
{
    __shared__ int part[1024];
    const int tid = threadIdx.x;
    const int chunk = (n + 1023) / 1024;
    const int begin = min(tid * chunk, n);
    const int end   = min(begin + chunk, n);
    int s = 0;
    for (int i = begin; i < end; i++) s += counts[i];
    part[tid] = s;
    __syncthreads();
    for (int off = 1; off < 1024; off <<= 1) {
        int v = (tid >= off) ? part[tid - off] : 0;
        __syncthreads();
        part[tid] += v;
        __syncthreads();
    }
    int pre = (tid == 0) ? 0 : part[tid - 1];
    for (int i = begin; i < end; i++) {
        rowptr[i] = pre;
        fill[i]   = pre;
        pre += counts[i];
    }
    if (end == n && begin <= n) rowptr[n] = pre;
}

__global__ void fill_csr(const int* __restrict__ src, const int* __restrict__ dst,
                         int* __restrict__ fill, int* __restrict__ csr, int E)
{
    int e = blockIdx.x * blockDim.x + threadIdx.x;
    if (e < E) {
        int pos = atomicAdd(&fill[dst[e]], 1);
        csr[pos] = src[e];
    }
}

// ---------------- CSR gather mean over fp16 planes (D=128), 4-edge unroll -----
__device__ __forceinline__ void acc_row(const fp16* hh, const fp16* hl,
                                        int s, int off,
                                        float& a0, float& a1, float& a2, float& a3)
{
    uint2 vh = *(const uint2*)(hh + (size_t)s * 128 + off);
    uint2 vl = *(const uint2*)(hl + (size_t)s * 128 + off);
    float2 p0 = __half22float2(*(const fp162*)&vh.x);
    float2 p1 = __half22float2(*(const fp162*)&vh.y);
    float2 q0 = __half22float2(*(const fp162*)&vl.x);
    float2 q1 = __half22float2(*(const fp162*)&vl.y);
    a0 += p0.x + q0.x;
    a1 += p0.y + q0.y;
    a2 += p1.x + q1.x;
    a3 += p1.y + q1.y;
}

__global__ void gather_mean(const fp16* __restrict__ hh, const fp16* __restrict__ hl,
                            const int* __restrict__ csr, const int* __restrict__ rowptr,
                            fp16* __restrict__ oh, fp16* __restrict__ ol, int Nn)
{
    const int warp = (blockIdx.x * blockDim.x + threadIdx.x) >> 5;
    const int lane = threadIdx.x & 31;
    if (warp >= Nn) return;
    const int e0 = rowptr[warp];
    const int e1 = rowptr[warp + 1];
    const float inv = 1.f / (float)max(e1 - e0, 1);
    const int off = lane * 4;

    float a0 = 0.f, a1 = 0.f, a2 = 0.f, a3 = 0.f;
    int e = e0;
    for (; e + 3 < e1; e += 4) {
        int s0 = csr[e], s1 = csr[e + 1], s2 = csr[e + 2], s3 = csr[e + 3];
        acc_row(hh, hl, s0, off, a0, a1, a2, a3);
        acc_row(hh, hl, s1, off, a0, a1, a2, a3);
        acc_row(hh, hl, s2, off, a0, a1, a2, a3);
        acc_row(hh, hl, s3, off, a0, a1, a2, a3);
    }
    for (; e < e1; e++)
        acc_row(hh, hl, csr[e], off, a0, a1, a2, a3);

    float v0 = a0 * inv, v1 = a1 * inv, v2 = a2 * inv, v3 = a3 * inv;
    fp162 h0 = __float22half2_rn(make_float2(v0, v1));
    fp162 h1 = __float22half2_rn(make_float2(v2, v3));
    float2 f0 = __half22float2(h0);
    float2 f1 = __half22float2(h1);
    fp162 l0 = __float22half2_rn(make_float2(v0 - f0.x, v1 - f0.y));
    fp162 l1 = __float22half2_rn(make_float2(v2 - f1.x, v3 - f1.y));
    uint2 wh_, wl_;
    wh_.x = *(uint32_t*)&h0; wh_.y = *(uint32_t*)&h1;
    wl_.x = *(uint32_t*)&l0; wl_.y = *(uint32_t*)&l1;
    *(uint2*)(oh + (size_t)warp * 128 + off) = wh_;
    *(uint2*)(ol + (size_t)warp * 128 + off) = wl_;
}

// ---------------- layer-1 fused gather (4-edge unroll) ----------------
__global__ void gather_fuse_bn(const float* __restrict__ S1,
                               const float* __restrict__ G1,
                               const int* __restrict__ csr,
                               const int* __restrict__ rowptr,
                               const float* __restrict__ bias,
                               const float* __restrict__ bng,
                               const float* __restrict__ bnb,
                               const float* __restrict__ bnm,
                               const float* __restrict__ bnv,
                               fp16* __restrict__ oh, fp16* __restrict__ ol,
                               int Nn)
{
    const int warp = (blockIdx.x * blockDim.x + threadIdx.x) >> 5;
    const int lane = threadIdx.x & 31;
    if (warp >= Nn) return;
    const int e0 = rowptr[warp];
    const int e1 = rowptr[warp + 1];
    const float inv = 1.f / (float)max(e1 - e0, 1);
    const int col = lane * 4;

    float acc0 = 0.f, acc1 = 0.f, acc2 = 0.f, acc3 = 0.f;
    int e = e0;
    for (; e + 3 < e1; e += 4) {
        const float4 v0 = *(const float4*)(G1 + (size_t)csr[e] * 128 + col);
        const float4 v1 = *(const float4*)(G1 + (size_t)csr[e + 1] * 128 + col);
        const float4 v2 = *(const float4*)(G1 + (size_t)csr[e + 2] * 128 + col);
        const float4 v3 = *(const float4*)(G1 + (size_t)csr[e + 3] * 128 + col);
        acc0 += (v0.x + v1.x) + (v2.x + v3.x);
        acc1 += (v0.y + v1.y) + (v2.y + v3.y);
        acc2 += (v0.z + v1.z) + (v2.z + v3.z);
        acc3 += (v0.w + v1.w) + (v2.w + v3.w);
    }
    for (; e < e1; e++) {
        const float4 v = *(const float4*)(G1 + (size_t)csr[e] * 128 + col);
        acc0 += v.x; acc1 += v.y; acc2 += v.z; acc3 += v.w;
    }
    const float4 s = *(const float4*)(S1 + (size_t)warp * 128 + col);

    float vo[4];
    const float* sp = &s.x;
    float ac[4] = {acc0, acc1, acc2, acc3};
#pragma unroll
    for (int j = 0; j < 4; j++) {
        const float sc = bng[col + j] * rsqrtf(bnv[col + j] + 1e-5f);
        const float sh = (bias[col + j] - bnm[col + j]) * sc + bnb[col + j];
        float x = (sp[j] + ac[j] * inv) * sc + sh;
        vo[j] = fmaxf(x, 0.f);
    }

    fp162 h0 = __float22half2_rn(make_float2(vo[0], vo[1]));
    fp162 h1 = __float22half2_rn(make_float2(vo[2], vo[3]));
    float2 f0 = __half22float2(h0);
    float2 f1 = __half22float2(h1);
    fp162 l0 = __float22half2_rn(make_float2(vo[0] - f0.x, vo[1] - f0.y));
    fp162 l1 = __float22half2_rn(make_float2(vo[2] - f1.x, vo[3] - f1.y));
    uint2 wh_, wl_;
    wh_.x = *(uint32_t*)&h0; wh_.y = *(uint32_t*)&h1;
    wl_.x = *(uint32_t*)&l0; wl_.y = *(uint32_t*)&l1;
    *(uint2*)(oh + (size_t)warp * 128 + col) = wh_;
    *(uint2*)(ol + (size_t)warp * 128 + col) = wl_;
}

// ---------------- launch helpers ----------------
static inline void launch_gemm(
    const fp16* A0h, const fp16* A0l, int K0,
    const fp16* A1h, const fp16* A1l, int K1,
    const fp16* W0, const fp16* W1,
    int M, int N,
    const float* bias, const float* bng, const float* bnb,
    const float* bnm, const float* bnv,
    int do_relu, float* Cf, fp16* Ch, fp16* Cl)
{
    if (N >= 128) {
        constexpr int BM_ = 64, BN_ = 128;
        constexpr int SMEM = 2 * (2 * BM_ * A_STRIDE + BK * (BN_ + 8)) * 2;
        dim3 grid(N / BN_, (M + BM_ - 1) / BM_);
        gemm_fp16x2<BM_, BN_, 0><<<grid, 256, SMEM>>>(
            A0h, A0l, K0, A1h, A1l, K1, nullptr, nullptr,
            W0, W1, M, N,
            bias, bng, bnb, bnm, bnv, do_relu, Cf, Ch, Cl);
    } else {
        constexpr int BM_ = 128, BN_ = 64;
        constexpr int SMEM = 2 * (2 * BM_ * A_STRIDE + BK * (BN_ + 8)) * 2;
        dim3 grid((N + BN_ - 1) / BN_, (M + BM_ - 1) / BM_);
        gemm_fp16x2<BM_, BN_, 0><<<grid, 256, SMEM>>>(
            A0h, A0l, K0, A1h, A1l, K1, nullptr, nullptr,
            W0, W1, M, N,
            bias, bng, bnb, bnm, bnv, do_relu, Cf, Ch, Cl);
    }
}

static inline void launch_gemm_f32(
    const float* Af0, int K0, const float* Af1, int K1,
    const fp16* W0, const fp16* W1,
    int M, int N, const float* bias, int do_relu, fp16* Ch, fp16* Cl)
{
    constexpr int BM_ = 64, BN_ = 128;
    constexpr int SMEM = 2 * (2 * BM_ * A_STRIDE + BK * (BN_ + 8)) * 2;
    dim3 grid(N / BN_, (M + BM_ - 1) / BM_);
    gemm_fp16x2<BM_, BN_, 1><<<grid, 256, SMEM>>>(
        nullptr, nullptr, K0, nullptr, nullptr, K1, Af0, Af1,
        W0, W1, M, N,
        bias, nullptr, nullptr, nullptr, nullptr, do_relu, nullptr, Ch, Cl);
}

extern "C" void kernel_launch(void* const* d_in, const int* in_sizes, int n_in,
                              void* d_out, int out_size)
{
    const float* structural = (const float*)d_in[0];
    const float* multimodal = (const float*)d_in[1];
    const int*   src        = (const int*)  d_in[2];
    const int*   dst        = (const int*)  d_in[3];
    const float* enc_w      = (const float*)d_in[4];
    const float* enc_b      = (const float*)d_in[5];
    const float* sage0_ws   = (const float*)d_in[6];
    const float* sage0_wn   = (const float*)d_in[7];
    const float* sage0_b    = (const float*)d_in[8];
    const float* bn0_g      = (const float*)d_in[9];
    const float* bn0_b      = (const float*)d_in[10];
    const float* bn0_m      = (const float*)d_in[11];
    const float* bn0_v      = (const float*)d_in[12];
    const float* sage1_ws   = (const float*)d_in[13];
    const float* sage1_wn   = (const float*)d_in[14];
    const float* sage1_b    = (const float*)d_in[15];
    const float* bn1_g      = (const float*)d_in[16];
    const float* bn1_b      = (const float*)d_in[17];
    const float* bn1_m      = (const float*)d_in[18];
    const float* bn1_v      = (const float*)d_in[19];
    const float* rel_w      = (const float*)d_in[20];
    const float* rel_b      = (const float*)d_in[21];
    const float* cls_w1     = (const float*)d_in[22];
    const float* cls_b1     = (const float*)d_in[23];
    const float* cls_w2     = (const float*)d_in[24];
    const float* cls_b2     = (const float*)d_in[25];
    float* out = (float*)d_out;

#define SYMADDR(var, sym) void* p_##var; cudaGetSymbolAddress(&p_##var, sym);
    SYMADDR(h0h, g_h0h) SYMADDR(h0l, g_h0l) SYMADDR(a0h, g_a0h) SYMADDR(a0l, g_a0l)
    SYMADDR(h1h, g_h1h) SYMADDR(h1l, g_h1l)
    SYMADDR(h2h, g_h2h) SYMADDR(h2l, g_h2l) SYMADDR(hfh, g_hfh) SYMADDR(hfl, g_hfl)
    SYMADDR(c1h, g_c1h) SYMADDR(c1l, g_c1l)
    SYMADDR(s1f, g_s1f) SYMADDR(g1f, g_g1f)
    SYMADDR(wh, g_wh)
    SYMADDR(counts, g_counts) SYMADDR(rowptr, g_rowptr)
    SYMADDR(fill, g_fill) SYMADDR(csr, g_csr)
#undef SYMADDR

    fp16* h0h = (fp16*)p_h0h; fp16* h0l = (fp16*)p_h0l;
    fp16* a0h = (fp16*)p_a0h; fp16* a0l = (fp16*)p_a0l;
    fp16* h1h = (fp16*)p_h1h; fp16* h1l = (fp16*)p_h1l;
    fp16* h2h = (fp16*)p_h2h; fp16* h2l = (fp16*)p_h2l;
    fp16* hfh = (fp16*)p_hfh; fp16* hfl = (fp16*)p_hfl;
    fp16* c1h = (fp16*)p_c1h; fp16* c1l = (fp16*)p_c1l;
    float* s1f = (float*)p_s1f; float* g1f = (float*)p_g1f;
    fp16* wh = (fp16*)p_wh;
    int* counts = (int*)p_counts; int* rowptr = (int*)p_rowptr;
    int* fill   = (int*)p_fill;   int* csr    = (int*)p_csr;

    {
        constexpr int SMEM_A = 2 * (2 * 64 * A_STRIDE + BK * (128 + 8)) * 2;
        constexpr int SMEM_B = 2 * (2 * 128 * A_STRIDE + BK * (64 + 8)) * 2;
        cudaFuncSetAttribute((const void*)gemm_fp16x2<64, 128, 0>,
                             cudaFuncAttributeMaxDynamicSharedMemorySize, SMEM_A);
        cudaFuncSetAttribute((const void*)gemm_fp16x2<64, 128, 1>,
                             cudaFuncAttributeMaxDynamicSharedMemorySize, SMEM_A);
        cudaFuncSetAttribute((const void*)gemm_fp16x2<128, 64, 0>,
                             cudaFuncAttributeMaxDynamicSharedMemorySize, SMEM_B);
    }

    const int M = N_NODES, E = N_EDGES;

    // ---- CSR build ----
    cudaMemsetAsync(counts, 0, N_NODES * sizeof(int), 0);
    count_deg<<<(E + 255) / 256, 256>>>(dst, counts, E);
    scan_counts<<<1, 1024>>>(counts, rowptr, fill, M);
    fill_csr<<<(E + 255) / 256, 256>>>(src, dst, fill, csr, E);

    // ---- split all weights to single fp16 plane ----
    {
        WSeg ws;
        ws.src[0] = enc_w;    ws.beg[0] = WOFF_ENC;
        ws.src[1] = sage0_ws; ws.beg[1] = WOFF_S0S;
        ws.src[2] = sage0_wn; ws.beg[2] = WOFF_S0N;
        ws.src[3] = sage1_ws; ws.beg[3] = WOFF_S1S;
        ws.src[4] = sage1_wn; ws.beg[4] = WOFF_S1N;
        ws.src[5] = rel_w;    ws.beg[5] = WOFF_REL;
        ws.src[6] = cls_w1;   ws.beg[6] = WOFF_C1;
        ws.src[7] = cls_w2;   ws.beg[7] = WOFF_C2;
        ws.beg[8] = WOFF_END;
        int w4 = WOFF_END / 4;
        split_weights<<<(w4 + 255) / 256, 256>>>(ws, wh);
    }

    // h0 = relu([structural|multimodal] @ enc_w + enc_b)  (pipelined fp32 A)
    launch_gemm_f32(structural, 128, multimodal, 384,
                    wh + WOFF_ENC, wh + WOFF_ENC + 128 * 128,
                    M, 128, enc_b, 1, h0h, h0l);

    // agg0 = mean h0
    gather_mean<<<(M * 32 + 255) / 256, 256>>>(h0h, h0l, csr, rowptr,
                                               a0h, a0l, M);

    // h1 = relu(bn0(h0 @ ws0 + agg0 @ wn0 + b0))
    launch_gemm(h0h, h0l, 128, a0h, a0l, 128,
                wh + WOFF_S0S, wh + WOFF_S0N,
                M, 256, sage0_b, bn0_g, bn0_b, bn0_m, bn0_v, 1,
                nullptr, h1h, h1l);

    // ---- sage1, commuted: mean(h1) @ Wn1 == mean(h1 @ Wn1) ----
    launch_gemm(h1h, h1l, 256, h1h, h1l, 0,
                wh + WOFF_S1N, wh + WOFF_S1N,
                M, 128, nullptr, nullptr, nullptr, nullptr, nullptr, 0,
                g1f, nullptr, nullptr);
    launch_gemm(h1h, h1l, 256, h1h, h1l, 0,
                wh + WOFF_S1S, wh + WOFF_S1S,
                M, 128, nullptr, nullptr, nullptr, nullptr, nullptr, 0,
                s1f, nullptr, nullptr);
    gather_fuse_bn<<<(M * 32 + 255) / 256, 256>>>(
        s1f, g1f, csr, rowptr, sage1_b, bn1_g, bn1_b, bn1_m, bn1_v,
        h2h, h2l, M);

    // hf = relu([h0|h2] @ rel_w + rel_b)
    launch_gemm(h0h, h0l, 128, h2h, h2l, 128,
                wh + WOFF_REL, wh + WOFF_REL + 128 * 128,
                M, 128, rel_b, nullptr, nullptr, nullptr, nullptr, 1,
                nullptr, hfh, hfl);

    // c1 = relu(hf @ cls_w1 + cls_b1)
    launch_gemm(hfh, hfl, 128, hfh, hfl, 0,
                wh + WOFF_C1, wh + WOFF_C1,
                M, 64, cls_b1, nullptr, nullptr, nullptr, nullptr, 1,
                nullptr, c1h, c1l);

    // out = c1 @ cls_w2 + cls_b2   (fp32)
    launch_gemm(c1h, c1l, 64, c1h, c1l, 0,
                wh + WOFF_C2, wh + WOFF_C2,
                M, 32, cls_b2, nullptr, nullptr, nullptr, nullptr, 0,
                out, nullptr, nullptr);
}

// round 16
// speedup vs baseline: 1.5110x; 1.0028x over previous
#include <cuda_runtime.h>
#include <cuda_fp16.h>
#include <math.h>
#include <stdint.h>

#define N_NODES 100000
#define N_EDGES 800000

typedef __half  fp16;
typedef __half2 fp162;

// ---------------- scratch (device globals; no allocs allowed) ----------------
__device__ fp16 g_h0h[(size_t)N_NODES * 128], g_h0l[(size_t)N_NODES * 128];
__device__ fp16 g_a0h[(size_t)N_NODES * 128], g_a0l[(size_t)N_NODES * 128];
__device__ fp16 g_h1h[(size_t)N_NODES * 256], g_h1l[(size_t)N_NODES * 256];
__device__ fp16 g_h2h[(size_t)N_NODES * 128], g_h2l[(size_t)N_NODES * 128];
__device__ fp16 g_hfh[(size_t)N_NODES * 128], g_hfl[(size_t)N_NODES * 128];
__device__ fp16 g_c1h[(size_t)N_NODES * 64],  g_c1l[(size_t)N_NODES * 64];
__device__ float g_s1f[(size_t)N_NODES * 128];
__device__ float g_g1f[(size_t)N_NODES * 128];
__device__ fp16 g_wh[262144];
__device__ int g_counts[N_NODES];
__device__ int g_rowptr[N_NODES + 1];
__device__ int g_fill  [N_NODES];
__device__ int g_csr   [N_EDGES];

#define WOFF_ENC 0
#define WOFF_S0S 65536
#define WOFF_S0N 98304
#define WOFF_S1S 131072
#define WOFF_S1N 163840
#define WOFF_REL 196608
#define WOFF_C1  229376
#define WOFF_C2  237568
#define WOFF_END 239616

#define BK 32
#define A_STRIDE 40

__device__ __forceinline__ void cp16(uint32_t dst, const void* src, bool pred) {
    asm volatile("cp.async.cg.shared.global [%0], [%1], 16, %2;"
                 :: "r"(dst), "l"(src), "r"(pred ? 16 : 0));
}

#define LDMX4(r, addr)                                                          \
    asm volatile("ldmatrix.sync.aligned.m8n8.x4.shared.b16 {%0,%1,%2,%3},[%4];" \
                 : "=r"((r)[0]), "=r"((r)[1]), "=r"((r)[2]), "=r"((r)[3])       \
                 : "r"(addr))

#define LDMX4T(r, addr)                                                         \
    asm volatile("ldmatrix.sync.aligned.m8n8.x4.trans.shared.b16 "              \
                 "{%0,%1,%2,%3},[%4];"                                          \
                 : "=r"((r)[0]), "=r"((r)[1]), "=r"((r)[2]), "=r"((r)[3])       \
                 : "r"(addr))

#define MMA_FP16(acc, a, b0, b1)                                                \
    asm volatile(                                                               \
        "mma.sync.aligned.m16n8k16.row.col.f32.f16.f16.f32 "                    \
        "{%0,%1,%2,%3},{%4,%5,%6,%7},{%8,%9},{%0,%1,%2,%3};"                    \
        : "+f"((acc)[0]), "+f"((acc)[1]), "+f"((acc)[2]), "+f"((acc)[3])        \
        : "r"((a)[0]), "r"((a)[1]), "r"((a)[2]), "r"((a)[3]),                   \
          "r"(b0), "r"(b1))

__device__ __forceinline__ void cvt8_planes(float4 v0, float4 v1,
                                            uint4& hi, uint4& lo)
{
    fp162 h0 = __float22half2_rn(make_float2(v0.x, v0.y));
    fp162 h1 = __float22half2_rn(make_float2(v0.z, v0.w));
    fp162 h2 = __float22half2_rn(make_float2(v1.x, v1.y));
    fp162 h3 = __float22half2_rn(make_float2(v1.z, v1.w));
    float2 f0 = __half22float2(h0);
    float2 f1 = __half22float2(h1);
    float2 f2 = __half22float2(h2);
    float2 f3 = __half22float2(h3);
    fp162 l0 = __float22half2_rn(make_float2(v0.x - f0.x, v0.y - f0.y));
    fp162 l1 = __float22half2_rn(make_float2(v0.z - f1.x, v0.w - f1.y));
    fp162 l2 = __float22half2_rn(make_float2(v1.x - f2.x, v1.y - f2.y));
    fp162 l3 = __float22half2_rn(make_float2(v1.z - f3.x, v1.w - f3.y));
    hi.x = *(uint32_t*)&h0; hi.y = *(uint32_t*)&h1;
    hi.z = *(uint32_t*)&h2; hi.w = *(uint32_t*)&h3;
    lo.x = *(uint32_t*)&l0; lo.y = *(uint32_t*)&l1;
    lo.z = *(uint32_t*)&l2; lo.w = *(uint32_t*)&l3;
}

// ---------------- fp16x2 tensor-core GEMM (A hi/lo split, B single) ----------
template<int BM_, int BN_, int AF32>
__global__ __launch_bounds__(256, 3) void gemm_fp16x2(
    const fp16* __restrict__ A0h, const fp16* __restrict__ A0l, int K0,
    const fp16* __restrict__ A1h, const fp16* __restrict__ A1l, int K1,
    const float* __restrict__ Af0, const float* __restrict__ Af1,
    const fp16* __restrict__ W0, const fp16* __restrict__ W1,
    int M, int N,
    const float* __restrict__ bias,
    const float* __restrict__ bng, const float* __restrict__ bnb,
    const float* __restrict__ bnm, const float* __restrict__ bnv,
    int do_relu,
    float* __restrict__ Cf, fp16* __restrict__ Ch, fp16* __restrict__ Cl)
{
    constexpr int A_PLANE_ = BM_ * A_STRIDE;
    constexpr int B_STRIDE = BN_ + 8;
    constexpr int B_PLANE  = BK * B_STRIDE;
    constexpr int STAGE_ELEMS = 2 * A_PLANE_ + B_PLANE;
    constexpr int WROWS  = BM_ / 32;
    constexpr int WARP_N = BN_ * WROWS / 8;
    constexpr int NT = WARP_N / 8;
    constexpr int P  = WARP_N / 16;
    constexpr int NCP = BN_ / 64;
    constexpr int NSTG = (BN_ == 128 && !AF32) ? 3 : 2;   // deep pipe on main path

    extern __shared__ fp16 smem[];
    const uint32_t smem_u32 = (uint32_t)__cvta_generic_to_shared(smem);

    const int tid  = threadIdx.x;
    const int lane = tid & 31;
    const int wid  = tid >> 5;
    const int wm   = (wid % WROWS) * 32;
    const int wn   = (wid / WROWS) * WARP_N;
    const int brow = blockIdx.y * BM_;
    const int bcol = blockIdx.x * BN_;
    const int K = K0 + K1;
    const int T = K / BK;

    constexpr int ATPR = 256 / BM_;
    const int a_row = tid / ATPR;
    const int a_k   = (tid % ATPR) * (32 / ATPR);
    const int a_gr  = brow + a_row;
    const bool a_ok = (a_gr < M);
    const int b_k  = tid >> 3;
    const int b_n0 = (tid & 7) * (BN_ / 8);

    const int a_lm = (wm + (lane & 15)) * A_STRIDE + (lane >> 4) * 8;
    const int b_lm = ((lane & 7) + ((lane >> 3) & 1) * 8) * B_STRIDE
                     + wn + (lane >> 4) * 8;

    float acc[2][NT][4];
#pragma unroll
    for (int mt = 0; mt < 2; mt++)
#pragma unroll
        for (int nt = 0; nt < NT; nt++)
#pragma unroll
            for (int i = 0; i < 4; i++) acc[mt][nt][i] = 0.f;

#define B_LOAD(t, stv) do {                                                       \
        int gk = (t) * BK + b_k;                                                  \
        const fp16 *wp; int kk2;                                                  \
        if (gk < K0) { wp = W0; kk2 = gk; }                                       \
        else         { wp = W1; kk2 = gk - K0; }                                  \
        uint32_t dbh = smem_u32 +                                                 \
            ((stv) * STAGE_ELEMS + 2 * A_PLANE_ + b_k * B_STRIDE + b_n0) * 2;     \
        _Pragma("unroll")                                                         \
        for (int cc = 0; cc < NCP; cc++) {                                        \
            int n0 = bcol + b_n0 + cc * 8;                                        \
            bool ok = (n0 < N);                                                   \
            cp16(dbh + cc * 16, wp + (size_t)kk2 * N + n0, ok);                   \
        }                                                                         \
    } while (0)

#define LOAD_TILE(t, stv) do {                                                    \
        int gk0 = (t) * BK + a_k;                                                 \
        const fp16 *sph, *spl;                                                    \
        if (gk0 < K0) { sph = A0h + (size_t)a_gr * K0 + gk0;                      \
                        spl = A0l + (size_t)a_gr * K0 + gk0; }                    \
        else          { sph = A1h + (size_t)a_gr * K1 + (gk0 - K0);               \
                        spl = A1l + (size_t)a_gr * K1 + (gk0 - K0); }             \
        uint32_t dh = smem_u32 +                                                  \
            ((stv) * STAGE_ELEMS + a_row * A_STRIDE + a_k) * 2;                   \
        if (ATPR == 2) {                                                          \
            cp16(dh,      sph,     a_ok);                                         \
            cp16(dh + 16, sph + 8, a_ok);                                         \
            cp16(dh + A_PLANE_ * 2,      spl,     a_ok);                          \
            cp16(dh + A_PLANE_ * 2 + 16, spl + 8, a_ok);                          \
        } else {                                                                  \
            cp16(dh,                sph, a_ok);                                   \
            cp16(dh + A_PLANE_ * 2, spl, a_ok);                                   \
        }                                                                         \
        B_LOAD(t, stv);                                                           \
        asm volatile("cp.async.commit_group;");                                   \
    } while (0)

#define A_LDG(t) do {                                                             \
        int gk0 = (t) * BK + a_k;                                                 \
        const float* sp;                                                          \
        if (gk0 < K0) sp = Af0 + (size_t)a_gr * K0 + gk0;                         \
        else          sp = Af1 + (size_t)a_gr * K1 + (gk0 - K0);                  \
        if (a_ok) { cv0 = *(const float4*)sp; cv1 = *(const float4*)(sp + 4); }   \
        else { cv0 = make_float4(0.f,0.f,0.f,0.f); cv1 = cv0; }                   \
    } while (0)

#define A_STS(stv) do {                                                           \
        uint4 hi_, lo_;                                                           \
        cvt8_planes(cv0, cv1, hi_, lo_);                                          \
        fp16* ap = smem + (stv) * STAGE_ELEMS + a_row * A_STRIDE + a_k;           \
        *(uint4*)ap = hi_;                                                        \
        *(uint4*)(ap + A_PLANE_) = lo_;                                           \
    } while (0)

#define MMA_STEP(stv) do {                                                        \
        const uint32_t base = smem_u32 + (stv) * STAGE_ELEMS * 2;                 \
        _Pragma("unroll")                                                         \
        for (int k16 = 0; k16 < 2; k16++) {                                       \
            uint32_t ah[2][4], al[2][4], bh[P][4];                                \
            _Pragma("unroll")                                                     \
            for (int mt = 0; mt < 2; mt++) {                                      \
                uint32_t ad = base + (a_lm + mt * 16 * A_STRIDE + k16 * 16) * 2;  \
                LDMX4(ah[mt], ad);                                                \
                LDMX4(al[mt], ad + A_PLANE_ * 2);                                 \
            }                                                                     \
            _Pragma("unroll")                                                     \
            for (int p = 0; p < P; p++) {                                         \
                uint32_t bd = base + (2 * A_PLANE_ + b_lm + p * 16                \
                                      + k16 * 16 * B_STRIDE) * 2;                 \
                LDMX4T(bh[p], bd);                                                \
            }                                                                     \
            _Pragma("unroll")                                                     \
            for (int mt = 0; mt < 2; mt++)                                        \
                _Pragma("unroll")                                                 \
                for (int nt = 0; nt < NT; nt++) {                                 \
                    const int p = nt >> 1, q = (nt & 1) * 2;                      \
                    MMA_FP16(acc[mt][nt], al[mt], bh[p][q], bh[p][q + 1]);        \
                    MMA_FP16(acc[mt][nt], ah[mt], bh[p][q], bh[p][q + 1]);        \
                }                                                                 \
        }                                                                         \
    } while (0)

    if (AF32) {
        // software-pipelined fp32 A path: LDG(t+2) hidden behind MMAs(t)
        float4 cv0, cv1;
        A_LDG(0);
        A_STS(0);
        B_LOAD(0, 0);
        asm volatile("cp.async.commit_group;");
        A_LDG(1);
        B_LOAD(1, 1);
        asm volatile("cp.async.commit_group;");

        for (int t = 0; t < T; ++t) {
            const int st = t & 1;
            if (t + 1 < T) {
                asm volatile("cp.async.wait_group 1;");
            } else {
                asm volatile("cp.async.wait_group 0;");
            }
            __syncthreads();
            MMA_STEP(st);
            __syncthreads();
            if (t + 1 < T) {
                A_STS(st ^ 1);
                if (t + 2 < T) {
                    A_LDG(t + 2);
                    B_LOAD(t + 2, st);
                    asm volatile("cp.async.commit_group;");
                }
            }
        }
    } else if (NSTG == 3) {
        LOAD_TILE(0, 0);
        if (T > 1) LOAD_TILE(1, 1);
        for (int t = 0; t < T; ++t) {
            const int st = t % 3;
            if (t + 2 < T) {
                LOAD_TILE(t + 2, (t + 2) % 3);
                asm volatile("cp.async.wait_group 2;");
            } else if (t + 1 < T) {
                asm volatile("cp.async.wait_group 1;");
            } else {
                asm volatile("cp.async.wait_group 0;");
            }
            __syncthreads();
            MMA_STEP(st);
            __syncthreads();
        }
    } else {
        LOAD_TILE(0, 0);
        for (int t = 0; t < T; ++t) {
            const int st = t & 1;
            if (t + 1 < T) {
                LOAD_TILE(t + 1, st ^ 1);
                asm volatile("cp.async.wait_group 1;");
            } else {
                asm volatile("cp.async.wait_group 0;");
            }
            __syncthreads();
            MMA_STEP(st);
            __syncthreads();
        }
    }

#pragma unroll
    for (int nt = 0; nt < NT; nt++) {
        const int col = bcol + wn + 8 * nt + 2 * (lane & 3);
        if (col >= N) continue;
        float sc0 = 1.f, sh0 = 0.f, sc1 = 1.f, sh1 = 0.f;
        if (bias) { sh0 = bias[col]; sh1 = bias[col + 1]; }
        if (bng) {
            float s0 = bng[col]     * rsqrtf(bnv[col]     + 1e-5f);
            float s1 = bng[col + 1] * rsqrtf(bnv[col + 1] + 1e-5f);
            sh0 = (sh0 - bnm[col])     * s0 + bnb[col];
            sh1 = (sh1 - bnm[col + 1]) * s1 + bnb[col + 1];
            sc0 = s0; sc1 = s1;
        }
#pragma unroll
        for (int mt = 0; mt < 2; mt++) {
#pragma unroll
            for (int half = 0; half < 2; half++) {
                const int row = brow + wm + 16 * mt + (lane >> 2) + 8 * half;
                if (row >= M) continue;
                const float* c = acc[mt][nt] + 2 * half;
                float v0 = c[0] * sc0 + sh0;
                float v1 = c[1] * sc1 + sh1;
                if (do_relu) { v0 = fmaxf(v0, 0.f); v1 = fmaxf(v1, 0.f); }
                if (Ch) {
                    fp162 hi = __float22half2_rn(make_float2(v0, v1));
                    float2 hf2 = __half22float2(hi);
                    fp162 lo = __float22half2_rn(
                        make_float2(v0 - hf2.x, v1 - hf2.y));
                    *(fp162*)(Ch + (size_t)row * N + col) = hi;
                    *(fp162*)(Cl + (size_t)row * N + col) = lo;
                } else {
                    *(float2*)(Cf + (size_t)row * N + col) = make_float2(v0, v1);
                }
            }
        }
    }
}

// ---------------- merged weight split ----------------
struct WSeg { const float* src[8]; int beg[9]; };

__global__ void split_weights(WSeg ws, fp16* __restrict__ wh)
{
    int i4 = blockIdx.x * blockDim.x + threadIdx.x;
    int i  = i4 * 4;
    if (i >= ws.beg[8]) return;
    int s = 0;
#pragma unroll
    for (int k = 0; k < 7; k++) s += (i >= ws.beg[k + 1]) ? 1 : 0;
    float4 v = *(const float4*)(ws.src[s] + (i - ws.beg[s]));
    fp162 h0 = __float22half2_rn(make_float2(v.x, v.y));
    fp162 h1 = __float22half2_rn(make_float2(v.z, v.w));
    ((fp162*)wh)[i4 * 2]     = h0;
    ((fp162*)wh)[i4 * 2 + 1] = h1;
}

// ---------------- CSR construction ----------------
__global__ void count_deg(const int* __restrict__ dst, int* __restrict__ counts, int E)
{
    int e = blockIdx.x * blockDim.x + threadIdx.x;
    if (e < E) atomicAdd(&counts[dst[e]], 1);
}

__global__ __launch_bounds__(1024) void scan_counts(
    const int* __restrict__ counts, int* __restrict__ rowptr,
    int* __restrict__ fill, int n)
{
    __shared__ int part[1024];
    const int tid = threadIdx.x;
    const int chunk = (n + 1023) / 1024;
    const int begin = min(tid * chunk, n);
    const int end   = min(begin + chunk, n);
    int s = 0;
    for (int i = begin; i < end; i++) s += counts[i];
    part[tid] = s;
    __syncthreads();
    for (int off = 1; off < 1024; off <<= 1) {
        int v = (tid >= off) ? part[tid - off] : 0;
        __syncthreads();
        part[tid] += v;
        __syncthreads();
    }
    int pre = (tid == 0) ? 0 : part[tid - 1];
    for (int i = begin; i < end; i++) {
        rowptr[i] = pre;
        fill[i]   = pre;
        pre += counts[i];
    }
    if (end == n && begin <= n) rowptr[n] = pre;
}

__global__ void fill_csr(const int* __restrict__ src, const int* __restrict__ dst,
                         int* __restrict__ fill, int* __restrict__ csr, int E)
{
    int e = blockIdx.x * blockDim.x + threadIdx.x;
    if (e < E) {
        int pos = atomicAdd(&fill[dst[e]], 1);
        csr[pos] = src[e];
    }
}

// ---------------- CSR gather mean over fp16 planes (D=128), 4-edge unroll -----
__device__ __forceinline__ void acc_row(const fp16* hh, const fp16* hl,
                                        int s, int off,
                                        float& a0, float& a1, float& a2, float& a3)
{
    uint2 vh = *(const uint2*)(hh + (size_t)s * 128 + off);
    uint2 vl = *(const uint2*)(hl + (size_t)s * 128 + off);
    float2 p0 = __half22float2(*(const fp162*)&vh.x);
    float2 p1 = __half22float2(*(const fp162*)&vh.y);
    float2 q0 = __half22float2(*(const fp162*)&vl.x);
    float2 q1 = __half22float2(*(const fp162*)&vl.y);
    a0 += p0.x + q0.x;
    a1 += p0.y + q0.y;
    a2 += p1.x + q1.x;
    a3 += p1.y + q1.y;
}

__global__ void gather_mean(const fp16* __restrict__ hh, const fp16* __restrict__ hl,
                            const int* __restrict__ csr, const int* __restrict__ rowptr,
                            fp16* __restrict__ oh, fp16* __restrict__ ol, int Nn)
{
    const int warp = (blockIdx.x * blockDim.x + threadIdx.x) >> 5;
    const int lane = threadIdx.x & 31;
    if (warp >= Nn) return;
    const int e0 = rowptr[warp];
    const int e1 = rowptr[warp + 1];
    const float inv = 1.f / (float)max(e1 - e0, 1);
    const int off = lane * 4;

    float a0 = 0.f, a1 = 0.f, a2 = 0.f, a3 = 0.f;
    int e = e0;
    for (; e + 3 < e1; e += 4) {
        int s0 = csr[e], s1 = csr[e + 1], s2 = csr[e + 2], s3 = csr[e + 3];
        acc_row(hh, hl, s0, off, a0, a1, a2, a3);
        acc_row(hh, hl, s1, off, a0, a1, a2, a3);
        acc_row(hh, hl, s2, off, a0, a1, a2, a3);
        acc_row(hh, hl, s3, off, a0, a1, a2, a3);
    }
    for (; e < e1; e++)
        acc_row(hh, hl, csr[e], off, a0, a1, a2, a3);

    float v0 = a0 * inv, v1 = a1 * inv, v2 = a2 * inv, v3 = a3 * inv;
    fp162 h0 = __float22half2_rn(make_float2(v0, v1));
    fp162 h1 = __float22half2_rn(make_float2(v2, v3));
    float2 f0 = __half22float2(h0);
    float2 f1 = __half22float2(h1);
    fp162 l0 = __float22half2_rn(make_float2(v0 - f0.x, v1 - f0.y));
    fp162 l1 = __float22half2_rn(make_float2(v2 - f1.x, v3 - f1.y));
    uint2 wh_, wl_;
    wh_.x = *(uint32_t*)&h0; wh_.y = *(uint32_t*)&h1;
    wl_.x = *(uint32_t*)&l0; wl_.y = *(uint32_t*)&l1;
    *(uint2*)(oh + (size_t)warp * 128 + off) = wh_;
    *(uint2*)(ol + (size_t)warp * 128 + off) = wl_;
}

// ---------------- layer-1 fused gather (4-edge unroll) ----------------
__global__ void gather_fuse_bn(const float* __restrict__ S1,
                               const float* __restrict__ G1,
                               const int* __restrict__ csr,
                               const int* __restrict__ rowptr,
                               const float* __restrict__ bias,
                               const float* __restrict__ bng,
                               const float* __restrict__ bnb,
                               const float* __restrict__ bnm,
                               const float* __restrict__ bnv,
                               fp16* __restrict__ oh, fp16* __restrict__ ol,
                               int Nn)
{
    const int warp = (blockIdx.x * blockDim.x + threadIdx.x) >> 5;
    const int lane = threadIdx.x & 31;
    if (warp >= Nn) return;
    const int e0 = rowptr[warp];
    const int e1 = rowptr[warp + 1];
    const float inv = 1.f / (float)max(e1 - e0, 1);
    const int col = lane * 4;

    float acc0 = 0.f, acc1 = 0.f, acc2 = 0.f, acc3 = 0.f;
    int e = e0;
    for (; e + 3 < e1; e += 4) {
        const float4 v0 = *(const float4*)(G1 + (size_t)csr[e] * 128 + col);
        const float4 v1 = *(const float4*)(G1 + (size_t)csr[e + 1] * 128 + col);
        const float4 v2 = *(const float4*)(G1 + (size_t)csr[e + 2] * 128 + col);
        const float4 v3 = *(const float4*)(G1 + (size_t)csr[e + 3] * 128 + col);
        acc0 += (v0.x + v1.x) + (v2.x + v3.x);
        acc1 += (v0.y + v1.y) + (v2.y + v3.y);
        acc2 += (v0.z + v1.z) + (v2.z + v3.z);
        acc3 += (v0.w + v1.w) + (v2.w + v3.w);
    }
    for (; e < e1; e++) {
        const float4 v = *(const float4*)(G1 + (size_t)csr[e] * 128 + col);
        acc0 += v.x; acc1 += v.y; acc2 += v.z; acc3 += v.w;
    }
    const float4 s = *(const float4*)(S1 + (size_t)warp * 128 + col);

    float vo[4];
    const float* sp = &s.x;
    float ac[4] = {acc0, acc1, acc2, acc3};
#pragma unroll
    for (int j = 0; j < 4; j++) {
        const float sc = bng[col + j] * rsqrtf(bnv[col + j] + 1e-5f);
        const float sh = (bias[col + j] - bnm[col + j]) * sc + bnb[col + j];
        float x = (sp[j] + ac[j] * inv) * sc + sh;
        vo[j] = fmaxf(x, 0.f);
    }

    fp162 h0 = __float22half2_rn(make_float2(vo[0], vo[1]));
    fp162 h1 = __float22half2_rn(make_float2(vo[2], vo[3]));
    float2 f0 = __half22float2(h0);
    float2 f1 = __half22float2(h1);
    fp162 l0 = __float22half2_rn(make_float2(vo[0] - f0.x, vo[1] - f0.y));
    fp162 l1 = __float22half2_rn(make_float2(vo[2] - f1.x, vo[3] - f1.y));
    uint2 wh_, wl_;
    wh_.x = *(uint32_t*)&h0; wh_.y = *(uint32_t*)&h1;
    wl_.x = *(uint32_t*)&l0; wl_.y = *(uint32_t*)&l1;
    *(uint2*)(oh + (size_t)warp * 128 + col) = wh_;
    *(uint2*)(ol + (size_t)warp * 128 + col) = wl_;
}

// ---------------- launch helpers ----------------
static inline void launch_gemm(
    const fp16* A0h, const fp16* A0l, int K0,
    const fp16* A1h, const fp16* A1l, int K1,
    const fp16* W0, const fp16* W1,
    int M, int N,
    const float* bias, const float* bng, const float* bnb,
    const float* bnm, const float* bnv,
    int do_relu, float* Cf, fp16* Ch, fp16* Cl)
{
    if (N >= 128) {
        constexpr int BM_ = 64, BN_ = 128;
        constexpr int SMEM = 3 * (2 * BM_ * A_STRIDE + BK * (BN_ + 8)) * 2;
        dim3 grid(N / BN_, (M + BM_ - 1) / BM_);
        gemm_fp16x2<BM_, BN_, 0><<<grid, 256, SMEM>>>(
            A0h, A0l, K0, A1h, A1l, K1, nullptr, nullptr,
            W0, W1, M, N,
            bias, bng, bnb, bnm, bnv, do_relu, Cf, Ch, Cl);
    } else {
        constexpr int BM_ = 128, BN_ = 64;
        constexpr int SMEM = 2 * (2 * BM_ * A_STRIDE + BK * (BN_ + 8)) * 2;
        dim3 grid((N + BN_ - 1) / BN_, (M + BM_ - 1) / BM_);
        gemm_fp16x2<BM_, BN_, 0><<<grid, 256, SMEM>>>(
            A0h, A0l, K0, A1h, A1l, K1, nullptr, nullptr,
            W0, W1, M, N,
            bias, bng, bnb, bnm, bnv, do_relu, Cf, Ch, Cl);
    }
}

static inline void launch_gemm_f32(
    const float* Af0, int K0, const float* Af1, int K1,
    const fp16* W0, const fp16* W1,
    int M, int N, const float* bias, int do_relu, fp16* Ch, fp16* Cl)
{
    constexpr int BM_ = 64, BN_ = 128;
    constexpr int SMEM = 2 * (2 * BM_ * A_STRIDE + BK * (BN_ + 8)) * 2;
    dim3 grid(N / BN_, (M + BM_ - 1) / BM_);
    gemm_fp16x2<BM_, BN_, 1><<<grid, 256, SMEM>>>(
        nullptr, nullptr, K0, nullptr, nullptr, K1, Af0, Af1,
        W0, W1, M, N,
        bias, nullptr, nullptr, nullptr, nullptr, do_relu, nullptr, Ch, Cl);
}

extern "C" void kernel_launch(void* const* d_in, const int* in_sizes, int n_in,
                              void* d_out, int out_size)
{
    const float* structural = (const float*)d_in[0];
    const float* multimodal = (const float*)d_in[1];
    const int*   src        = (const int*)  d_in[2];
    const int*   dst        = (const int*)  d_in[3];
    const float* enc_w      = (const float*)d_in[4];
    const float* enc_b      = (const float*)d_in[5];
    const float* sage0_ws   = (const float*)d_in[6];
    const float* sage0_wn   = (const float*)d_in[7];
    const float* sage0_b    = (const float*)d_in[8];
    const float* bn0_g      = (const float*)d_in[9];
    const float* bn0_b      = (const float*)d_in[10];
    const float* bn0_m      = (const float*)d_in[11];
    const float* bn0_v      = (const float*)d_in[12];
    const float* sage1_ws   = (const float*)d_in[13];
    const float* sage1_wn   = (const float*)d_in[14];
    const float* sage1_b    = (const float*)d_in[15];
    const float* bn1_g      = (const float*)d_in[16];
    const float* bn1_b      = (const float*)d_in[17];
    const float* bn1_m      = (const float*)d_in[18];
    const float* bn1_v      = (const float*)d_in[19];
    const float* rel_w      = (const float*)d_in[20];
    const float* rel_b      = (const float*)d_in[21];
    const float* cls_w1     = (const float*)d_in[22];
    const float* cls_b1     = (const float*)d_in[23];
    const float* cls_w2     = (const float*)d_in[24];
    const float* cls_b2     = (const float*)d_in[25];
    float* out = (float*)d_out;

#define SYMADDR(var, sym) void* p_##var; cudaGetSymbolAddress(&p_##var, sym);
    SYMADDR(h0h, g_h0h) SYMADDR(h0l, g_h0l) SYMADDR(a0h, g_a0h) SYMADDR(a0l, g_a0l)
    SYMADDR(h1h, g_h1h) SYMADDR(h1l, g_h1l)
    SYMADDR(h2h, g_h2h) SYMADDR(h2l, g_h2l) SYMADDR(hfh, g_hfh) SYMADDR(hfl, g_hfl)
    SYMADDR(c1h, g_c1h) SYMADDR(c1l, g_c1l)
    SYMADDR(s1f, g_s1f) SYMADDR(g1f, g_g1f)
    SYMADDR(wh, g_wh)
    SYMADDR(counts, g_counts) SYMADDR(rowptr, g_rowptr)
    SYMADDR(fill, g_fill) SYMADDR(csr, g_csr)
#undef SYMADDR

    fp16* h0h = (fp16*)p_h0h; fp16* h0l = (fp16*)p_h0l;
    fp16* a0h = (fp16*)p_a0h; fp16* a0l = (fp16*)p_a0l;
    fp16* h1h = (fp16*)p_h1h; fp16* h1l = (fp16*)p_h1l;
    fp16* h2h = (fp16*)p_h2h; fp16* h2l = (fp16*)p_h2l;
    fp16* hfh = (fp16*)p_hfh; fp16* hfl = (fp16*)p_hfl;
    fp16* c1h = (fp16*)p_c1h; fp16* c1l = (fp16*)p_c1l;
    float* s1f = (float*)p_s1f; float* g1f = (float*)p_g1f;
    fp16* wh = (fp16*)p_wh;
    int* counts = (int*)p_counts; int* rowptr = (int*)p_rowptr;
    int* fill   = (int*)p_fill;   int* csr    = (int*)p_csr;

    {
        constexpr int SMEM_A3 = 3 * (2 * 64 * A_STRIDE + BK * (128 + 8)) * 2;
        constexpr int SMEM_A2 = 2 * (2 * 64 * A_STRIDE + BK * (128 + 8)) * 2;
        constexpr int SMEM_B  = 2 * (2 * 128 * A_STRIDE + BK * (64 + 8)) * 2;
        cudaFuncSetAttribute((const void*)gemm_fp16x2<64, 128, 0>,
                             cudaFuncAttributeMaxDynamicSharedMemorySize, SMEM_A3);
        cudaFuncSetAttribute((const void*)gemm_fp16x2<64, 128, 1>,
                             cudaFuncAttributeMaxDynamicSharedMemorySize, SMEM_A2);
        cudaFuncSetAttribute((const void*)gemm_fp16x2<128, 64, 0>,
                             cudaFuncAttributeMaxDynamicSharedMemorySize, SMEM_B);
    }

    const int M = N_NODES, E = N_EDGES;

    // ---- CSR build ----
    cudaMemsetAsync(counts, 0, N_NODES * sizeof(int), 0);
    count_deg<<<(E + 255) / 256, 256>>>(dst, counts, E);
    scan_counts<<<1, 1024>>>(counts, rowptr, fill, M);
    fill_csr<<<(E + 255) / 256, 256>>>(src, dst, fill, csr, E);

    // ---- split all weights to single fp16 plane ----
    {
        WSeg ws;
        ws.src[0] = enc_w;    ws.beg[0] = WOFF_ENC;
        ws.src[1] = sage0_ws; ws.beg[1] = WOFF_S0S;
        ws.src[2] = sage0_wn; ws.beg[2] = WOFF_S0N;
        ws.src[3] = sage1_ws; ws.beg[3] = WOFF_S1S;
        ws.src[4] = sage1_wn; ws.beg[4] = WOFF_S1N;
        ws.src[5] = rel_w;    ws.beg[5] = WOFF_REL;
        ws.src[6] = cls_w1;   ws.beg[6] = WOFF_C1;
        ws.src[7] = cls_w2;   ws.beg[7] = WOFF_C2;
        ws.beg[8] = WOFF_END;
        int w4 = WOFF_END / 4;
        split_weights<<<(w4 + 255) / 256, 256>>>(ws, wh);
    }

    // h0 = relu([structural|multimodal] @ enc_w + enc_b)  (pipelined fp32 A)
    launch_gemm_f32(structural, 128, multimodal, 384,
                    wh + WOFF_ENC, wh + WOFF_ENC + 128 * 128,
                    M, 128, enc_b, 1, h0h, h0l);

    // agg0 = mean h0
    gather_mean<<<(M * 32 + 255) / 256, 256>>>(h0h, h0l, csr, rowptr,
                                               a0h, a0l, M);

    // h1 = relu(bn0(h0 @ ws0 + agg0 @ wn0 + b0))
    launch_gemm(h0h, h0l, 128, a0h, a0l, 128,
                wh + WOFF_S0S, wh + WOFF_S0N,
                M, 256, sage0_b, bn0_g, bn0_b, bn0_m, bn0_v, 1,
                nullptr, h1h, h1l);

    // ---- sage1, commuted: mean(h1) @ Wn1 == mean(h1 @ Wn1) ----
    launch_gemm(h1h, h1l, 256, h1h, h1l, 0,
                wh + WOFF_S1N, wh + WOFF_S1N,
                M, 128, nullptr, nullptr, nullptr, nullptr, nullptr, 0,
                g1f, nullptr, nullptr);
    launch_gemm(h1h, h1l, 256, h1h, h1l, 0,
                wh + WOFF_S1S, wh + WOFF_S1S,
                M, 128, nullptr, nullptr, nullptr, nullptr, nullptr, 0,
                s1f, nullptr, nullptr);
    gather_fuse_bn<<<(M * 32 + 255) / 256, 256>>>(
        s1f, g1f, csr, rowptr, sage1_b, bn1_g, bn1_b, bn1_m, bn1_v,
        h2h, h2l, M);

    // hf = relu([h0|h2] @ rel_w + rel_b)
    launch_gemm(h0h, h0l, 128, h2h, h2l, 128,
                wh + WOFF_REL, wh + WOFF_REL + 128 * 128,
                M, 128, rel_b, nullptr, nullptr, nullptr, nullptr, 1,
                nullptr, hfh, hfl);

    // c1 = relu(hf @ cls_w1 + cls_b1)
    launch_gemm(hfh, hfl, 128, hfh, hfl, 0,
                wh + WOFF_C1, wh + WOFF_C1,
                M, 64, cls_b1, nullptr, nullptr, nullptr, nullptr, 1,
                nullptr, c1h, c1l);

    // out = c1 @ cls_w2 + cls_b2   (fp32)
    launch_gemm(c1h, c1l, 64, c1h, c1l, 0,
                wh + WOFF_C2, wh + WOFF_C2,
                M, 32, cls_b2, nullptr, nullptr, nullptr, nullptr, 0,
                out, nullptr, nullptr);
}

// round 17
// speedup vs baseline: 1.7397x; 1.1514x over previous
#include <cuda_runtime.h>
#include <cuda_fp16.h>
#include <math.h>
#include <stdint.h>

#define N_NODES 100000
#define N_EDGES 800000

typedef __half  fp16;
typedef __half2 fp162;

// ---------------- scratch (device globals; no allocs allowed) ----------------
__device__ fp16 g_h0h[(size_t)N_NODES * 128], g_h0l[(size_t)N_NODES * 128];
__device__ fp16 g_a0h[(size_t)N_NODES * 128], g_a0l[(size_t)N_NODES * 128];
__device__ fp16 g_h1h[(size_t)N_NODES * 256], g_h1l[(size_t)N_NODES * 256];
__device__ fp16 g_h2h[(size_t)N_NODES * 128], g_h2l[(size_t)N_NODES * 128];
__device__ fp16 g_hfh[(size_t)N_NODES * 128], g_hfl[(size_t)N_NODES * 128];
__device__ fp16 g_c1h[(size_t)N_NODES * 64],  g_c1l[(size_t)N_NODES * 64];
__device__ float g_s1f[(size_t)N_NODES * 128];
__device__ float g_g1f[(size_t)N_NODES * 128];
__device__ fp16 g_wh[262144];
__device__ int g_counts[N_NODES];
__device__ int g_rowptr[N_NODES + 1];
__device__ int g_fill  [N_NODES];
__device__ int g_csr   [N_EDGES];

#define WOFF_ENC 0
#define WOFF_S0S 65536
#define WOFF_S0N 98304
#define WOFF_S1S 131072
#define WOFF_S1N 163840
#define WOFF_REL 196608
#define WOFF_C1  229376
#define WOFF_C2  237568
#define WOFF_END 239616

#define BK 32
#define A_STRIDE 40

__device__ __forceinline__ void cp16(uint32_t dst, const void* src, bool pred) {
    asm volatile("cp.async.cg.shared.global [%0], [%1], 16, %2;"
                 :: "r"(dst), "l"(src), "r"(pred ? 16 : 0));
}

#define LDMX4(r, addr)                                                          \
    asm volatile("ldmatrix.sync.aligned.m8n8.x4.shared.b16 {%0,%1,%2,%3},[%4];" \
                 : "=r"((r)[0]), "=r"((r)[1]), "=r"((r)[2]), "=r"((r)[3])       \
                 : "r"(addr))

#define LDMX4T(r, addr)                                                         \
    asm volatile("ldmatrix.sync.aligned.m8n8.x4.trans.shared.b16 "              \
                 "{%0,%1,%2,%3},[%4];"                                          \
                 : "=r"((r)[0]), "=r"((r)[1]), "=r"((r)[2]), "=r"((r)[3])       \
                 : "r"(addr))

#define MMA_FP16(acc, a, b0, b1)                                                \
    asm volatile(                                                               \
        "mma.sync.aligned.m16n8k16.row.col.f32.f16.f16.f32 "                    \
        "{%0,%1,%2,%3},{%4,%5,%6,%7},{%8,%9},{%0,%1,%2,%3};"                    \
        : "+f"((acc)[0]), "+f"((acc)[1]), "+f"((acc)[2]), "+f"((acc)[3])        \
        : "r"((a)[0]), "r"((a)[1]), "r"((a)[2]), "r"((a)[3]),                   \
          "r"(b0), "r"(b1))

__device__ __forceinline__ void cvt8_planes(float4 v0, float4 v1,
                                            uint4& hi, uint4& lo)
{
    fp162 h0 = __float22half2_rn(make_float2(v0.x, v0.y));
    fp162 h1 = __float22half2_rn(make_float2(v0.z, v0.w));
    fp162 h2 = __float22half2_rn(make_float2(v1.x, v1.y));
    fp162 h3 = __float22half2_rn(make_float2(v1.z, v1.w));
    float2 f0 = __half22float2(h0);
    float2 f1 = __half22float2(h1);
    float2 f2 = __half22float2(h2);
    float2 f3 = __half22float2(h3);
    fp162 l0 = __float22half2_rn(make_float2(v0.x - f0.x, v0.y - f0.y));
    fp162 l1 = __float22half2_rn(make_float2(v0.z - f1.x, v0.w - f1.y));
    fp162 l2 = __float22half2_rn(make_float2(v1.x - f2.x, v1.y - f2.y));
    fp162 l3 = __float22half2_rn(make_float2(v1.z - f3.x, v1.w - f3.y));
    hi.x = *(uint32_t*)&h0; hi.y = *(uint32_t*)&h1;
    hi.z = *(uint32_t*)&h2; hi.w = *(uint32_t*)&h3;
    lo.x = *(uint32_t*)&l0; lo.y = *(uint32_t*)&l1;
    lo.z = *(uint32_t*)&l2; lo.w = *(uint32_t*)&l3;
}

// ---------------- fp16x2 tensor-core GEMM (A hi/lo split, B single) ----------
template<int BM_, int BN_, int AF32>
__global__ __launch_bounds__(256, 3) void gemm_fp16x2(
    const fp16* __restrict__ A0h, const fp16* __restrict__ A0l, int K0,
    const fp16* __restrict__ A1h, const fp16* __restrict__ A1l, int K1,
    const float* __restrict__ Af0, const float* __restrict__ Af1,
    const fp16* __restrict__ W0, const fp16* __restrict__ W1,
    int M, int N,
    const float* __restrict__ bias,
    const float* __restrict__ bng, const float* __restrict__ bnb,
    const float* __restrict__ bnm, const float* __restrict__ bnv,
    int do_relu,
    float* __restrict__ Cf, fp16* __restrict__ Ch, fp16* __restrict__ Cl)
{
    constexpr int A_PLANE_ = BM_ * A_STRIDE;
    constexpr int B_STRIDE = BN_ + 8;
    constexpr int B_PLANE  = BK * B_STRIDE;
    constexpr int STAGE_ELEMS = 2 * A_PLANE_ + B_PLANE;
    constexpr int WROWS  = BM_ / 32;
    constexpr int WARP_N = BN_ * WROWS / 8;
    constexpr int NT = WARP_N / 8;
    constexpr int P  = WARP_N / 16;
    constexpr int NCP = BN_ / 64;
    constexpr int NSTG = (BN_ == 128 && !AF32) ? 3 : 2;

    extern __shared__ fp16 smem[];
    const uint32_t smem_u32 = (uint32_t)__cvta_generic_to_shared(smem);

    const int tid  = threadIdx.x;
    const int lane = tid & 31;
    const int wid  = tid >> 5;
    const int wm   = (wid % WROWS) * 32;
    const int wn   = (wid / WROWS) * WARP_N;
    const int brow = blockIdx.y * BM_;
    const int bcol = blockIdx.x * BN_;
    const int K = K0 + K1;
    const int T = K / BK;

    constexpr int ATPR = 256 / BM_;
    const int a_row = tid / ATPR;
    const int a_k   = (tid % ATPR) * (32 / ATPR);
    const int a_gr  = brow + a_row;
    const bool a_ok = (a_gr < M);
    const int b_k  = tid >> 3;
    const int b_n0 = (tid & 7) * (BN_ / 8);

    const int a_lm = (wm + (lane & 15)) * A_STRIDE + (lane >> 4) * 8;
    const int b_lm = ((lane & 7) + ((lane >> 3) & 1) * 8) * B_STRIDE
                     + wn + (lane >> 4) * 8;

    float acc[2][NT][4];
#pragma unroll
    for (int mt = 0; mt < 2; mt++)
#pragma unroll
        for (int nt = 0; nt < NT; nt++)
#pragma unroll
            for (int i = 0; i < 4; i++) acc[mt][nt][i] = 0.f;

#define B_LOAD(t, stv) do {                                                       \
        int gk = (t) * BK + b_k;                                                  \
        const fp16 *wp; int kk2;                                                  \
        if (gk < K0) { wp = W0; kk2 = gk; }                                       \
        else         { wp = W1; kk2 = gk - K0; }                                  \
        uint32_t dbh = smem_u32 +                                                 \
            ((stv) * STAGE_ELEMS + 2 * A_PLANE_ + b_k * B_STRIDE + b_n0) * 2;     \
        _Pragma("unroll")                                                         \
        for (int cc = 0; cc < NCP; cc++) {                                        \
            int n0 = bcol + b_n0 + cc * 8;                                        \
            bool ok = (n0 < N);                                                   \
            cp16(dbh + cc * 16, wp + (size_t)kk2 * N + n0, ok);                   \
        }                                                                         \
    } while (0)

#define LOAD_TILE(t, stv) do {                                                    \
        int gk0 = (t) * BK + a_k;                                                 \
        const fp16 *sph, *spl;                                                    \
        if (gk0 < K0) { sph = A0h + (size_t)a_gr * K0 + gk0;                      \
                        spl = A0l + (size_t)a_gr * K0 + gk0; }                    \
        else          { sph = A1h + (size_t)a_gr * K1 + (gk0 - K0);               \
                        spl = A1l + (size_t)a_gr * K1 + (gk0 - K0); }             \
        uint32_t dh = smem_u32 +                                                  \
            ((stv) * STAGE_ELEMS + a_row * A_STRIDE + a_k) * 2;                   \
        if (ATPR == 2) {                                                          \
            cp16(dh,      sph,     a_ok);                                         \
            cp16(dh + 16, sph + 8, a_ok);                                         \
            cp16(dh + A_PLANE_ * 2,      spl,     a_ok);                          \
            cp16(dh + A_PLANE_ * 2 + 16, spl + 8, a_ok);                          \
        } else {                                                                  \
            cp16(dh,                sph, a_ok);                                   \
            cp16(dh + A_PLANE_ * 2, spl, a_ok);                                   \
        }                                                                         \
        B_LOAD(t, stv);                                                           \
        asm volatile("cp.async.commit_group;");                                   \
    } while (0)

#define A_LDG(t) do {                                                             \
        int gk0 = (t) * BK + a_k;                                                 \
        const float* sp;                                                          \
        if (gk0 < K0) sp = Af0 + (size_t)a_gr * K0 + gk0;                         \
        else          sp = Af1 + (size_t)a_gr * K1 + (gk0 - K0);                  \
        if (a_ok) { cv0 = *(const float4*)sp; cv1 = *(const float4*)(sp + 4); }   \
        else { cv0 = make_float4(0.f,0.f,0.f,0.f); cv1 = cv0; }                   \
    } while (0)

#define A_STS(stv) do {                                                           \
        uint4 hi_, lo_;                                                           \
        cvt8_planes(cv0, cv1, hi_, lo_);                                          \
        fp16* ap = smem + (stv) * STAGE_ELEMS + a_row * A_STRIDE + a_k;           \
        *(uint4*)ap = hi_;                                                        \
        *(uint4*)(ap + A_PLANE_) = lo_;                                           \
    } while (0)

#define MMA_STEP(stv) do {                                                        \
        const uint32_t base = smem_u32 + (stv) * STAGE_ELEMS * 2;                 \
        _Pragma("unroll")                                                         \
        for (int k16 = 0; k16 < 2; k16++) {                                       \
            uint32_t ah[2][4], al[2][4], bh[P][4];                                \
            _Pragma("unroll")                                                     \
            for (int mt = 0; mt < 2; mt++) {                                      \
                uint32_t ad = base + (a_lm + mt * 16 * A_STRIDE + k16 * 16) * 2;  \
                LDMX4(ah[mt], ad);                                                \
                LDMX4(al[mt], ad + A_PLANE_ * 2);                                 \
            }                                                                     \
            _Pragma("unroll")                                                     \
            for (int p = 0; p < P; p++) {                                         \
                uint32_t bd = base + (2 * A_PLANE_ + b_lm + p * 16                \
                                      + k16 * 16 * B_STRIDE) * 2;                 \
                LDMX4T(bh[p], bd);                                                \
            }                                                                     \
            _Pragma("unroll")                                                     \
            for (int mt = 0; mt < 2; mt++)                                        \
                _Pragma("unroll")                                                 \
                for (int nt = 0; nt < NT; nt++) {                                 \
                    const int p = nt >> 1, q = (nt & 1) * 2;                      \
                    MMA_FP16(acc[mt][nt], al[mt], bh[p][q], bh[p][q + 1]);        \
                    MMA_FP16(acc[mt][nt], ah[mt], bh[p][q], bh[p][q + 1]);        \
                }                                                                 \
        }                                                                         \
    } while (0)

    if (AF32) {
        float4 cv0, cv1;
        A_LDG(0);
        A_STS(0);
        B_LOAD(0, 0);
        asm volatile("cp.async.commit_group;");
        A_LDG(1);
        B_LOAD(1, 1);
        asm volatile("cp.async.commit_group;");

        for (int t = 0; t < T; ++t) {
            const int st = t & 1;
            if (t + 1 < T) {
                asm volatile("cp.async.wait_group 1;");
            } else {
                asm volatile("cp.async.wait_group 0;");
            }
            __syncthreads();
            MMA_STEP(st);
            __syncthreads();
            if (t + 1 < T) {
                A_STS(st ^ 1);
                if (t + 2 < T) {
                    A_LDG(t + 2);
                    B_LOAD(t + 2, st);
                    asm volatile("cp.async.commit_group;");
                }
            }
        }
    } else if (NSTG == 3) {
        LOAD_TILE(0, 0);
        if (T > 1) LOAD_TILE(1, 1);
        for (int t = 0; t < T; ++t) {
            const int st = t % 3;
            if (t + 2 < T) {
                LOAD_TILE(t + 2, (t + 2) % 3);
                asm volatile("cp.async.wait_group 2;");
            } else if (t + 1 < T) {
                asm volatile("cp.async.wait_group 1;");
            } else {
                asm volatile("cp.async.wait_group 0;");
            }
            __syncthreads();
            MMA_STEP(st);
            __syncthreads();
        }
    } else {
        LOAD_TILE(0, 0);
        for (int t = 0; t < T; ++t) {
            const int st = t & 1;
            if (t + 1 < T) {
                LOAD_TILE(t + 1, st ^ 1);
                asm volatile("cp.async.wait_group 1;");
            } else {
                asm volatile("cp.async.wait_group 0;");
            }
            __syncthreads();
            MMA_STEP(st);
            __syncthreads();
        }
    }

#pragma unroll
    for (int nt = 0; nt < NT; nt++) {
        const int col = bcol + wn + 8 * nt + 2 * (lane & 3);
        if (col >= N) continue;
        float sc0 = 1.f, sh0 = 0.f, sc1 = 1.f, sh1 = 0.f;
        if (bias) { sh0 = bias[col]; sh1 = bias[col + 1]; }
        if (bng) {
            float s0 = bng[col]     * rsqrtf(bnv[col]     + 1e-5f);
            float s1 = bng[col + 1] * rsqrtf(bnv[col + 1] + 1e-5f);
            sh0 = (sh0 - bnm[col])     * s0 + bnb[col];
            sh1 = (sh1 - bnm[col + 1]) * s1 + bnb[col + 1];
            sc0 = s0; sc1 = s1;
        }
#pragma unroll
        for (int mt = 0; mt < 2; mt++) {
#pragma unroll
            for (int half = 0; half < 2; half++) {
                const int row = brow + wm + 16 * mt + (lane >> 2) + 8 * half;
                if (row >= M) continue;
                const float* c = acc[mt][nt] + 2 * half;
                float v0 = c[0] * sc0 + sh0;
                float v1 = c[1] * sc1 + sh1;
                if (do_relu) { v0 = fmaxf(v0, 0.f); v1 = fmaxf(v1, 0.f); }
                if (Ch) {
                    fp162 hi = __float22half2_rn(make_float2(v0, v1));
                    float2 hf2 = __half22float2(hi);
                    fp162 lo = __float22half2_rn(
                        make_float2(v0 - hf2.x, v1 - hf2.y));
                    *(fp162*)(Ch + (size_t)row * N + col) = hi;
                    *(fp162*)(Cl + (size_t)row * N + col) = lo;
                } else {
                    *(float2*)(Cf + (size_t)row * N + col) = make_float2(v0, v1);
                }
            }
        }
    }
}

// ---------------- merged weight split ----------------
struct WSeg { const float* src[8]; int beg[9]; };

__global__ void split_weights(WSeg ws, fp16* __restrict__ wh)
{
    int i4 = blockIdx.x * blockDim.x + threadIdx.x;
    int i  = i4 * 4;
    if (i >= ws.beg[8]) return;
    int s = 0;
#pragma unroll
    for (int k = 0; k < 7; k++) s += (i >= ws.beg[k + 1]) ? 1 : 0;
    float4 v = *(const float4*)(ws.src[s] + (i - ws.beg[s]));
    fp162 h0 = __float22half2_rn(make_float2(v.x, v.y));
    fp162 h1 = __float22half2_rn(make_float2(v.z, v.w));
    ((fp162*)wh)[i4 * 2]     = h0;
    ((fp162*)wh)[i4 * 2 + 1] = h1;
}

// ---------------- CSR construction ----------------
__global__ void count_deg(const int* __restrict__ dst, int* __restrict__ counts, int E)
{
    int e = blockIdx.x * blockDim.x + threadIdx.x;
    if (e < E) atomicAdd(&counts[dst[e]], 1);
}

__global__ __launch_bounds__(1024) void scan_counts(
    const int* __restrict__ counts, int* __restrict__ rowptr,
    int* __restrict__ fill, int n)
{
    __shared__ int part[1024];
    const int tid = threadIdx.x;
    const int chunk = (n + 1023) / 1024;
    const int begin = min(tid * chunk, n);
    const int end   = min(begin + chunk, n);
    int s = 0;
    for (int i = begin; i < end; i++) s += counts[i];
    part[tid] = s;
    __syncthreads();
    for (int off = 1; off < 1024; off <<= 1) {
        int v = (tid >= off) ? part[tid - off] : 0;
        __syncthreads();
        part[tid] += v;
        __syncthreads();
    }
    int pre = (tid == 0) ? 0 : part[tid - 1];
    for (int i = begin; i < end; i++) {
        rowptr[i] = pre;
        fill[i]   = pre;
        pre += counts[i];
    }
    if (end == n && begin <= n) rowptr[n] = pre;
}

__global__ void fill_csr(const int* __restrict__ src, const int* __restrict__ dst,
                         int* __restrict__ fill, int* __restrict__ csr, int E)
{
    int e = blockIdx.x * blockDim.x + threadIdx.x;
    if (e < E) {
        int pos = atomicAdd(&fill[dst[e]], 1);
        csr[pos] = src[e];
    }
}

// ---------------- CSR gather mean over fp16 planes (D=128), 4-edge unroll -----
__device__ __forceinline__ void acc_row(const fp16* hh, const fp16* hl,
                                        int s, int off,
                                        float& a0, float& a1, float& a2, float& a3)
{
    uint2 vh = *(const uint2*)(hh + (size_t)s * 128 + off);
    uint2 vl = *(const uint2*)(hl + (size_t)s * 128 + off);
    float2 p0 = __half22float2(*(const fp162*)&vh.x);
    float2 p1 = __half22float2(*(const fp162*)&vh.y);
    float2 q0 = __half22float2(*(const fp162*)&vl.x);
    float2 q1 = __half22float2(*(const fp162*)&vl.y);
    a0 += p0.x + q0.x;
    a1 += p0.y + q0.y;
    a2 += p1.x + q1.x;
    a3 += p1.y + q1.y;
}

__global__ void gather_mean(const fp16* __restrict__ hh, const fp16* __restrict__ hl,
                            const int* __restrict__ csr, const int* __restrict__ rowptr,
                            fp16* __restrict__ oh, fp16* __restrict__ ol, int Nn)
{
    const int warp = (blockIdx.x * blockDim.x + threadIdx.x) >> 5;
    const int lane = threadIdx.x & 31;
    if (warp >= Nn) return;
    const int e0 = rowptr[warp];
    const int e1 = rowptr[warp + 1];
    const float inv = 1.f / (float)max(e1 - e0, 1);
    const int off = lane * 4;

    float a0 = 0.f, a1 = 0.f, a2 = 0.f, a3 = 0.f;
    int e = e0;
    for (; e + 3 < e1; e += 4) {
        int s0 = csr[e], s1 = csr[e + 1], s2 = csr[e + 2], s3 = csr[e + 3];
        acc_row(hh, hl, s0, off, a0, a1, a2, a3);
        acc_row(hh, hl, s1, off, a0, a1, a2, a3);
        acc_row(hh, hl, s2, off, a0, a1, a2, a3);
        acc_row(hh, hl, s3, off, a0, a1, a2, a3);
    }
    for (; e < e1; e++)
        acc_row(hh, hl, csr[e], off, a0, a1, a2, a3);

    float v0 = a0 * inv, v1 = a1 * inv, v2 = a2 * inv, v3 = a3 * inv;
    fp162 h0 = __float22half2_rn(make_float2(v0, v1));
    fp162 h1 = __float22half2_rn(make_float2(v2, v3));
    float2 f0 = __half22float2(h0);
    float2 f1 = __half22float2(h1);
    fp162 l0 = __float22half2_rn(make_float2(v0 - f0.x, v1 - f0.y));
    fp162 l1 = __float22half2_rn(make_float2(v2 - f1.x, v3 - f1.y));
    uint2 wh_, wl_;
    wh_.x = *(uint32_t*)&h0; wh_.y = *(uint32_t*)&h1;
    wl_.x = *(uint32_t*)&l0; wl_.y = *(uint32_t*)&l1;
    *(uint2*)(oh + (size_t)warp * 128 + off) = wh_;
    *(uint2*)(ol + (size_t)warp * 128 + off) = wl_;
}

// ---------------- layer-1 fused gather (4-edge unroll) ----------------
__global__ void gather_fuse_bn(const float* __restrict__ S1,
                               const float* __restrict__ G1,
                               const int* __restrict__ csr,
                               const int* __restrict__ rowptr,
                               const float* __restrict__ bias,
                               const float* __restrict__ bng,
                               const float* __restrict__ bnb,
                               const float* __restrict__ bnm,
                               const float* __restrict__ bnv,
                               fp16* __restrict__ oh, fp16* __restrict__ ol,
                               int Nn)
{
    const int warp = (blockIdx.x * blockDim.x + threadIdx.x) >> 5;
    const int lane = threadIdx.x & 31;
    if (warp >= Nn) return;
    const int e0 = rowptr[warp];
    const int e1 = rowptr[warp + 1];
    const float inv = 1.f / (float)max(e1 - e0, 1);
    const int col = lane * 4;

    float acc0 = 0.f, acc1 = 0.f, acc2 = 0.f, acc3 = 0.f;
    int e = e0;
    for (; e + 3 < e1; e += 4) {
        const float4 v0 = *(const float4*)(G1 + (size_t)csr[e] * 128 + col);
        const float4 v1 = *(const float4*)(G1 + (size_t)csr[e + 1] * 128 + col);
        const float4 v2 = *(const float4*)(G1 + (size_t)csr[e + 2] * 128 + col);
        const float4 v3 = *(const float4*)(G1 + (size_t)csr[e + 3] * 128 + col);
        acc0 += (v0.x + v1.x) + (v2.x + v3.x);
        acc1 += (v0.y + v1.y) + (v2.y + v3.y);
        acc2 += (v0.z + v1.z) + (v2.z + v3.z);
        acc3 += (v0.w + v1.w) + (v2.w + v3.w);
    }
    for (; e < e1; e++) {
        const float4 v = *(const float4*)(G1 + (size_t)csr[e] * 128 + col);
        acc0 += v.x; acc1 += v.y; acc2 += v.z; acc3 += v.w;
    }
    const float4 s = *(const float4*)(S1 + (size_t)warp * 128 + col);

    float vo[4];
    const float* sp = &s.x;
    float ac[4] = {acc0, acc1, acc2, acc3};
#pragma unroll
    for (int j = 0; j < 4; j++) {
        const float sc = bng[col + j] * rsqrtf(bnv[col + j] + 1e-5f);
        const float sh = (bias[col + j] - bnm[col + j]) * sc + bnb[col + j];
        float x = (sp[j] + ac[j] * inv) * sc + sh;
        vo[j] = fmaxf(x, 0.f);
    }

    fp162 h0 = __float22half2_rn(make_float2(vo[0], vo[1]));
    fp162 h1 = __float22half2_rn(make_float2(vo[2], vo[3]));
    float2 f0 = __half22float2(h0);
    float2 f1 = __half22float2(h1);
    fp162 l0 = __float22half2_rn(make_float2(vo[0] - f0.x, vo[1] - f0.y));
    fp162 l1 = __float22half2_rn(make_float2(vo[2] - f1.x, vo[3] - f1.y));
    uint2 wh_, wl_;
    wh_.x = *(uint32_t*)&h0; wh_.y = *(uint32_t*)&h1;
    wl_.x = *(uint32_t*)&l0; wl_.y = *(uint32_t*)&l1;
    *(uint2*)(oh + (size_t)warp * 128 + col) = wh_;
    *(uint2*)(ol + (size_t)warp * 128 + col) = wl_;
}

// ---------------- launch helpers ----------------
static inline void launch_gemm(
    const fp16* A0h, const fp16* A0l, int K0,
    const fp16* A1h, const fp16* A1l, int K1,
    const fp16* W0, const fp16* W1,
    int M, int N,
    const float* bias, const float* bng, const float* bnb,
    const float* bnm, const float* bnv,
    int do_relu, float* Cf, fp16* Ch, fp16* Cl)
{
    if (N >= 128) {
        constexpr int BM_ = 64, BN_ = 128;
        constexpr int SMEM = 3 * (2 * BM_ * A_STRIDE + BK * (BN_ + 8)) * 2;
        dim3 grid(N / BN_, (M + BM_ - 1) / BM_);
        gemm_fp16x2<BM_, BN_, 0><<<grid, 256, SMEM>>>(
            A0h, A0l, K0, A1h, A1l, K1, nullptr, nullptr,
            W0, W1, M, N,
            bias, bng, bnb, bnm, bnv, do_relu, Cf, Ch, Cl);
    } else {
        constexpr int BM_ = 128, BN_ = 64;
        constexpr int SMEM = 2 * (2 * BM_ * A_STRIDE + BK * (BN_ + 8)) * 2;
        dim3 grid((N + BN_ - 1) / BN_, (M + BM_ - 1) / BM_);
        gemm_fp16x2<BM_, BN_, 0><<<grid, 256, SMEM>>>(
            A0h, A0l, K0, A1h, A1l, K1, nullptr, nullptr,
            W0, W1, M, N,
            bias, bng, bnb, bnm, bnv, do_relu, Cf, Ch, Cl);
    }
}

static inline void launch_gemm_f32(
    const float* Af0, int K0, const float* Af1, int K1,
    const fp16* W0, const fp16* W1,
    int M, int N, const float* bias, int do_relu, fp16* Ch, fp16* Cl)
{
    constexpr int BM_ = 64, BN_ = 128;
    constexpr int SMEM = 2 * (2 * BM_ * A_STRIDE + BK * (BN_ + 8)) * 2;
    dim3 grid(N / BN_, (M + BM_ - 1) / BM_);
    gemm_fp16x2<BM_, BN_, 1><<<grid, 256, SMEM>>>(
        nullptr, nullptr, K0, nullptr, nullptr, K1, Af0, Af1,
        W0, W1, M, N,
        bias, nullptr, nullptr, nullptr, nullptr, do_relu, nullptr, Ch, Cl);
}

extern "C" void kernel_launch(void* const* d_in, const int* in_sizes, int n_in,
                              void* d_out, int out_size)
{
    const float* structural = (const float*)d_in[0];
    const float* multimodal = (const float*)d_in[1];
    const int*   src        = (const int*)  d_in[2];
    const int*   dst        = (const int*)  d_in[3];
    const float* enc_w      = (const float*)d_in[4];
    const float* enc_b      = (const float*)d_in[5];
    const float* sage0_ws   = (const float*)d_in[6];
    const float* sage0_wn   = (const float*)d_in[7];
    const float* sage0_b    = (const float*)d_in[8];
    const float* bn0_g      = (const float*)d_in[9];
    const float* bn0_b      = (const float*)d_in[10];
    const float* bn0_m      = (const float*)d_in[11];
    const float* bn0_v      = (const float*)d_in[12];
    const float* sage1_ws   = (const float*)d_in[13];
    const float* sage1_wn   = (const float*)d_in[14];
    const float* sage1_b    = (const float*)d_in[15];
    const float* bn1_g      = (const float*)d_in[16];
    const float* bn1_b      = (const float*)d_in[17];
    const float* bn1_m      = (const float*)d_in[18];
    const float* bn1_v      = (const float*)d_in[19];
    const float* rel_w      = (const float*)d_in[20];
    const float* rel_b      = (const float*)d_in[21];
    const float* cls_w1     = (const float*)d_in[22];
    const float* cls_b1     = (const float*)d_in[23];
    const float* cls_w2     = (const float*)d_in[24];
    const float* cls_b2     = (const float*)d_in[25];
    float* out = (float*)d_out;

#define SYMADDR(var, sym) void* p_##var; cudaGetSymbolAddress(&p_##var, sym);
    SYMADDR(h0h, g_h0h) SYMADDR(h0l, g_h0l) SYMADDR(a0h, g_a0h) SYMADDR(a0l, g_a0l)
    SYMADDR(h1h, g_h1h) SYMADDR(h1l, g_h1l)
    SYMADDR(h2h, g_h2h) SYMADDR(h2l, g_h2l) SYMADDR(hfh, g_hfh) SYMADDR(hfl, g_hfl)
    SYMADDR(c1h, g_c1h) SYMADDR(c1l, g_c1l)
    SYMADDR(s1f, g_s1f) SYMADDR(g1f, g_g1f)
    SYMADDR(wh, g_wh)
    SYMADDR(counts, g_counts) SYMADDR(rowptr, g_rowptr)
    SYMADDR(fill, g_fill) SYMADDR(csr, g_csr)
#undef SYMADDR

    fp16* h0h = (fp16*)p_h0h; fp16* h0l = (fp16*)p_h0l;
    fp16* a0h = (fp16*)p_a0h; fp16* a0l = (fp16*)p_a0l;
    fp16* h1h = (fp16*)p_h1h; fp16* h1l = (fp16*)p_h1l;
    fp16* h2h = (fp16*)p_h2h; fp16* h2l = (fp16*)p_h2l;
    fp16* hfh = (fp16*)p_hfh; fp16* hfl = (fp16*)p_hfl;
    fp16* c1h = (fp16*)p_c1h; fp16* c1l = (fp16*)p_c1l;
    float* s1f = (float*)p_s1f; float* g1f = (float*)p_g1f;
    fp16* wh = (fp16*)p_wh;
    int* counts = (int*)p_counts; int* rowptr = (int*)p_rowptr;
    int* fill   = (int*)p_fill;   int* csr    = (int*)p_csr;

    // one-time stream/event resources (created on the uncaptured correctness
    // call; reused identically on every subsequent call -> deterministic work)
    static cudaStream_t s2 = nullptr;
    static cudaEvent_t evFork = nullptr, evCsr = nullptr;
    if (!s2) {
        cudaStreamCreateWithFlags(&s2, cudaStreamNonBlocking);
        cudaEventCreateWithFlags(&evFork, cudaEventDisableTiming);
        cudaEventCreateWithFlags(&evCsr, cudaEventDisableTiming);
    }

    {
        constexpr int SMEM_A3 = 3 * (2 * 64 * A_STRIDE + BK * (128 + 8)) * 2;
        constexpr int SMEM_A2 = 2 * (2 * 64 * A_STRIDE + BK * (128 + 8)) * 2;
        constexpr int SMEM_B  = 2 * (2 * 128 * A_STRIDE + BK * (64 + 8)) * 2;
        cudaFuncSetAttribute((const void*)gemm_fp16x2<64, 128, 0>,
                             cudaFuncAttributeMaxDynamicSharedMemorySize, SMEM_A3);
        cudaFuncSetAttribute((const void*)gemm_fp16x2<64, 128, 1>,
                             cudaFuncAttributeMaxDynamicSharedMemorySize, SMEM_A2);
        cudaFuncSetAttribute((const void*)gemm_fp16x2<128, 64, 0>,
                             cudaFuncAttributeMaxDynamicSharedMemorySize, SMEM_B);
    }

    const int M = N_NODES, E = N_EDGES;

    // ---- fork: CSR build runs on s2, concurrent with split + enc GEMM ----
    cudaEventRecord(evFork, 0);
    cudaStreamWaitEvent(s2, evFork, 0);
    cudaMemsetAsync(counts, 0, N_NODES * sizeof(int), s2);
    count_deg<<<(E + 255) / 256, 256, 0, s2>>>(dst, counts, E);
    scan_counts<<<1, 1024, 0, s2>>>(counts, rowptr, fill, M);
    fill_csr<<<(E + 255) / 256, 256, 0, s2>>>(src, dst, fill, csr, E);
    cudaEventRecord(evCsr, s2);

    // ---- main stream: weight split + enc GEMM ----
    {
        WSeg ws;
        ws.src[0] = enc_w;    ws.beg[0] = WOFF_ENC;
        ws.src[1] = sage0_ws; ws.beg[1] = WOFF_S0S;
        ws.src[2] = sage0_wn; ws.beg[2] = WOFF_S0N;
        ws.src[3] = sage1_ws; ws.beg[3] = WOFF_S1S;
        ws.src[4] = sage1_wn; ws.beg[4] = WOFF_S1N;
        ws.src[5] = rel_w;    ws.beg[5] = WOFF_REL;
        ws.src[6] = cls_w1;   ws.beg[6] = WOFF_C1;
        ws.src[7] = cls_w2;   ws.beg[7] = WOFF_C2;
        ws.beg[8] = WOFF_END;
        int w4 = WOFF_END / 4;
        split_weights<<<(w4 + 255) / 256, 256>>>(ws, wh);
    }

    // h0 = relu([structural|multimodal] @ enc_w + enc_b)  (pipelined fp32 A)
    launch_gemm_f32(structural, 128, multimodal, 384,
                    wh + WOFF_ENC, wh + WOFF_ENC + 128 * 128,
                    M, 128, enc_b, 1, h0h, h0l);

    // ---- join: gather needs CSR ----
    cudaStreamWaitEvent(0, evCsr, 0);

    // agg0 = mean h0
    gather_mean<<<(M * 32 + 255) / 256, 256>>>(h0h, h0l, csr, rowptr,
                                               a0h, a0l, M);

    // h1 = relu(bn0(h0 @ ws0 + agg0 @ wn0 + b0))
    launch_gemm(h0h, h0l, 128, a0h, a0l, 128,
                wh + WOFF_S0S, wh + WOFF_S0N,
                M, 256, sage0_b, bn0_g, bn0_b, bn0_m, bn0_v, 1,
                nullptr, h1h, h1l);

    // ---- sage1, commuted: mean(h1) @ Wn1 == mean(h1 @ Wn1) ----
    launch_gemm(h1h, h1l, 256, h1h, h1l, 0,
                wh + WOFF_S1N, wh + WOFF_S1N,
                M, 128, nullptr, nullptr, nullptr, nullptr, nullptr, 0,
                g1f, nullptr, nullptr);
    launch_gemm(h1h, h1l, 256, h1h, h1l, 0,
                wh + WOFF_S1S, wh + WOFF_S1S,
                M, 128, nullptr, nullptr, nullptr, nullptr, nullptr, 0,
                s1f, nullptr, nullptr);
    gather_fuse_bn<<<(M * 32 + 255) / 256, 256>>>(
        s1f, g1f, csr, rowptr, sage1_b, bn1_g, bn1_b, bn1_m, bn1_v,
        h2h, h2l, M);

    // hf = relu([h0|h2] @ rel_w + rel_b)
    launch_gemm(h0h, h0l, 128, h2h, h2l, 128,
                wh + WOFF_REL, wh + WOFF_REL + 128 * 128,
                M, 128, rel_b, nullptr, nullptr, nullptr, nullptr, 1,
                nullptr, hfh, hfl);

    // c1 = relu(hf @ cls_w1 + cls_b1)
    launch_gemm(hfh, hfl, 128, hfh, hfl, 0,
                wh + WOFF_C1, wh + WOFF_C1,
                M, 64, cls_b1, nullptr, nullptr, nullptr, nullptr, 1,
                nullptr, c1h, c1l);

    // out = c1 @ cls_w2 + cls_b2   (fp32)
    launch_gemm(c1h, c1l, 64, c1h, c1l, 0,
                wh + WOFF_C2, wh + WOFF_C2,
                M, 32, cls_b2, nullptr, nullptr, nullptr, nullptr, 0,
                out, nullptr, nullptr);
}